// round 1
// baseline (speedup 1.0000x reference)
#include <cuda_runtime.h>
#include <cuda_bf16.h>
#include <math.h>

// Problem constants
#define B_   4
#define S_   2048
#define H_   16
#define DH_  64
#define D_   1024          // EMBED
#define FF_  2048
#define BS_  (B_*S_)       // 8192 rows
#define BH_  (B_*H_)       // 64

// ---------------- scratch (device globals; no runtime allocation) -----------
__device__ float g_qkv[(size_t)BS_ * 3 * D_];   // 8192 x 3072
__device__ float g_q  [(size_t)BH_ * S_ * DH_];
__device__ float g_k  [(size_t)BH_ * S_ * DH_];
__device__ float g_v  [(size_t)BH_ * S_ * DH_];
__device__ float g_att[(size_t)BS_ * D_];
__device__ float g_x  [(size_t)BS_ * D_];       // LN output (residual source)
__device__ float g_h  [(size_t)BS_ * FF_];      // FF hidden

// ---------------- SGEMM: C = act(A@B + bias) (+ residual) -------------------
// 128x128 tile, BK=8, 256 threads, 8x8 per-thread micro-tile.
// MODE 0: plain   MODE 1: SiLU   MODE 2: add residual (res)
template <int MODE>
__global__ __launch_bounds__(256) void sgemm_kernel(
    const float* __restrict__ A, const float* __restrict__ Bm,
    const float* __restrict__ bias, const float* __restrict__ res,
    float* __restrict__ C, int M, int N, int K)
{
    __shared__ float As[8][128];
    __shared__ float Bs[8][128];

    const int tid = threadIdx.x;
    const int bx = blockIdx.x, by = blockIdx.y;

    const float* Ab = A + (size_t)by * 128 * K;
    const float* Bb = Bm + (size_t)bx * 128;

    const int arow = tid >> 1;
    const int acol = (tid & 1) * 4;
    const int brow = tid >> 5;
    const int bcol = (tid & 31) * 4;

    const int row = (tid >> 4) * 8;   // 0..120
    const int col = (tid & 15) * 8;   // 0..120

    float acc[8][8];
    #pragma unroll
    for (int i = 0; i < 8; i++)
        #pragma unroll
        for (int j = 0; j < 8; j++) acc[i][j] = 0.f;

    for (int k0 = 0; k0 < K; k0 += 8) {
        float4 a4 = *(const float4*)(Ab + (size_t)arow * K + k0 + acol);
        As[acol + 0][arow] = a4.x;
        As[acol + 1][arow] = a4.y;
        As[acol + 2][arow] = a4.z;
        As[acol + 3][arow] = a4.w;
        float4 b4 = *(const float4*)(Bb + (size_t)(k0 + brow) * N + bcol);
        *(float4*)&Bs[brow][bcol] = b4;
        __syncthreads();

        #pragma unroll
        for (int kk = 0; kk < 8; kk++) {
            float af[8], bf[8];
            *(float4*)&af[0] = *(const float4*)&As[kk][row];
            *(float4*)&af[4] = *(const float4*)&As[kk][row + 4];
            *(float4*)&bf[0] = *(const float4*)&Bs[kk][col];
            *(float4*)&bf[4] = *(const float4*)&Bs[kk][col + 4];
            #pragma unroll
            for (int i = 0; i < 8; i++)
                #pragma unroll
                for (int j = 0; j < 8; j++)
                    acc[i][j] = fmaf(af[i], bf[j], acc[i][j]);
        }
        __syncthreads();
    }

    const int gcol0 = bx * 128 + col;
    float bi[8];
    *(float4*)&bi[0] = *(const float4*)(bias + gcol0);
    *(float4*)&bi[4] = *(const float4*)(bias + gcol0 + 4);

    #pragma unroll
    for (int i = 0; i < 8; i++) {
        const size_t grow = (size_t)(by * 128 + row + i);
        float out[8];
        #pragma unroll
        for (int j = 0; j < 8; j++) {
            float c = acc[i][j] + bi[j];
            if (MODE == 1) c = c / (1.f + __expf(-c));   // SiLU
            out[j] = c;
        }
        if (MODE == 2) {
            float r[8];
            *(float4*)&r[0] = *(const float4*)(res + grow * N + gcol0);
            *(float4*)&r[4] = *(const float4*)(res + grow * N + gcol0 + 4);
            #pragma unroll
            for (int j = 0; j < 8; j++) out[j] += r[j];
        }
        *(float4*)(C + grow * N + gcol0)     = *(float4*)&out[0];
        *(float4*)(C + grow * N + gcol0 + 4) = *(float4*)&out[4];
    }
}

// ---------------- QKV transform: l2norm + scale + xpos rotary ---------------
// One warp per (b,h,s). Lane handles dims d=lane and d+32.
__global__ __launch_bounds__(256) void transform_kernel(
    const float* __restrict__ qkv,
    const float* __restrict__ q_scale, const float* __restrict__ k_scale,
    float* __restrict__ Qo, float* __restrict__ Ko, float* __restrict__ Vo)
{
    const int gw   = (blockIdx.x * blockDim.x + threadIdx.x) >> 5;
    const int lane = threadIdx.x & 31;
    const int s  = gw & (S_ - 1);
    const int bh = gw >> 11;            // /S_
    if (bh >= BH_) return;
    const int b = bh >> 4, h = bh & 15;

    const float* base = qkv + ((size_t)(b * S_ + s)) * (3 * D_) + h * (3 * DH_);
    float q0 = base[lane],       q1 = base[lane + 32];
    float k0 = base[64 + lane],  k1 = base[96 + lane];
    float v0 = base[128 + lane], v1 = base[160 + lane];

    float nq = q0 * q0 + q1 * q1;
    float nk = k0 * k0 + k1 * k1;
    #pragma unroll
    for (int off = 16; off; off >>= 1) {
        nq += __shfl_xor_sync(0xffffffffu, nq, off);
        nk += __shfl_xor_sync(0xffffffffu, nk, off);
    }
    nq = fmaxf(sqrtf(nq), 1e-12f);
    nk = fmaxf(sqrtf(nk), 1e-12f);

    q0 = q0 / nq * q_scale[lane]; q1 = q1 / nq * q_scale[lane + 32];
    k0 = k0 / nk * k_scale[lane]; k1 = k1 / nk * k_scale[lane + 32];

    const float d2 = 2.0f * (float)lane;
    // inv_freq = 10000^(-d2/64)
    const float inv_freq = exp2f(-d2 * (13.287712379549449f / 64.0f));
    const float fr = (float)s * inv_freq;
    float sn, c;
    sincosf(fr, &sn, &c);

    const float basev = (d2 + 0.4f * 64.0f) / (1.4f * 64.0f);
    const float power = ((float)s - (float)(S_ / 2)) / 512.0f;
    const float scale = exp2f(power * log2f(basev));
    const float iscale = 1.0f / scale;

    const float qo0 = (q0 * c - q1 * sn) * scale;
    const float qo1 = (q1 * c + q0 * sn) * scale;
    const float ko0 = (k0 * c - k1 * sn) * iscale;
    const float ko1 = (k1 * c + k0 * sn) * iscale;

    const size_t ob = ((size_t)bh * S_ + s) * DH_;
    // pre-apply softmax scale 1/sqrt(dh)=0.125 to q
    Qo[ob + lane]      = qo0 * 0.125f;
    Qo[ob + lane + 32] = qo1 * 0.125f;
    Ko[ob + lane]      = ko0;
    Ko[ob + lane + 32] = ko1;
    Vo[ob + lane]      = v0;
    Vo[ob + lane + 32] = v1;
}

// ---------------- attention: streaming softmax, 1 thread = 1 query row ------
__global__ __launch_bounds__(128) void attn_kernel(
    const float* __restrict__ Q, const float* __restrict__ Kt,
    const float* __restrict__ V, float* __restrict__ O)
{
    __shared__ float Ks[32 * 64];
    __shared__ float Vs[32 * 64];

    const int tid  = threadIdx.x;
    const int bh   = blockIdx.y;
    const int qrow = blockIdx.x * 128 + tid;

    const float* qp = Q + ((size_t)bh * S_ + qrow) * DH_;
    float4 q[16];
    #pragma unroll
    for (int i = 0; i < 16; i++) q[i] = ((const float4*)qp)[i];

    float4 o[16];
    #pragma unroll
    for (int i = 0; i < 16; i++) o[i] = make_float4(0.f, 0.f, 0.f, 0.f);
    float m = -1e30f, l = 0.f;

    const float* kb = Kt + (size_t)bh * S_ * DH_;
    const float* vb = V  + (size_t)bh * S_ * DH_;

    for (int t = 0; t < S_; t += 32) {
        // flat cooperative copy: 32x64 floats = 512 float4
        const float4* kg = (const float4*)(kb + (size_t)t * DH_);
        const float4* vg = (const float4*)(vb + (size_t)t * DH_);
        #pragma unroll
        for (int i = 0; i < 4; i++) {
            ((float4*)Ks)[tid + i * 128] = kg[tid + i * 128];
            ((float4*)Vs)[tid + i * 128] = vg[tid + i * 128];
        }
        __syncthreads();

        #pragma unroll 1
        for (int kj = 0; kj < 32; kj++) {
            const float4* kr = (const float4*)&Ks[kj * 64];
            float s = 0.f;
            #pragma unroll
            for (int i = 0; i < 16; i++) {
                float4 kv = kr[i];
                s = fmaf(q[i].x, kv.x, s);
                s = fmaf(q[i].y, kv.y, s);
                s = fmaf(q[i].z, kv.z, s);
                s = fmaf(q[i].w, kv.w, s);
            }
            if (s > m) {
                float corr = __expf(m - s);
                l *= corr;
                #pragma unroll
                for (int i = 0; i < 16; i++) {
                    o[i].x *= corr; o[i].y *= corr; o[i].z *= corr; o[i].w *= corr;
                }
                m = s;
            }
            float p = __expf(s - m);
            l += p;
            const float4* vr = (const float4*)&Vs[kj * 64];
            #pragma unroll
            for (int i = 0; i < 16; i++) {
                float4 vv = vr[i];
                o[i].x = fmaf(p, vv.x, o[i].x);
                o[i].y = fmaf(p, vv.y, o[i].y);
                o[i].z = fmaf(p, vv.z, o[i].z);
                o[i].w = fmaf(p, vv.w, o[i].w);
            }
        }
        __syncthreads();
    }

    const float inv = 1.f / l;
    const int b = bh >> 4, h = bh & 15;
    float* op = O + ((size_t)(b * S_ + qrow)) * D_ + h * DH_;
    #pragma unroll
    for (int i = 0; i < 16; i++) {
        float4 ov = o[i];
        ov.x *= inv; ov.y *= inv; ov.z *= inv; ov.w *= inv;
        ((float4*)op)[i] = ov;
    }
}

// ---------------- LayerNorm --------------------------------------------------
__global__ __launch_bounds__(256) void ln_kernel(
    const float* __restrict__ X, const float* __restrict__ g,
    const float* __restrict__ bb, float* __restrict__ Y)
{
    __shared__ float red[16];
    const int row = blockIdx.x;
    const int tid = threadIdx.x;
    const float* xp = X + (size_t)row * D_;

    float4 x4 = ((const float4*)xp)[tid];
    float s  = x4.x + x4.y + x4.z + x4.w;
    float ss = x4.x * x4.x + x4.y * x4.y + x4.z * x4.z + x4.w * x4.w;

    #pragma unroll
    for (int off = 16; off; off >>= 1) {
        s  += __shfl_xor_sync(0xffffffffu, s,  off);
        ss += __shfl_xor_sync(0xffffffffu, ss, off);
    }
    const int wid = tid >> 5, lane = tid & 31;
    if (lane == 0) { red[wid] = s; red[wid + 8] = ss; }
    __syncthreads();
    if (wid == 0) {
        float a = (lane < 8) ? red[lane] : 0.f;
        float bsum = (lane < 8) ? red[lane + 8] : 0.f;
        #pragma unroll
        for (int off = 4; off; off >>= 1) {
            a    += __shfl_xor_sync(0xffffffffu, a,    off);
            bsum += __shfl_xor_sync(0xffffffffu, bsum, off);
        }
        if (lane == 0) { red[0] = a; red[1] = bsum; }
    }
    __syncthreads();
    const float mu  = red[0] * (1.0f / D_);
    const float var = red[1] * (1.0f / D_) - mu * mu;
    const float rstd = rsqrtf(var + 1e-5f);

    float4 g4 = ((const float4*)g)[tid];
    float4 b4 = ((const float4*)bb)[tid];
    float4 y;
    y.x = (x4.x - mu) * rstd * g4.x + b4.x;
    y.y = (x4.y - mu) * rstd * g4.y + b4.y;
    y.z = (x4.z - mu) * rstd * g4.z + b4.z;
    y.w = (x4.w - mu) * rstd * g4.w + b4.w;
    ((float4*)(Y + (size_t)row * D_))[tid] = y;
}

// ---------------- launch -----------------------------------------------------
extern "C" void kernel_launch(void* const* d_in, const int* in_sizes, int n_in,
                              void* d_out, int out_size)
{
    const float* Q     = (const float*)d_in[0];
    // d_in[1] (K), d_in[2] (V) unused by the reference
    const float* Wqkv  = (const float*)d_in[3];
    const float* bqkv  = (const float*)d_in[4];
    const float* q_sc  = (const float*)d_in[5];
    const float* k_sc  = (const float*)d_in[6];
    const float* ln_g  = (const float*)d_in[7];
    const float* ln_b  = (const float*)d_in[8];
    const float* W1    = (const float*)d_in[9];
    const float* b1    = (const float*)d_in[10];
    const float* W2    = (const float*)d_in[11];
    const float* b2    = (const float*)d_in[12];
    float* out = (float*)d_out;

    float *qkv, *qb, *kb, *vb, *att, *x, *h;
    cudaGetSymbolAddress((void**)&qkv, g_qkv);
    cudaGetSymbolAddress((void**)&qb,  g_q);
    cudaGetSymbolAddress((void**)&kb,  g_k);
    cudaGetSymbolAddress((void**)&vb,  g_v);
    cudaGetSymbolAddress((void**)&att, g_att);
    cudaGetSymbolAddress((void**)&x,   g_x);
    cudaGetSymbolAddress((void**)&h,   g_h);

    // 1) QKV projection: [8192,1024] @ [1024,3072]
    sgemm_kernel<0><<<dim3(3 * D_ / 128, BS_ / 128), 256>>>(
        Q, Wqkv, bqkv, nullptr, qkv, BS_, 3 * D_, D_);

    // 2) l2norm + scale + rotary -> q,k,v in [BH,S,dh]
    {
        int warps = BH_ * S_;
        int blocks = warps / 8;   // 8 warps/block
        transform_kernel<<<blocks, 256>>>(qkv, q_sc, k_sc, qb, kb, vb);
    }

    // 3) attention
    attn_kernel<<<dim3(S_ / 128, BH_), 128>>>(qb, kb, vb, att);

    // 4) LayerNorm -> x
    ln_kernel<<<BS_, 256>>>(att, ln_g, ln_b, x);

    // 5) FF1 + SiLU: [8192,1024]@[1024,2048]
    sgemm_kernel<1><<<dim3(FF_ / 128, BS_ / 128), 256>>>(
        x, W1, b1, nullptr, h, BS_, FF_, D_);

    // 6) FF2 + residual: [8192,2048]@[2048,1024] + x
    sgemm_kernel<2><<<dim3(D_ / 128, BS_ / 128), 256>>>(
        h, W2, b2, x, out, BS_, D_, FF_);
}

// round 5
// speedup vs baseline: 1.3123x; 1.3123x over previous
#include <cuda_runtime.h>
#include <cuda_bf16.h>
#include <mma.h>
#include <math.h>
#include <stdint.h>

using namespace nvcuda;

#define B_   4
#define S_   2048
#define H_   16
#define DH_  64
#define D_   1024
#define FF_  2048
#define BS_  (B_*S_)
#define BH_  (B_*H_)

// ---------------- scratch (device globals; no runtime allocation) -----------
__device__ float g_qkv[(size_t)BS_ * 3 * D_];
__device__ float g_q  [(size_t)BH_ * S_ * DH_];
__device__ float g_k  [(size_t)BH_ * S_ * DH_];
__device__ float g_v  [(size_t)BH_ * S_ * DH_];
__device__ float g_att[(size_t)BS_ * D_];
__device__ float g_x  [(size_t)BS_ * D_];
__device__ float g_h  [(size_t)BS_ * FF_];

// ---------------- split-bf16 helpers ----------------------------------------
__device__ __forceinline__ float bfres(float a) {
    return a - __bfloat162float(__float2bfloat16_rn(a));
}
__device__ __forceinline__ unsigned int packbf(float a, float b) {
    __nv_bfloat162 t;
    t.x = __float2bfloat16_rn(a);
    t.y = __float2bfloat16_rn(b);
    return *reinterpret_cast<unsigned int*>(&t);
}

// ============================================================================
// WMMA split-bf16 GEMM: C = act(A@B + bias) (+ residual)
// fp32 = bf16_hi + bf16_lo; acc += Ah*Bh + Ah*Bl + Al*Bh  (lo*lo dropped)
// CTA tile 128x128x32, 8 warps, warp tile 32x64 (2x4 wmma 16x16x16 tiles).
// MODE 0: plain   MODE 1: SiLU   MODE 2: add residual
// ============================================================================
#define LDA_ 40
#define LDB_ 136

template <int MODE>
__global__ __launch_bounds__(256, 1) void wmma_gemm(
    const float* __restrict__ A, const float* __restrict__ Bm,
    const float* __restrict__ bias, const float* __restrict__ res,
    float* __restrict__ C, int M, int N, int K)
{
    __shared__ __align__(16) unsigned char smem[38912];
    __nv_bfloat16* Ah = (__nv_bfloat16*)(smem);            // [128][40]
    __nv_bfloat16* Al = (__nv_bfloat16*)(smem + 10240);    // [128][40]
    __nv_bfloat16* Bh = (__nv_bfloat16*)(smem + 20480);    // [32][136]
    __nv_bfloat16* Bl = (__nv_bfloat16*)(smem + 29184);    // [32][136]
    float* fbuf = (float*)(smem);                          // [128][68] epilogue

    const int tid = threadIdx.x;
    const int wid = tid >> 5;
    const int wm  = wid & 3;     // m offset = wm*32
    const int wn  = wid >> 2;    // n offset = wn*64
    const int bx  = blockIdx.x, by = blockIdx.y;

    wmma::fragment<wmma::accumulator, 16, 16, 16, float> acc[2][4];
    #pragma unroll
    for (int i = 0; i < 2; i++) {
        #pragma unroll
        for (int j = 0; j < 4; j++) {
            wmma::fill_fragment(acc[i][j], 0.0f);
        }
    }

    // staging indices
    const int ar = tid >> 1;          // A row 0..127
    const int af = (tid & 1) * 4;     // A float4 slot base (0 or 4)
    const int br = tid >> 3;          // B row 0..31
    const int bf = (tid & 7) * 4;     // B float4 slot base 0..28

    const float* Ag = A + (size_t)(by * 128 + ar) * K;
    const float* Bg = Bm + (size_t)br * N + (size_t)bx * 128;

    float4 pa[4];
    float4 pb[4];
    #pragma unroll
    for (int j = 0; j < 4; j++) {
        pa[j] = *(const float4*)(Ag + (af + j) * 4);
        pb[j] = *(const float4*)(Bg + (bf + j) * 4);
    }

    for (int k0 = 0; k0 < K; k0 += 32) {
        // store staged tile (fp32 -> bf16 hi/lo)
        #pragma unroll
        for (int j = 0; j < 4; j++) {
            const int ca = (af + j) * 4;
            float4 v = pa[j];
            *(unsigned int*)(Ah + ar * LDA_ + ca)     = packbf(v.x, v.y);
            *(unsigned int*)(Ah + ar * LDA_ + ca + 2) = packbf(v.z, v.w);
            *(unsigned int*)(Al + ar * LDA_ + ca)     = packbf(bfres(v.x), bfres(v.y));
            *(unsigned int*)(Al + ar * LDA_ + ca + 2) = packbf(bfres(v.z), bfres(v.w));
            const int cb = (bf + j) * 4;
            float4 w = pb[j];
            *(unsigned int*)(Bh + br * LDB_ + cb)     = packbf(w.x, w.y);
            *(unsigned int*)(Bh + br * LDB_ + cb + 2) = packbf(w.z, w.w);
            *(unsigned int*)(Bl + br * LDB_ + cb)     = packbf(bfres(w.x), bfres(w.y));
            *(unsigned int*)(Bl + br * LDB_ + cb + 2) = packbf(bfres(w.z), bfres(w.w));
        }
        __syncthreads();

        // prefetch next k-chunk
        if (k0 + 32 < K) {
            #pragma unroll
            for (int j = 0; j < 4; j++) {
                pa[j] = *(const float4*)(Ag + k0 + 32 + (af + j) * 4);
                pb[j] = *(const float4*)(Bg + (size_t)(k0 + 32) * N + (bf + j) * 4);
            }
        }

        // compute 2 x k16 steps
        #pragma unroll
        for (int ks = 0; ks < 32; ks += 16) {
            wmma::fragment<wmma::matrix_a, 16, 16, 16, __nv_bfloat16, wmma::row_major> fah[2];
            wmma::fragment<wmma::matrix_a, 16, 16, 16, __nv_bfloat16, wmma::row_major> fal[2];
            wmma::fragment<wmma::matrix_b, 16, 16, 16, __nv_bfloat16, wmma::row_major> fbh[4];
            wmma::fragment<wmma::matrix_b, 16, 16, 16, __nv_bfloat16, wmma::row_major> fbl[4];
            #pragma unroll
            for (int i = 0; i < 2; i++) {
                wmma::load_matrix_sync(fah[i], Ah + (wm * 32 + i * 16) * LDA_ + ks, LDA_);
                wmma::load_matrix_sync(fal[i], Al + (wm * 32 + i * 16) * LDA_ + ks, LDA_);
            }
            #pragma unroll
            for (int j = 0; j < 4; j++) {
                wmma::load_matrix_sync(fbh[j], Bh + ks * LDB_ + wn * 64 + j * 16, LDB_);
                wmma::load_matrix_sync(fbl[j], Bl + ks * LDB_ + wn * 64 + j * 16, LDB_);
            }
            #pragma unroll
            for (int i = 0; i < 2; i++) {
                #pragma unroll
                for (int j = 0; j < 4; j++) {
                    wmma::mma_sync(acc[i][j], fah[i], fbh[j], acc[i][j]);
                    wmma::mma_sync(acc[i][j], fah[i], fbl[j], acc[i][j]);
                    wmma::mma_sync(acc[i][j], fal[i], fbh[j], acc[i][j]);
                }
            }
        }
        __syncthreads();
    }

    // epilogue: two passes through fbuf (halves of N)
    #pragma unroll
    for (int p = 0; p < 2; p++) {
        __syncthreads();
        if (wn == p) {
            #pragma unroll
            for (int i = 0; i < 2; i++) {
                #pragma unroll
                for (int j = 0; j < 4; j++) {
                    wmma::store_matrix_sync(fbuf + (wm * 32 + i * 16) * 68 + j * 16,
                                            acc[i][j], 68, wmma::mem_row_major);
                }
            }
        }
        __syncthreads();

        const int ncol0 = bx * 128 + p * 64;
        #pragma unroll
        for (int it = 0; it < 8; it++) {
            const int idx = tid + it * 256;       // 0..2047
            const int r = idx >> 4;               // 0..127
            const int c = (idx & 15) * 4;         // 0..60
            float4 v = *(const float4*)(fbuf + r * 68 + c);
            float4 b4 = *(const float4*)(bias + ncol0 + c);
            v.x += b4.x; v.y += b4.y; v.z += b4.z; v.w += b4.w;
            if (MODE == 1) {
                v.x = v.x / (1.f + __expf(-v.x));
                v.y = v.y / (1.f + __expf(-v.y));
                v.z = v.z / (1.f + __expf(-v.z));
                v.w = v.w / (1.f + __expf(-v.w));
            }
            const size_t grow = (size_t)(by * 128 + r);
            if (MODE == 2) {
                float4 r4 = *(const float4*)(res + grow * N + ncol0 + c);
                v.x += r4.x; v.y += r4.y; v.z += r4.z; v.w += r4.w;
            }
            *(float4*)(C + grow * N + ncol0 + c) = v;
        }
    }
}

// ---------------- QKV transform: l2norm + scale + xpos rotary ---------------
__global__ __launch_bounds__(256) void transform_kernel(
    const float* __restrict__ qkv,
    const float* __restrict__ q_scale, const float* __restrict__ k_scale,
    float* __restrict__ Qo, float* __restrict__ Ko, float* __restrict__ Vo)
{
    const int gw   = (blockIdx.x * blockDim.x + threadIdx.x) >> 5;
    const int lane = threadIdx.x & 31;
    const int s  = gw & (S_ - 1);
    const int bh = gw >> 11;
    if (bh >= BH_) return;
    const int b = bh >> 4, h = bh & 15;

    const float* base = qkv + ((size_t)(b * S_ + s)) * (3 * D_) + h * (3 * DH_);
    float q0 = base[lane],       q1 = base[lane + 32];
    float k0 = base[64 + lane],  k1 = base[96 + lane];
    float v0 = base[128 + lane], v1 = base[160 + lane];

    float nq = q0 * q0 + q1 * q1;
    float nk = k0 * k0 + k1 * k1;
    #pragma unroll
    for (int off = 16; off; off >>= 1) {
        nq += __shfl_xor_sync(0xffffffffu, nq, off);
        nk += __shfl_xor_sync(0xffffffffu, nk, off);
    }
    nq = fmaxf(sqrtf(nq), 1e-12f);
    nk = fmaxf(sqrtf(nk), 1e-12f);

    q0 = q0 / nq * q_scale[lane]; q1 = q1 / nq * q_scale[lane + 32];
    k0 = k0 / nk * k_scale[lane]; k1 = k1 / nk * k_scale[lane + 32];

    const float d2 = 2.0f * (float)lane;
    const float inv_freq = exp2f(-d2 * (13.287712379549449f / 64.0f));
    const float fr = (float)s * inv_freq;
    float sn, c;
    sincosf(fr, &sn, &c);

    const float basev = (d2 + 0.4f * 64.0f) / (1.4f * 64.0f);
    const float power = ((float)s - (float)(S_ / 2)) / 512.0f;
    const float scale = exp2f(power * log2f(basev));
    const float iscale = 1.0f / scale;

    const float qo0 = (q0 * c - q1 * sn) * scale;
    const float qo1 = (q1 * c + q0 * sn) * scale;
    const float ko0 = (k0 * c - k1 * sn) * iscale;
    const float ko1 = (k1 * c + k0 * sn) * iscale;

    const size_t ob = ((size_t)bh * S_ + s) * DH_;
    Qo[ob + lane]      = qo0 * 0.125f;
    Qo[ob + lane + 32] = qo1 * 0.125f;
    Ko[ob + lane]      = ko0;
    Ko[ob + lane + 32] = ko1;
    Vo[ob + lane]      = v0;
    Vo[ob + lane + 32] = v1;
}

// ---------------- attention: streaming softmax, 1 thread = 1 query row ------
__global__ __launch_bounds__(128) void attn_kernel(
    const float* __restrict__ Q, const float* __restrict__ Kt,
    const float* __restrict__ V, float* __restrict__ O)
{
    __shared__ float Ks[32 * 64];
    __shared__ float Vs[32 * 64];

    const int tid  = threadIdx.x;
    const int bh   = blockIdx.y;
    const int qrow = blockIdx.x * 128 + tid;

    const float* qp = Q + ((size_t)bh * S_ + qrow) * DH_;
    float4 q[16];
    #pragma unroll
    for (int i = 0; i < 16; i++) q[i] = ((const float4*)qp)[i];

    float4 o[16];
    #pragma unroll
    for (int i = 0; i < 16; i++) o[i] = make_float4(0.f, 0.f, 0.f, 0.f);
    float m = -1e30f, l = 0.f;

    const float* kb = Kt + (size_t)bh * S_ * DH_;
    const float* vb = V  + (size_t)bh * S_ * DH_;

    for (int t = 0; t < S_; t += 32) {
        const float4* kg = (const float4*)(kb + (size_t)t * DH_);
        const float4* vg = (const float4*)(vb + (size_t)t * DH_);
        #pragma unroll
        for (int i = 0; i < 4; i++) {
            ((float4*)Ks)[tid + i * 128] = kg[tid + i * 128];
            ((float4*)Vs)[tid + i * 128] = vg[tid + i * 128];
        }
        __syncthreads();

        #pragma unroll 1
        for (int kj = 0; kj < 32; kj++) {
            const float4* kr = (const float4*)&Ks[kj * 64];
            float s = 0.f;
            #pragma unroll
            for (int i = 0; i < 16; i++) {
                float4 kv = kr[i];
                s = fmaf(q[i].x, kv.x, s);
                s = fmaf(q[i].y, kv.y, s);
                s = fmaf(q[i].z, kv.z, s);
                s = fmaf(q[i].w, kv.w, s);
            }
            if (s > m) {
                float corr = __expf(m - s);
                l *= corr;
                #pragma unroll
                for (int i = 0; i < 16; i++) {
                    o[i].x *= corr; o[i].y *= corr; o[i].z *= corr; o[i].w *= corr;
                }
                m = s;
            }
            float p = __expf(s - m);
            l += p;
            const float4* vr = (const float4*)&Vs[kj * 64];
            #pragma unroll
            for (int i = 0; i < 16; i++) {
                float4 vv = vr[i];
                o[i].x = fmaf(p, vv.x, o[i].x);
                o[i].y = fmaf(p, vv.y, o[i].y);
                o[i].z = fmaf(p, vv.z, o[i].z);
                o[i].w = fmaf(p, vv.w, o[i].w);
            }
        }
        __syncthreads();
    }

    const float inv = 1.f / l;
    const int b = bh >> 4, h = bh & 15;
    float* op = O + ((size_t)(b * S_ + qrow)) * D_ + h * DH_;
    #pragma unroll
    for (int i = 0; i < 16; i++) {
        float4 ov = o[i];
        ov.x *= inv; ov.y *= inv; ov.z *= inv; ov.w *= inv;
        ((float4*)op)[i] = ov;
    }
}

// ---------------- LayerNorm --------------------------------------------------
__global__ __launch_bounds__(256) void ln_kernel(
    const float* __restrict__ X, const float* __restrict__ g,
    const float* __restrict__ bb, float* __restrict__ Y)
{
    __shared__ float red[16];
    const int row = blockIdx.x;
    const int tid = threadIdx.x;
    const float* xp = X + (size_t)row * D_;

    float4 x4 = ((const float4*)xp)[tid];
    float s  = x4.x + x4.y + x4.z + x4.w;
    float ss = x4.x * x4.x + x4.y * x4.y + x4.z * x4.z + x4.w * x4.w;

    #pragma unroll
    for (int off = 16; off; off >>= 1) {
        s  += __shfl_xor_sync(0xffffffffu, s,  off);
        ss += __shfl_xor_sync(0xffffffffu, ss, off);
    }
    const int wid = tid >> 5, lane = tid & 31;
    if (lane == 0) { red[wid] = s; red[wid + 8] = ss; }
    __syncthreads();
    if (wid == 0) {
        float a = (lane < 8) ? red[lane] : 0.f;
        float bsum = (lane < 8) ? red[lane + 8] : 0.f;
        #pragma unroll
        for (int off = 4; off; off >>= 1) {
            a    += __shfl_xor_sync(0xffffffffu, a,    off);
            bsum += __shfl_xor_sync(0xffffffffu, bsum, off);
        }
        if (lane == 0) { red[0] = a; red[1] = bsum; }
    }
    __syncthreads();
    const float mu  = red[0] * (1.0f / D_);
    const float var = red[1] * (1.0f / D_) - mu * mu;
    const float rstd = rsqrtf(var + 1e-5f);

    float4 g4 = ((const float4*)g)[tid];
    float4 b4 = ((const float4*)bb)[tid];
    float4 y;
    y.x = (x4.x - mu) * rstd * g4.x + b4.x;
    y.y = (x4.y - mu) * rstd * g4.y + b4.y;
    y.z = (x4.z - mu) * rstd * g4.z + b4.z;
    y.w = (x4.w - mu) * rstd * g4.w + b4.w;
    ((float4*)(Y + (size_t)row * D_))[tid] = y;
}

// ---------------- launch -----------------------------------------------------
extern "C" void kernel_launch(void* const* d_in, const int* in_sizes, int n_in,
                              void* d_out, int out_size)
{
    const float* Q     = (const float*)d_in[0];
    const float* Wqkv  = (const float*)d_in[3];
    const float* bqkv  = (const float*)d_in[4];
    const float* q_sc  = (const float*)d_in[5];
    const float* k_sc  = (const float*)d_in[6];
    const float* ln_g  = (const float*)d_in[7];
    const float* ln_b  = (const float*)d_in[8];
    const float* W1    = (const float*)d_in[9];
    const float* b1    = (const float*)d_in[10];
    const float* W2    = (const float*)d_in[11];
    const float* b2    = (const float*)d_in[12];
    float* out = (float*)d_out;

    float *qkv, *qb, *kb, *vb, *att, *x, *h;
    cudaGetSymbolAddress((void**)&qkv, g_qkv);
    cudaGetSymbolAddress((void**)&qb,  g_q);
    cudaGetSymbolAddress((void**)&kb,  g_k);
    cudaGetSymbolAddress((void**)&vb,  g_v);
    cudaGetSymbolAddress((void**)&att, g_att);
    cudaGetSymbolAddress((void**)&x,   g_x);
    cudaGetSymbolAddress((void**)&h,   g_h);

    // 1) QKV projection: [8192,1024] @ [1024,3072]
    wmma_gemm<0><<<dim3(3 * D_ / 128, BS_ / 128), 256>>>(
        Q, Wqkv, bqkv, nullptr, qkv, BS_, 3 * D_, D_);

    // 2) l2norm + scale + rotary
    transform_kernel<<<BH_ * S_ / 8, 256>>>(qkv, q_sc, k_sc, qb, kb, vb);

    // 3) attention
    attn_kernel<<<dim3(S_ / 128, BH_), 128>>>(qb, kb, vb, att);

    // 4) LayerNorm
    ln_kernel<<<BS_, 256>>>(att, ln_g, ln_b, x);

    // 5) FF1 + SiLU
    wmma_gemm<1><<<dim3(FF_ / 128, BS_ / 128), 256>>>(
        x, W1, b1, nullptr, h, BS_, FF_, D_);

    // 6) FF2 + residual
    wmma_gemm<2><<<dim3(D_ / 128, BS_ / 128), 256>>>(
        h, W2, b2, x, out, BS_, D_, FF_);
}

// round 6
// speedup vs baseline: 1.6431x; 1.2521x over previous
#include <cuda_runtime.h>
#include <cuda_bf16.h>
#include <mma.h>
#include <math.h>
#include <stdint.h>

using namespace nvcuda;

#define B_   4
#define S_   2048
#define H_   16
#define DH_  64
#define D_   1024
#define FF_  2048
#define BS_  (B_*S_)
#define BH_  (B_*H_)

// ---------------- scratch (device globals; no runtime allocation) -----------
__device__ float g_qkv[(size_t)BS_ * 3 * D_];
__device__ float g_q  [(size_t)BH_ * S_ * DH_];
__device__ float g_k  [(size_t)BH_ * S_ * DH_];
__device__ float g_v  [(size_t)BH_ * S_ * DH_];
__device__ float g_att[(size_t)BS_ * D_];
__device__ float g_x  [(size_t)BS_ * D_];
__device__ float g_h  [(size_t)BS_ * FF_];

__device__ __forceinline__ float totf(float x) { return wmma::__float_to_tf32(x); }

// ============================================================================
// tf32 WMMA GEMM: C = act(A@B + bias) (+ residual)
// CTA tile 128x128x32, 8 warps, warp tile 32x64 (2x4 of m16n16k8 tiles).
// MODE 0: plain   MODE 1: SiLU   MODE 2: add residual
// ============================================================================
#define LDA_ 36
#define LDB_ 132

template <int MODE>
__global__ __launch_bounds__(256, 1) void tf32_gemm(
    const float* __restrict__ A, const float* __restrict__ Bm,
    const float* __restrict__ bias, const float* __restrict__ res,
    float* __restrict__ C, int M, int N, int K)
{
    __shared__ __align__(16) float smem[128 * LDA_ + 32 * LDB_]; // 35328 B
    float* As = smem;                 // [128][36]
    float* Bs = smem + 128 * LDA_;    // [32][132]
    float* fbuf = smem;               // [128][68] epilogue reuse

    const int tid = threadIdx.x;
    const int wid = tid >> 5;
    const int wm  = wid & 3;     // m offset = wm*32
    const int wn  = wid >> 2;    // n offset = wn*64
    const int bx  = blockIdx.x, by = blockIdx.y;

    wmma::fragment<wmma::accumulator, 16, 16, 8, float> acc[2][4];
    #pragma unroll
    for (int i = 0; i < 2; i++)
        #pragma unroll
        for (int j = 0; j < 4; j++)
            wmma::fill_fragment(acc[i][j], 0.0f);

    // staging: A rows 128 x 32k (2 thr/row, 16 floats each)
    const int ar = tid >> 1;
    const int af = (tid & 1) * 16;
    // B rows 32k x 128n (8 thr/row, 16 floats each)
    const int br = tid >> 3;
    const int bf = (tid & 7) * 16;

    const float* Ag = A + (size_t)(by * 128 + ar) * K + af;
    const float* Bg = Bm + (size_t)br * N + (size_t)bx * 128 + bf;

    float4 pa[4], pb[4];
    #pragma unroll
    for (int i = 0; i < 4; i++) {
        pa[i] = *(const float4*)(Ag + i * 4);
        pb[i] = *(const float4*)(Bg + i * 4);
    }

    for (int k0 = 0; k0 < K; k0 += 32) {
        #pragma unroll
        for (int i = 0; i < 4; i++) {
            float* ap = As + ar * LDA_ + af + i * 4;
            ap[0] = totf(pa[i].x); ap[1] = totf(pa[i].y);
            ap[2] = totf(pa[i].z); ap[3] = totf(pa[i].w);
            float* bp = Bs + br * LDB_ + bf + i * 4;
            bp[0] = totf(pb[i].x); bp[1] = totf(pb[i].y);
            bp[2] = totf(pb[i].z); bp[3] = totf(pb[i].w);
        }
        __syncthreads();

        if (k0 + 32 < K) {
            #pragma unroll
            for (int i = 0; i < 4; i++) {
                pa[i] = *(const float4*)(Ag + k0 + 32 + i * 4);
                pb[i] = *(const float4*)(Bg + (size_t)(k0 + 32) * N + i * 4);
            }
        }

        #pragma unroll
        for (int ks = 0; ks < 4; ks++) {
            wmma::fragment<wmma::matrix_a, 16, 16, 8, wmma::precision::tf32, wmma::row_major> fa[2];
            wmma::fragment<wmma::matrix_b, 16, 16, 8, wmma::precision::tf32, wmma::row_major> fb[4];
            #pragma unroll
            for (int i = 0; i < 2; i++)
                wmma::load_matrix_sync(fa[i], As + (wm * 32 + i * 16) * LDA_ + ks * 8, LDA_);
            #pragma unroll
            for (int j = 0; j < 4; j++)
                wmma::load_matrix_sync(fb[j], Bs + (ks * 8) * LDB_ + wn * 64 + j * 16, LDB_);
            #pragma unroll
            for (int i = 0; i < 2; i++)
                #pragma unroll
                for (int j = 0; j < 4; j++)
                    wmma::mma_sync(acc[i][j], fa[i], fb[j], acc[i][j]);
        }
        __syncthreads();
    }

    // epilogue: two passes through fbuf (halves of N)
    #pragma unroll
    for (int p = 0; p < 2; p++) {
        __syncthreads();
        if (wn == p) {
            #pragma unroll
            for (int i = 0; i < 2; i++)
                #pragma unroll
                for (int j = 0; j < 4; j++)
                    wmma::store_matrix_sync(fbuf + (wm * 32 + i * 16) * 68 + j * 16,
                                            acc[i][j], 68, wmma::mem_row_major);
        }
        __syncthreads();

        const int ncol0 = bx * 128 + p * 64;
        #pragma unroll
        for (int it = 0; it < 8; it++) {
            const int idx = tid + it * 256;
            const int r = idx >> 4;
            const int c = (idx & 15) * 4;
            float4 v = *(const float4*)(fbuf + r * 68 + c);
            float4 b4 = *(const float4*)(bias + ncol0 + c);
            v.x += b4.x; v.y += b4.y; v.z += b4.z; v.w += b4.w;
            if (MODE == 1) {
                v.x = v.x / (1.f + __expf(-v.x));
                v.y = v.y / (1.f + __expf(-v.y));
                v.z = v.z / (1.f + __expf(-v.z));
                v.w = v.w / (1.f + __expf(-v.w));
            }
            const size_t grow = (size_t)(by * 128 + r);
            if (MODE == 2) {
                float4 r4 = *(const float4*)(res + grow * N + ncol0 + c);
                v.x += r4.x; v.y += r4.y; v.z += r4.z; v.w += r4.w;
            }
            *(float4*)(C + grow * N + ncol0 + c) = v;
        }
    }
}

// ============================================================================
// tf32 WMMA flash attention (no max-tracking: |logit| <= ~19 fits fp32 exp)
// CTA: 128 q-rows x head. 8 warps (4x2), warp tile 32x32.
// SMEM: Q[128][72], K[64][72], V[64][72], P[128][72], L[128]
// ============================================================================
#define LDS_ 72
#define SM_Q 0
#define SM_K (128 * LDS_)
#define SM_V (SM_K + 64 * LDS_)
#define SM_P (SM_V + 64 * LDS_)
#define SM_L (SM_P + 128 * LDS_)
#define ATTN_SMEM ((SM_L + 128) * 4)

__global__ __launch_bounds__(256, 1) void fattn_kernel(
    const float* __restrict__ Q, const float* __restrict__ Kg,
    const float* __restrict__ Vg, float* __restrict__ O)
{
    extern __shared__ float sm[];
    float* sQ = sm + SM_Q;
    float* sK = sm + SM_K;
    float* sV = sm + SM_V;
    float* sP = sm + SM_P;
    float* sL = sm + SM_L;

    const int tid = threadIdx.x;
    const int wid = tid >> 5;
    const int wr  = wid >> 1;      // 0..3 -> m offset 32*wr
    const int wc  = wid & 1;       // 0..1 -> n offset 32*wc
    const int bh  = blockIdx.y;
    const int qt  = blockIdx.x;

    // load Q tile (tf32-rounded): 128 rows, 2 thr/row, 32 floats each
    {
        const int r = tid >> 1;
        const int c0 = (tid & 1) * 32;
        const float* qg = Q + ((size_t)bh * S_ + qt * 128 + r) * DH_ + c0;
        float* qs = sQ + r * LDS_ + c0;
        #pragma unroll
        for (int i = 0; i < 8; i++) {
            float4 v = ((const float4*)qg)[i];
            qs[i * 4 + 0] = totf(v.x); qs[i * 4 + 1] = totf(v.y);
            qs[i * 4 + 2] = totf(v.z); qs[i * 4 + 3] = totf(v.w);
        }
    }
    if (tid < 128) sL[tid] = 0.f;

    wmma::fragment<wmma::accumulator, 16, 16, 8, float> oacc[2][2];
    #pragma unroll
    for (int i = 0; i < 2; i++)
        #pragma unroll
        for (int j = 0; j < 2; j++)
            wmma::fill_fragment(oacc[i][j], 0.0f);

    // K/V staging: 64 rows, 4 thr/row, 16 floats each
    const int kr = tid >> 2;
    const int kc = (tid & 3) * 16;
    const float* kgp = Kg + ((size_t)bh * S_ + kr) * DH_ + kc;
    const float* vgp = Vg + ((size_t)bh * S_ + kr) * DH_ + kc;

    float4 pk[4], pv[4];
    #pragma unroll
    for (int i = 0; i < 4; i++) {
        pk[i] = *(const float4*)(kgp + i * 4);
        pv[i] = *(const float4*)(vgp + i * 4);
    }

    const int NT = S_ / 64;
    for (int kt = 0; kt < NT; kt++) {
        // store K/V tile (tf32)
        #pragma unroll
        for (int i = 0; i < 4; i++) {
            float* kp = sK + kr * LDS_ + kc + i * 4;
            kp[0] = totf(pk[i].x); kp[1] = totf(pk[i].y);
            kp[2] = totf(pk[i].z); kp[3] = totf(pk[i].w);
            float* vp = sV + kr * LDS_ + kc + i * 4;
            vp[0] = totf(pv[i].x); vp[1] = totf(pv[i].y);
            vp[2] = totf(pv[i].z); vp[3] = totf(pv[i].w);
        }
        __syncthreads();

        // prefetch next K/V tile
        if (kt + 1 < NT) {
            const size_t adv = (size_t)(kt + 1) * 64 * DH_;
            #pragma unroll
            for (int i = 0; i < 4; i++) {
                pk[i] = *(const float4*)(kgp + adv + i * 4);
                pv[i] = *(const float4*)(vgp + adv + i * 4);
            }
        }

        // S = Q @ K^T  (128x64)
        wmma::fragment<wmma::accumulator, 16, 16, 8, float> sacc[2][2];
        #pragma unroll
        for (int i = 0; i < 2; i++)
            #pragma unroll
            for (int j = 0; j < 2; j++)
                wmma::fill_fragment(sacc[i][j], 0.0f);

        #pragma unroll
        for (int ks = 0; ks < 8; ks++) {
            wmma::fragment<wmma::matrix_a, 16, 16, 8, wmma::precision::tf32, wmma::row_major> fa[2];
            wmma::fragment<wmma::matrix_b, 16, 16, 8, wmma::precision::tf32, wmma::col_major> fb[2];
            #pragma unroll
            for (int i = 0; i < 2; i++)
                wmma::load_matrix_sync(fa[i], sQ + (wr * 32 + i * 16) * LDS_ + ks * 8, LDS_);
            #pragma unroll
            for (int j = 0; j < 2; j++)
                wmma::load_matrix_sync(fb[j], sK + (wc * 32 + j * 16) * LDS_ + ks * 8, LDS_);
            #pragma unroll
            for (int i = 0; i < 2; i++)
                #pragma unroll
                for (int j = 0; j < 2; j++)
                    wmma::mma_sync(sacc[i][j], fa[i], fb[j], sacc[i][j]);
        }
        #pragma unroll
        for (int i = 0; i < 2; i++)
            #pragma unroll
            for (int j = 0; j < 2; j++)
                wmma::store_matrix_sync(sP + (wr * 32 + i * 16) * LDS_ + wc * 32 + j * 16,
                                        sacc[i][j], LDS_, wmma::mem_row_major);
        __syncthreads();

        // exp + row-sum + tf32 round (no max needed: |logit| <= ~19)
        {
            const int r = tid >> 1;
            const int c0 = (tid & 1) * 32;
            float* pr = sP + r * LDS_ + c0;
            float lsum = 0.f;
            #pragma unroll
            for (int i = 0; i < 32; i++) {
                float p = __expf(pr[i]);
                lsum += p;
                pr[i] = totf(p);
            }
            lsum += __shfl_xor_sync(0xffffffffu, lsum, 1);
            if ((tid & 1) == 0) sL[r] += lsum;
        }
        __syncthreads();

        // O += P @ V  (128x64 += 128x64 @ 64x64)
        #pragma unroll
        for (int ks = 0; ks < 8; ks++) {
            wmma::fragment<wmma::matrix_a, 16, 16, 8, wmma::precision::tf32, wmma::row_major> fa[2];
            wmma::fragment<wmma::matrix_b, 16, 16, 8, wmma::precision::tf32, wmma::row_major> fb[2];
            #pragma unroll
            for (int i = 0; i < 2; i++)
                wmma::load_matrix_sync(fa[i], sP + (wr * 32 + i * 16) * LDS_ + ks * 8, LDS_);
            #pragma unroll
            for (int j = 0; j < 2; j++)
                wmma::load_matrix_sync(fb[j], sV + (ks * 8) * LDS_ + wc * 32 + j * 16, LDS_);
            #pragma unroll
            for (int i = 0; i < 2; i++)
                #pragma unroll
                for (int j = 0; j < 2; j++)
                    wmma::mma_sync(oacc[i][j], fa[i], fb[j], oacc[i][j]);
        }
        __syncthreads();
    }

    // epilogue: O / l -> gmem [b, s, h*64+d]
    #pragma unroll
    for (int i = 0; i < 2; i++)
        #pragma unroll
        for (int j = 0; j < 2; j++)
            wmma::store_matrix_sync(sP + (wr * 32 + i * 16) * LDS_ + wc * 32 + j * 16,
                                    oacc[i][j], LDS_, wmma::mem_row_major);
    __syncthreads();

    {
        const int r = tid >> 1;
        const int c0 = (tid & 1) * 32;
        const float inv = 1.f / sL[r];
        const int qrow = qt * 128 + r;
        const int b = bh >> 4, h = bh & 15;
        float* op = O + ((size_t)(b * S_ + qrow)) * D_ + h * DH_ + c0;
        const float* pr = sP + r * LDS_ + c0;
        #pragma unroll
        for (int i = 0; i < 8; i++) {
            float4 v = ((const float4*)pr)[i];
            v.x *= inv; v.y *= inv; v.z *= inv; v.w *= inv;
            ((float4*)op)[i] = v;
        }
    }
}

// ---------------- QKV transform: l2norm + scale + xpos rotary ---------------
__global__ __launch_bounds__(256) void transform_kernel(
    const float* __restrict__ qkv,
    const float* __restrict__ q_scale, const float* __restrict__ k_scale,
    float* __restrict__ Qo, float* __restrict__ Ko, float* __restrict__ Vo)
{
    const int gw   = (blockIdx.x * blockDim.x + threadIdx.x) >> 5;
    const int lane = threadIdx.x & 31;
    const int s  = gw & (S_ - 1);
    const int bh = gw >> 11;
    if (bh >= BH_) return;
    const int b = bh >> 4, h = bh & 15;

    const float* base = qkv + ((size_t)(b * S_ + s)) * (3 * D_) + h * (3 * DH_);
    float q0 = base[lane],       q1 = base[lane + 32];
    float k0 = base[64 + lane],  k1 = base[96 + lane];
    float v0 = base[128 + lane], v1 = base[160 + lane];

    float nq = q0 * q0 + q1 * q1;
    float nk = k0 * k0 + k1 * k1;
    #pragma unroll
    for (int off = 16; off; off >>= 1) {
        nq += __shfl_xor_sync(0xffffffffu, nq, off);
        nk += __shfl_xor_sync(0xffffffffu, nk, off);
    }
    nq = fmaxf(sqrtf(nq), 1e-12f);
    nk = fmaxf(sqrtf(nk), 1e-12f);

    q0 = q0 / nq * q_scale[lane]; q1 = q1 / nq * q_scale[lane + 32];
    k0 = k0 / nk * k_scale[lane]; k1 = k1 / nk * k_scale[lane + 32];

    const float d2 = 2.0f * (float)lane;
    const float inv_freq = exp2f(-d2 * (13.287712379549449f / 64.0f));
    const float fr = (float)s * inv_freq;
    float sn, c;
    sincosf(fr, &sn, &c);

    const float basev = (d2 + 0.4f * 64.0f) / (1.4f * 64.0f);
    const float power = ((float)s - (float)(S_ / 2)) / 512.0f;
    const float scale = exp2f(power * log2f(basev));
    const float iscale = 1.0f / scale;

    const float qo0 = (q0 * c - q1 * sn) * scale;
    const float qo1 = (q1 * c + q0 * sn) * scale;
    const float ko0 = (k0 * c - k1 * sn) * iscale;
    const float ko1 = (k1 * c + k0 * sn) * iscale;

    const size_t ob = ((size_t)bh * S_ + s) * DH_;
    Qo[ob + lane]      = qo0 * 0.125f;
    Qo[ob + lane + 32] = qo1 * 0.125f;
    Ko[ob + lane]      = ko0;
    Ko[ob + lane + 32] = ko1;
    Vo[ob + lane]      = v0;
    Vo[ob + lane + 32] = v1;
}

// ---------------- LayerNorm --------------------------------------------------
__global__ __launch_bounds__(256) void ln_kernel(
    const float* __restrict__ X, const float* __restrict__ g,
    const float* __restrict__ bb, float* __restrict__ Y)
{
    __shared__ float red[16];
    const int row = blockIdx.x;
    const int tid = threadIdx.x;
    const float* xp = X + (size_t)row * D_;

    float4 x4 = ((const float4*)xp)[tid];
    float s  = x4.x + x4.y + x4.z + x4.w;
    float ss = x4.x * x4.x + x4.y * x4.y + x4.z * x4.z + x4.w * x4.w;

    #pragma unroll
    for (int off = 16; off; off >>= 1) {
        s  += __shfl_xor_sync(0xffffffffu, s,  off);
        ss += __shfl_xor_sync(0xffffffffu, ss, off);
    }
    const int wid = tid >> 5, lane = tid & 31;
    if (lane == 0) { red[wid] = s; red[wid + 8] = ss; }
    __syncthreads();
    if (wid == 0) {
        float a = (lane < 8) ? red[lane] : 0.f;
        float bsum = (lane < 8) ? red[lane + 8] : 0.f;
        #pragma unroll
        for (int off = 4; off; off >>= 1) {
            a    += __shfl_xor_sync(0xffffffffu, a,    off);
            bsum += __shfl_xor_sync(0xffffffffu, bsum, off);
        }
        if (lane == 0) { red[0] = a; red[1] = bsum; }
    }
    __syncthreads();
    const float mu  = red[0] * (1.0f / D_);
    const float var = red[1] * (1.0f / D_) - mu * mu;
    const float rstd = rsqrtf(var + 1e-5f);

    float4 g4 = ((const float4*)g)[tid];
    float4 b4 = ((const float4*)bb)[tid];
    float4 y;
    y.x = (x4.x - mu) * rstd * g4.x + b4.x;
    y.y = (x4.y - mu) * rstd * g4.y + b4.y;
    y.z = (x4.z - mu) * rstd * g4.z + b4.z;
    y.w = (x4.w - mu) * rstd * g4.w + b4.w;
    ((float4*)(Y + (size_t)row * D_))[tid] = y;
}

// ---------------- launch -----------------------------------------------------
extern "C" void kernel_launch(void* const* d_in, const int* in_sizes, int n_in,
                              void* d_out, int out_size)
{
    const float* Q     = (const float*)d_in[0];
    const float* Wqkv  = (const float*)d_in[3];
    const float* bqkv  = (const float*)d_in[4];
    const float* q_sc  = (const float*)d_in[5];
    const float* k_sc  = (const float*)d_in[6];
    const float* ln_g  = (const float*)d_in[7];
    const float* ln_b  = (const float*)d_in[8];
    const float* W1    = (const float*)d_in[9];
    const float* b1    = (const float*)d_in[10];
    const float* W2    = (const float*)d_in[11];
    const float* b2    = (const float*)d_in[12];
    float* out = (float*)d_out;

    float *qkv, *qb, *kb, *vb, *att, *x, *h;
    cudaGetSymbolAddress((void**)&qkv, g_qkv);
    cudaGetSymbolAddress((void**)&qb,  g_q);
    cudaGetSymbolAddress((void**)&kb,  g_k);
    cudaGetSymbolAddress((void**)&vb,  g_v);
    cudaGetSymbolAddress((void**)&att, g_att);
    cudaGetSymbolAddress((void**)&x,   g_x);
    cudaGetSymbolAddress((void**)&h,   g_h);

    cudaFuncSetAttribute(fattn_kernel,
                         cudaFuncAttributeMaxDynamicSharedMemorySize, ATTN_SMEM);

    // 1) QKV projection: [8192,1024] @ [1024,3072]
    tf32_gemm<0><<<dim3(3 * D_ / 128, BS_ / 128), 256>>>(
        Q, Wqkv, bqkv, nullptr, qkv, BS_, 3 * D_, D_);

    // 2) l2norm + scale + rotary
    transform_kernel<<<BH_ * S_ / 8, 256>>>(qkv, q_sc, k_sc, qb, kb, vb);

    // 3) flash attention (tf32 tensor cores)
    fattn_kernel<<<dim3(S_ / 128, BH_), 256, ATTN_SMEM>>>(qb, kb, vb, att);

    // 4) LayerNorm
    ln_kernel<<<BS_, 256>>>(att, ln_g, ln_b, x);

    // 5) FF1 + SiLU
    tf32_gemm<1><<<dim3(FF_ / 128, BS_ / 128), 256>>>(
        x, W1, b1, nullptr, h, BS_, FF_, D_);

    // 6) FF2 + residual
    tf32_gemm<2><<<dim3(D_ / 128, BS_ / 128), 256>>>(
        h, W2, b2, x, out, BS_, D_, FF_);
}

// round 7
// speedup vs baseline: 1.6512x; 1.0049x over previous
#include <cuda_runtime.h>
#include <cuda_bf16.h>
#include <mma.h>
#include <math.h>
#include <stdint.h>

using namespace nvcuda;

#define B_   4
#define S_   2048
#define H_   16
#define DH_  64
#define D_   1024
#define FF_  2048
#define BS_  (B_*S_)
#define BH_  (B_*H_)

// ---------------- scratch (device globals; no runtime allocation) -----------
__device__ float g_qkv[(size_t)BS_ * 3 * D_];
__device__ float g_q  [(size_t)BH_ * S_ * DH_];
__device__ float g_k  [(size_t)BH_ * S_ * DH_];
__device__ float g_v  [(size_t)BH_ * S_ * DH_];
__device__ float g_att[(size_t)BS_ * D_];
__device__ float g_x  [(size_t)BS_ * D_];
__device__ float g_h  [(size_t)BS_ * FF_];

__device__ __forceinline__ float totf(float x) { return wmma::__float_to_tf32(x); }

// ============================================================================
// tf32 WMMA GEMM: C = act(A@B + bias) (+ residual)
// CTA tile 128x128x32, 8 warps, warp tile 32x64 (2x4 of m16n16k8 tiles).
// MODE 0: plain   MODE 1: SiLU   MODE 2: add residual
// ============================================================================
#define LDA_ 36
#define LDB_ 132

template <int MODE>
__global__ __launch_bounds__(256, 2) void tf32_gemm(
    const float* __restrict__ A, const float* __restrict__ Bm,
    const float* __restrict__ bias, const float* __restrict__ res,
    float* __restrict__ C, int M, int N, int K)
{
    __shared__ __align__(16) float smem[128 * LDA_ + 32 * LDB_]; // 35328 B
    float* As = smem;                 // [128][36]
    float* Bs = smem + 128 * LDA_;    // [32][132]
    float* fbuf = smem;               // [128][68] epilogue reuse

    const int tid = threadIdx.x;
    const int wid = tid >> 5;
    const int wm  = wid & 3;     // m offset = wm*32
    const int wn  = wid >> 2;    // n offset = wn*64
    const int bx  = blockIdx.x, by = blockIdx.y;

    wmma::fragment<wmma::accumulator, 16, 16, 8, float> acc[2][4];
    #pragma unroll
    for (int i = 0; i < 2; i++)
        #pragma unroll
        for (int j = 0; j < 4; j++)
            wmma::fill_fragment(acc[i][j], 0.0f);

    // staging: A rows 128 x 32k (2 thr/row, 16 floats each)
    const int ar = tid >> 1;
    const int af = (tid & 1) * 16;
    // B rows 32k x 128n (8 thr/row, 16 floats each)
    const int br = tid >> 3;
    const int bf = (tid & 7) * 16;

    const float* Ag = A + (size_t)(by * 128 + ar) * K + af;
    const float* Bg = Bm + (size_t)br * N + (size_t)bx * 128 + bf;

    float4 pa[4], pb[4];
    #pragma unroll
    for (int i = 0; i < 4; i++) {
        pa[i] = *(const float4*)(Ag + i * 4);
        pb[i] = *(const float4*)(Bg + i * 4);
    }

    for (int k0 = 0; k0 < K; k0 += 32) {
        #pragma unroll
        for (int i = 0; i < 4; i++) {
            float* ap = As + ar * LDA_ + af + i * 4;
            ap[0] = totf(pa[i].x); ap[1] = totf(pa[i].y);
            ap[2] = totf(pa[i].z); ap[3] = totf(pa[i].w);
            float* bp = Bs + br * LDB_ + bf + i * 4;
            bp[0] = totf(pb[i].x); bp[1] = totf(pb[i].y);
            bp[2] = totf(pb[i].z); bp[3] = totf(pb[i].w);
        }
        __syncthreads();

        if (k0 + 32 < K) {
            #pragma unroll
            for (int i = 0; i < 4; i++) {
                pa[i] = *(const float4*)(Ag + k0 + 32 + i * 4);
                pb[i] = *(const float4*)(Bg + (size_t)(k0 + 32) * N + i * 4);
            }
        }

        #pragma unroll
        for (int ks = 0; ks < 4; ks++) {
            wmma::fragment<wmma::matrix_a, 16, 16, 8, wmma::precision::tf32, wmma::row_major> fa[2];
            wmma::fragment<wmma::matrix_b, 16, 16, 8, wmma::precision::tf32, wmma::row_major> fb[4];
            #pragma unroll
            for (int i = 0; i < 2; i++)
                wmma::load_matrix_sync(fa[i], As + (wm * 32 + i * 16) * LDA_ + ks * 8, LDA_);
            #pragma unroll
            for (int j = 0; j < 4; j++)
                wmma::load_matrix_sync(fb[j], Bs + (ks * 8) * LDB_ + wn * 64 + j * 16, LDB_);
            #pragma unroll
            for (int i = 0; i < 2; i++)
                #pragma unroll
                for (int j = 0; j < 4; j++)
                    wmma::mma_sync(acc[i][j], fa[i], fb[j], acc[i][j]);
        }
        __syncthreads();
    }

    // epilogue: two passes through fbuf (halves of N)
    #pragma unroll
    for (int p = 0; p < 2; p++) {
        __syncthreads();
        if (wn == p) {
            #pragma unroll
            for (int i = 0; i < 2; i++)
                #pragma unroll
                for (int j = 0; j < 4; j++)
                    wmma::store_matrix_sync(fbuf + (wm * 32 + i * 16) * 68 + j * 16,
                                            acc[i][j], 68, wmma::mem_row_major);
        }
        __syncthreads();

        const int ncol0 = bx * 128 + p * 64;
        #pragma unroll
        for (int it = 0; it < 8; it++) {
            const int idx = tid + it * 256;
            const int r = idx >> 4;
            const int c = (idx & 15) * 4;
            float4 v = *(const float4*)(fbuf + r * 68 + c);
            float4 b4 = *(const float4*)(bias + ncol0 + c);
            v.x += b4.x; v.y += b4.y; v.z += b4.z; v.w += b4.w;
            if (MODE == 1) {
                v.x = v.x / (1.f + __expf(-v.x));
                v.y = v.y / (1.f + __expf(-v.y));
                v.z = v.z / (1.f + __expf(-v.z));
                v.w = v.w / (1.f + __expf(-v.w));
            }
            const size_t grow = (size_t)(by * 128 + r);
            if (MODE == 2) {
                float4 r4 = *(const float4*)(res + grow * N + ncol0 + c);
                v.x += r4.x; v.y += r4.y; v.z += r4.z; v.w += r4.w;
            }
            *(float4*)(C + grow * N + ncol0 + c) = v;
        }
    }
}

// ============================================================================
// tf32 WMMA flash attention (no max-tracking: |logit| <= ~19 fits fp32 exp)
// CTA: 128 q-rows x head. 8 warps (4x2), warp tile 32x32.
// SMEM: Q[128][72], K[64][72], V[64][72], P[128][72], L[128]  (~108.5 KB)
// 2 CTAs/SM co-resident (228KB SMEM budget) to fill sync bubbles.
// ============================================================================
#define LDS_ 72
#define SM_Q 0
#define SM_K (128 * LDS_)
#define SM_V (SM_K + 64 * LDS_)
#define SM_P (SM_V + 64 * LDS_)
#define SM_L (SM_P + 128 * LDS_)
#define ATTN_SMEM ((SM_L + 128) * 4)

__global__ __launch_bounds__(256, 2) void fattn_kernel(
    const float* __restrict__ Q, const float* __restrict__ Kg,
    const float* __restrict__ Vg, float* __restrict__ O)
{
    extern __shared__ float sm[];
    float* sQ = sm + SM_Q;
    float* sK = sm + SM_K;
    float* sV = sm + SM_V;
    float* sP = sm + SM_P;
    float* sL = sm + SM_L;

    const int tid = threadIdx.x;
    const int wid = tid >> 5;
    const int wr  = wid >> 1;      // 0..3 -> m offset 32*wr
    const int wc  = wid & 1;       // 0..1 -> n offset 32*wc
    const int bh  = blockIdx.y;
    const int qt  = blockIdx.x;

    // load Q tile (tf32-rounded): 128 rows, 2 thr/row, 32 floats each
    {
        const int r = tid >> 1;
        const int c0 = (tid & 1) * 32;
        const float* qg = Q + ((size_t)bh * S_ + qt * 128 + r) * DH_ + c0;
        float* qs = sQ + r * LDS_ + c0;
        #pragma unroll
        for (int i = 0; i < 8; i++) {
            float4 v = ((const float4*)qg)[i];
            qs[i * 4 + 0] = totf(v.x); qs[i * 4 + 1] = totf(v.y);
            qs[i * 4 + 2] = totf(v.z); qs[i * 4 + 3] = totf(v.w);
        }
    }
    if (tid < 128) sL[tid] = 0.f;

    wmma::fragment<wmma::accumulator, 16, 16, 8, float> oacc[2][2];
    #pragma unroll
    for (int i = 0; i < 2; i++)
        #pragma unroll
        for (int j = 0; j < 2; j++)
            wmma::fill_fragment(oacc[i][j], 0.0f);

    // K/V staging: 64 rows, 4 thr/row, 16 floats each
    const int kr = tid >> 2;
    const int kc = (tid & 3) * 16;
    const float* kgp = Kg + ((size_t)bh * S_ + kr) * DH_ + kc;
    const float* vgp = Vg + ((size_t)bh * S_ + kr) * DH_ + kc;

    float4 pk[4], pv[4];
    #pragma unroll
    for (int i = 0; i < 4; i++) {
        pk[i] = *(const float4*)(kgp + i * 4);
        pv[i] = *(const float4*)(vgp + i * 4);
    }

    const int NT = S_ / 64;
    for (int kt = 0; kt < NT; kt++) {
        // store K/V tile (tf32)
        #pragma unroll
        for (int i = 0; i < 4; i++) {
            float* kp = sK + kr * LDS_ + kc + i * 4;
            kp[0] = totf(pk[i].x); kp[1] = totf(pk[i].y);
            kp[2] = totf(pk[i].z); kp[3] = totf(pk[i].w);
            float* vp = sV + kr * LDS_ + kc + i * 4;
            vp[0] = totf(pv[i].x); vp[1] = totf(pv[i].y);
            vp[2] = totf(pv[i].z); vp[3] = totf(pv[i].w);
        }
        __syncthreads();

        // prefetch next K/V tile
        if (kt + 1 < NT) {
            const size_t adv = (size_t)(kt + 1) * 64 * DH_;
            #pragma unroll
            for (int i = 0; i < 4; i++) {
                pk[i] = *(const float4*)(kgp + adv + i * 4);
                pv[i] = *(const float4*)(vgp + adv + i * 4);
            }
        }

        // S = Q @ K^T  (128x64)
        wmma::fragment<wmma::accumulator, 16, 16, 8, float> sacc[2][2];
        #pragma unroll
        for (int i = 0; i < 2; i++)
            #pragma unroll
            for (int j = 0; j < 2; j++)
                wmma::fill_fragment(sacc[i][j], 0.0f);

        #pragma unroll
        for (int ks = 0; ks < 8; ks++) {
            wmma::fragment<wmma::matrix_a, 16, 16, 8, wmma::precision::tf32, wmma::row_major> fa[2];
            wmma::fragment<wmma::matrix_b, 16, 16, 8, wmma::precision::tf32, wmma::col_major> fb[2];
            #pragma unroll
            for (int i = 0; i < 2; i++)
                wmma::load_matrix_sync(fa[i], sQ + (wr * 32 + i * 16) * LDS_ + ks * 8, LDS_);
            #pragma unroll
            for (int j = 0; j < 2; j++)
                wmma::load_matrix_sync(fb[j], sK + (wc * 32 + j * 16) * LDS_ + ks * 8, LDS_);
            #pragma unroll
            for (int i = 0; i < 2; i++)
                #pragma unroll
                for (int j = 0; j < 2; j++)
                    wmma::mma_sync(sacc[i][j], fa[i], fb[j], sacc[i][j]);
        }
        #pragma unroll
        for (int i = 0; i < 2; i++)
            #pragma unroll
            for (int j = 0; j < 2; j++)
                wmma::store_matrix_sync(sP + (wr * 32 + i * 16) * LDS_ + wc * 32 + j * 16,
                                        sacc[i][j], LDS_, wmma::mem_row_major);
        __syncthreads();

        // exp + row-sum + tf32 round (no max needed: |logit| <= ~19)
        {
            const int r = tid >> 1;
            const int c0 = (tid & 1) * 32;
            float* pr = sP + r * LDS_ + c0;
            float lsum = 0.f;
            #pragma unroll
            for (int i = 0; i < 32; i++) {
                float p = __expf(pr[i]);
                lsum += p;
                pr[i] = totf(p);
            }
            lsum += __shfl_xor_sync(0xffffffffu, lsum, 1);
            if ((tid & 1) == 0) sL[r] += lsum;
        }
        __syncthreads();

        // O += P @ V  (128x64 += 128x64 @ 64x64)
        #pragma unroll
        for (int ks = 0; ks < 8; ks++) {
            wmma::fragment<wmma::matrix_a, 16, 16, 8, wmma::precision::tf32, wmma::row_major> fa[2];
            wmma::fragment<wmma::matrix_b, 16, 16, 8, wmma::precision::tf32, wmma::row_major> fb[2];
            #pragma unroll
            for (int i = 0; i < 2; i++)
                wmma::load_matrix_sync(fa[i], sP + (wr * 32 + i * 16) * LDS_ + ks * 8, LDS_);
            #pragma unroll
            for (int j = 0; j < 2; j++)
                wmma::load_matrix_sync(fb[j], sV + (ks * 8) * LDS_ + wc * 32 + j * 16, LDS_);
            #pragma unroll
            for (int i = 0; i < 2; i++)
                #pragma unroll
                for (int j = 0; j < 2; j++)
                    wmma::mma_sync(oacc[i][j], fa[i], fb[j], oacc[i][j]);
        }
        __syncthreads();
    }

    // epilogue: O / l -> gmem [b, s, h*64+d]
    #pragma unroll
    for (int i = 0; i < 2; i++)
        #pragma unroll
        for (int j = 0; j < 2; j++)
            wmma::store_matrix_sync(sP + (wr * 32 + i * 16) * LDS_ + wc * 32 + j * 16,
                                    oacc[i][j], LDS_, wmma::mem_row_major);
    __syncthreads();

    {
        const int r = tid >> 1;
        const int c0 = (tid & 1) * 32;
        const float inv = 1.f / sL[r];
        const int qrow = qt * 128 + r;
        const int b = bh >> 4, h = bh & 15;
        float* op = O + ((size_t)(b * S_ + qrow)) * D_ + h * DH_ + c0;
        const float* pr = sP + r * LDS_ + c0;
        #pragma unroll
        for (int i = 0; i < 8; i++) {
            float4 v = ((const float4*)pr)[i];
            v.x *= inv; v.y *= inv; v.z *= inv; v.w *= inv;
            ((float4*)op)[i] = v;
        }
    }
}

// ---------------- QKV transform: l2norm + scale + xpos rotary ---------------
__global__ __launch_bounds__(256) void transform_kernel(
    const float* __restrict__ qkv,
    const float* __restrict__ q_scale, const float* __restrict__ k_scale,
    float* __restrict__ Qo, float* __restrict__ Ko, float* __restrict__ Vo)
{
    const int gw   = (blockIdx.x * blockDim.x + threadIdx.x) >> 5;
    const int lane = threadIdx.x & 31;
    const int s  = gw & (S_ - 1);
    const int bh = gw >> 11;
    if (bh >= BH_) return;
    const int b = bh >> 4, h = bh & 15;

    const float* base = qkv + ((size_t)(b * S_ + s)) * (3 * D_) + h * (3 * DH_);
    float q0 = base[lane],       q1 = base[lane + 32];
    float k0 = base[64 + lane],  k1 = base[96 + lane];
    float v0 = base[128 + lane], v1 = base[160 + lane];

    float nq = q0 * q0 + q1 * q1;
    float nk = k0 * k0 + k1 * k1;
    #pragma unroll
    for (int off = 16; off; off >>= 1) {
        nq += __shfl_xor_sync(0xffffffffu, nq, off);
        nk += __shfl_xor_sync(0xffffffffu, nk, off);
    }
    nq = fmaxf(sqrtf(nq), 1e-12f);
    nk = fmaxf(sqrtf(nk), 1e-12f);

    q0 = q0 / nq * q_scale[lane]; q1 = q1 / nq * q_scale[lane + 32];
    k0 = k0 / nk * k_scale[lane]; k1 = k1 / nk * k_scale[lane + 32];

    const float d2 = 2.0f * (float)lane;
    const float inv_freq = exp2f(-d2 * (13.287712379549449f / 64.0f));
    const float fr = (float)s * inv_freq;
    float sn, c;
    sincosf(fr, &sn, &c);

    const float basev = (d2 + 0.4f * 64.0f) / (1.4f * 64.0f);
    const float power = ((float)s - (float)(S_ / 2)) / 512.0f;
    const float scale = exp2f(power * log2f(basev));
    const float iscale = 1.0f / scale;

    const float qo0 = (q0 * c - q1 * sn) * scale;
    const float qo1 = (q1 * c + q0 * sn) * scale;
    const float ko0 = (k0 * c - k1 * sn) * iscale;
    const float ko1 = (k1 * c + k0 * sn) * iscale;

    const size_t ob = ((size_t)bh * S_ + s) * DH_;
    Qo[ob + lane]      = qo0 * 0.125f;
    Qo[ob + lane + 32] = qo1 * 0.125f;
    Ko[ob + lane]      = ko0;
    Ko[ob + lane + 32] = ko1;
    Vo[ob + lane]      = v0;
    Vo[ob + lane + 32] = v1;
}

// ---------------- LayerNorm --------------------------------------------------
__global__ __launch_bounds__(256) void ln_kernel(
    const float* __restrict__ X, const float* __restrict__ g,
    const float* __restrict__ bb, float* __restrict__ Y)
{
    __shared__ float red[16];
    const int row = blockIdx.x;
    const int tid = threadIdx.x;
    const float* xp = X + (size_t)row * D_;

    float4 x4 = ((const float4*)xp)[tid];
    float s  = x4.x + x4.y + x4.z + x4.w;
    float ss = x4.x * x4.x + x4.y * x4.y + x4.z * x4.z + x4.w * x4.w;

    #pragma unroll
    for (int off = 16; off; off >>= 1) {
        s  += __shfl_xor_sync(0xffffffffu, s,  off);
        ss += __shfl_xor_sync(0xffffffffu, ss, off);
    }
    const int wid = tid >> 5, lane = tid & 31;
    if (lane == 0) { red[wid] = s; red[wid + 8] = ss; }
    __syncthreads();
    if (wid == 0) {
        float a = (lane < 8) ? red[lane] : 0.f;
        float bsum = (lane < 8) ? red[lane + 8] : 0.f;
        #pragma unroll
        for (int off = 4; off; off >>= 1) {
            a    += __shfl_xor_sync(0xffffffffu, a,    off);
            bsum += __shfl_xor_sync(0xffffffffu, bsum, off);
        }
        if (lane == 0) { red[0] = a; red[1] = bsum; }
    }
    __syncthreads();
    const float mu  = red[0] * (1.0f / D_);
    const float var = red[1] * (1.0f / D_) - mu * mu;
    const float rstd = rsqrtf(var + 1e-5f);

    float4 g4 = ((const float4*)g)[tid];
    float4 b4 = ((const float4*)bb)[tid];
    float4 y;
    y.x = (x4.x - mu) * rstd * g4.x + b4.x;
    y.y = (x4.y - mu) * rstd * g4.y + b4.y;
    y.z = (x4.z - mu) * rstd * g4.z + b4.z;
    y.w = (x4.w - mu) * rstd * g4.w + b4.w;
    ((float4*)(Y + (size_t)row * D_))[tid] = y;
}

// ---------------- launch -----------------------------------------------------
extern "C" void kernel_launch(void* const* d_in, const int* in_sizes, int n_in,
                              void* d_out, int out_size)
{
    const float* Q     = (const float*)d_in[0];
    const float* Wqkv  = (const float*)d_in[3];
    const float* bqkv  = (const float*)d_in[4];
    const float* q_sc  = (const float*)d_in[5];
    const float* k_sc  = (const float*)d_in[6];
    const float* ln_g  = (const float*)d_in[7];
    const float* ln_b  = (const float*)d_in[8];
    const float* W1    = (const float*)d_in[9];
    const float* b1    = (const float*)d_in[10];
    const float* W2    = (const float*)d_in[11];
    const float* b2    = (const float*)d_in[12];
    float* out = (float*)d_out;

    float *qkv, *qb, *kb, *vb, *att, *x, *h;
    cudaGetSymbolAddress((void**)&qkv, g_qkv);
    cudaGetSymbolAddress((void**)&qb,  g_q);
    cudaGetSymbolAddress((void**)&kb,  g_k);
    cudaGetSymbolAddress((void**)&vb,  g_v);
    cudaGetSymbolAddress((void**)&att, g_att);
    cudaGetSymbolAddress((void**)&x,   g_x);
    cudaGetSymbolAddress((void**)&h,   g_h);

    cudaFuncSetAttribute(fattn_kernel,
                         cudaFuncAttributeMaxDynamicSharedMemorySize, ATTN_SMEM);

    // 1) QKV projection: [8192,1024] @ [1024,3072]
    tf32_gemm<0><<<dim3(3 * D_ / 128, BS_ / 128), 256>>>(
        Q, Wqkv, bqkv, nullptr, qkv, BS_, 3 * D_, D_);

    // 2) l2norm + scale + rotary
    transform_kernel<<<BH_ * S_ / 8, 256>>>(qkv, q_sc, k_sc, qb, kb, vb);

    // 3) flash attention (tf32 tensor cores)
    fattn_kernel<<<dim3(S_ / 128, BH_), 256, ATTN_SMEM>>>(qb, kb, vb, att);

    // 4) LayerNorm
    ln_kernel<<<BS_, 256>>>(att, ln_g, ln_b, x);

    // 5) FF1 + SiLU
    tf32_gemm<1><<<dim3(FF_ / 128, BS_ / 128), 256>>>(
        x, W1, b1, nullptr, h, BS_, FF_, D_);

    // 6) FF2 + residual
    tf32_gemm<2><<<dim3(D_ / 128, BS_ / 128), 256>>>(
        h, W2, b2, x, out, BS_, D_, FF_);
}

// round 8
// speedup vs baseline: 1.9400x; 1.1749x over previous
#include <cuda_runtime.h>
#include <cuda_bf16.h>
#include <mma.h>
#include <math.h>
#include <stdint.h>

using namespace nvcuda;

#define B_   4
#define S_   2048
#define H_   16
#define DH_  64
#define D_   1024
#define FF_  2048
#define BS_  (B_*S_)
#define BH_  (B_*H_)

// ---------------- scratch (device globals; no runtime allocation) -----------
__device__ float g_qkv[(size_t)BS_ * 3 * D_];
__device__ float g_q  [(size_t)BH_ * S_ * DH_];
__device__ float g_k  [(size_t)BH_ * S_ * DH_];
__device__ float g_v  [(size_t)BH_ * S_ * DH_];
__device__ float g_att[(size_t)BS_ * D_];
__device__ float g_x  [(size_t)BS_ * D_];
__device__ float g_h  [(size_t)BS_ * FF_];

// ---------------- split-bf16 helpers ----------------------------------------
__device__ __forceinline__ float bfres(float a) {
    return a - __bfloat162float(__float2bfloat16_rn(a));
}
__device__ __forceinline__ unsigned int packbf(float a, float b) {
    __nv_bfloat162 t;
    t.x = __float2bfloat16_rn(a);
    t.y = __float2bfloat16_rn(b);
    return *reinterpret_cast<unsigned int*>(&t);
}

// ============================================================================
// WMMA split-bf16 GEMM (measured ~477 TF/s raw in R4): C = act(A@B+bias)(+res)
// fp32 = bf16_hi + bf16_lo; acc += Ah*Bh + Ah*Bl + Al*Bh  (lo*lo dropped)
// CTA tile 128x128x32, 8 warps, warp tile 32x64.
// MODE 0: plain   MODE 1: SiLU   MODE 2: add residual
// ============================================================================
#define LDA_ 40
#define LDB_ 136

template <int MODE>
__global__ __launch_bounds__(256, 2) void wmma_gemm(
    const float* __restrict__ A, const float* __restrict__ Bm,
    const float* __restrict__ bias, const float* __restrict__ res,
    float* __restrict__ C, int M, int N, int K)
{
    __shared__ __align__(16) unsigned char smem[38912];
    __nv_bfloat16* Ah = (__nv_bfloat16*)(smem);            // [128][40]
    __nv_bfloat16* Al = (__nv_bfloat16*)(smem + 10240);    // [128][40]
    __nv_bfloat16* Bh = (__nv_bfloat16*)(smem + 20480);    // [32][136]
    __nv_bfloat16* Bl = (__nv_bfloat16*)(smem + 29184);    // [32][136]
    float* fbuf = (float*)(smem);                          // [128][68] epilogue

    const int tid = threadIdx.x;
    const int wid = tid >> 5;
    const int wm  = wid & 3;     // m offset = wm*32
    const int wn  = wid >> 2;    // n offset = wn*64
    const int bx  = blockIdx.x, by = blockIdx.y;

    wmma::fragment<wmma::accumulator, 16, 16, 16, float> acc[2][4];
    #pragma unroll
    for (int i = 0; i < 2; i++)
        #pragma unroll
        for (int j = 0; j < 4; j++)
            wmma::fill_fragment(acc[i][j], 0.0f);

    const int ar = tid >> 1;          // A row 0..127
    const int af = (tid & 1) * 4;     // A float4 slot base (0 or 4)
    const int br = tid >> 3;          // B row 0..31
    const int bf = (tid & 7) * 4;     // B float4 slot base 0..28

    const float* Ag = A + (size_t)(by * 128 + ar) * K;
    const float* Bg = Bm + (size_t)br * N + (size_t)bx * 128;

    float4 pa[4];
    float4 pb[4];
    #pragma unroll
    for (int j = 0; j < 4; j++) {
        pa[j] = *(const float4*)(Ag + (af + j) * 4);
        pb[j] = *(const float4*)(Bg + (bf + j) * 4);
    }

    for (int k0 = 0; k0 < K; k0 += 32) {
        #pragma unroll
        for (int j = 0; j < 4; j++) {
            const int ca = (af + j) * 4;
            float4 v = pa[j];
            *(unsigned int*)(Ah + ar * LDA_ + ca)     = packbf(v.x, v.y);
            *(unsigned int*)(Ah + ar * LDA_ + ca + 2) = packbf(v.z, v.w);
            *(unsigned int*)(Al + ar * LDA_ + ca)     = packbf(bfres(v.x), bfres(v.y));
            *(unsigned int*)(Al + ar * LDA_ + ca + 2) = packbf(bfres(v.z), bfres(v.w));
            const int cb = (bf + j) * 4;
            float4 w = pb[j];
            *(unsigned int*)(Bh + br * LDB_ + cb)     = packbf(w.x, w.y);
            *(unsigned int*)(Bh + br * LDB_ + cb + 2) = packbf(w.z, w.w);
            *(unsigned int*)(Bl + br * LDB_ + cb)     = packbf(bfres(w.x), bfres(w.y));
            *(unsigned int*)(Bl + br * LDB_ + cb + 2) = packbf(bfres(w.z), bfres(w.w));
        }
        __syncthreads();

        if (k0 + 32 < K) {
            #pragma unroll
            for (int j = 0; j < 4; j++) {
                pa[j] = *(const float4*)(Ag + k0 + 32 + (af + j) * 4);
                pb[j] = *(const float4*)(Bg + (size_t)(k0 + 32) * N + (bf + j) * 4);
            }
        }

        #pragma unroll
        for (int ks = 0; ks < 32; ks += 16) {
            wmma::fragment<wmma::matrix_a, 16, 16, 16, __nv_bfloat16, wmma::row_major> fah[2];
            wmma::fragment<wmma::matrix_a, 16, 16, 16, __nv_bfloat16, wmma::row_major> fal[2];
            wmma::fragment<wmma::matrix_b, 16, 16, 16, __nv_bfloat16, wmma::row_major> fbh[4];
            wmma::fragment<wmma::matrix_b, 16, 16, 16, __nv_bfloat16, wmma::row_major> fbl[4];
            #pragma unroll
            for (int i = 0; i < 2; i++) {
                wmma::load_matrix_sync(fah[i], Ah + (wm * 32 + i * 16) * LDA_ + ks, LDA_);
                wmma::load_matrix_sync(fal[i], Al + (wm * 32 + i * 16) * LDA_ + ks, LDA_);
            }
            #pragma unroll
            for (int j = 0; j < 4; j++) {
                wmma::load_matrix_sync(fbh[j], Bh + ks * LDB_ + wn * 64 + j * 16, LDB_);
                wmma::load_matrix_sync(fbl[j], Bl + ks * LDB_ + wn * 64 + j * 16, LDB_);
            }
            #pragma unroll
            for (int i = 0; i < 2; i++) {
                #pragma unroll
                for (int j = 0; j < 4; j++) {
                    wmma::mma_sync(acc[i][j], fah[i], fbh[j], acc[i][j]);
                    wmma::mma_sync(acc[i][j], fah[i], fbl[j], acc[i][j]);
                    wmma::mma_sync(acc[i][j], fal[i], fbh[j], acc[i][j]);
                }
            }
        }
        __syncthreads();
    }

    // epilogue: two passes through fbuf (halves of N)
    #pragma unroll
    for (int p = 0; p < 2; p++) {
        __syncthreads();
        if (wn == p) {
            #pragma unroll
            for (int i = 0; i < 2; i++)
                #pragma unroll
                for (int j = 0; j < 4; j++)
                    wmma::store_matrix_sync(fbuf + (wm * 32 + i * 16) * 68 + j * 16,
                                            acc[i][j], 68, wmma::mem_row_major);
        }
        __syncthreads();

        const int ncol0 = bx * 128 + p * 64;
        #pragma unroll
        for (int it = 0; it < 8; it++) {
            const int idx = tid + it * 256;
            const int r = idx >> 4;
            const int c = (idx & 15) * 4;
            float4 v = *(const float4*)(fbuf + r * 68 + c);
            float4 b4 = *(const float4*)(bias + ncol0 + c);
            v.x += b4.x; v.y += b4.y; v.z += b4.z; v.w += b4.w;
            if (MODE == 1) {
                v.x = v.x / (1.f + __expf(-v.x));
                v.y = v.y / (1.f + __expf(-v.y));
                v.z = v.z / (1.f + __expf(-v.z));
                v.w = v.w / (1.f + __expf(-v.w));
            }
            const size_t grow = (size_t)(by * 128 + r);
            if (MODE == 2) {
                float4 r4 = *(const float4*)(res + grow * N + ncol0 + c);
                v.x += r4.x; v.y += r4.y; v.z += r4.z; v.w += r4.w;
            }
            *(float4*)(C + grow * N + ncol0 + c) = v;
        }
    }
}

// ============================================================================
// split-bf16 WMMA flash attention (no max-tracking: |logit| <= ~19)
// CTA: 128 q-rows x head, 8 warps (4x2), warp tile 32x32, key tile 64.
// hi/lo bf16 planes for Q, K, V, P; 3 MMA passes per product.
// SMEM byte layout (111104 total, 2 CTAs/SM):
//   Qh 0..18432, Ql ..36864, Kh ..46080, Kl ..55296, Vh ..64512, Vl ..73728,
//   S(fp32 [128][68]) overlays Ph/Pl at 73728..110592, L at 110592 (512B)
// ============================================================================
#define FLDS 72     // bf16 row stride (elements)
#define FLDF 68     // fp32 S row stride (elements)
#define ATTN_SMEM 111104

__global__ __launch_bounds__(256, 2) void fattn_kernel(
    const float* __restrict__ Q, const float* __restrict__ Kg,
    const float* __restrict__ Vg, float* __restrict__ O)
{
    extern __shared__ unsigned char smc[];
    __nv_bfloat16* qh = (__nv_bfloat16*)(smc);
    __nv_bfloat16* ql = (__nv_bfloat16*)(smc + 18432);
    __nv_bfloat16* kh = (__nv_bfloat16*)(smc + 36864);
    __nv_bfloat16* kl = (__nv_bfloat16*)(smc + 46080);
    __nv_bfloat16* vh = (__nv_bfloat16*)(smc + 55296);
    __nv_bfloat16* vl = (__nv_bfloat16*)(smc + 64512);
    float*         sS = (float*)(smc + 73728);
    __nv_bfloat16* ph = (__nv_bfloat16*)(smc + 73728);
    __nv_bfloat16* pl = (__nv_bfloat16*)(smc + 92160);
    float*         sL = (float*)(smc + 110592);

    const int tid = threadIdx.x;
    const int wid = tid >> 5;
    const int wr  = wid >> 1;      // 0..3 -> m offset 32*wr
    const int wc  = wid & 1;       // 0..1 -> n offset 32*wc
    const int bh  = blockIdx.y;
    const int qt  = blockIdx.x;

    // load Q tile -> hi/lo bf16: 128 rows, 2 thr/row, 32 floats each
    {
        const int r = tid >> 1;
        const int c0 = (tid & 1) * 32;
        const float* qg = Q + ((size_t)bh * S_ + qt * 128 + r) * DH_ + c0;
        #pragma unroll
        for (int i = 0; i < 8; i++) {
            float4 v = ((const float4*)qg)[i];
            *(unsigned int*)(qh + r * FLDS + c0 + i * 4)     = packbf(v.x, v.y);
            *(unsigned int*)(qh + r * FLDS + c0 + i * 4 + 2) = packbf(v.z, v.w);
            *(unsigned int*)(ql + r * FLDS + c0 + i * 4)     = packbf(bfres(v.x), bfres(v.y));
            *(unsigned int*)(ql + r * FLDS + c0 + i * 4 + 2) = packbf(bfres(v.z), bfres(v.w));
        }
    }
    if (tid < 128) sL[tid] = 0.f;

    wmma::fragment<wmma::accumulator, 16, 16, 16, float> oacc[2][2];
    #pragma unroll
    for (int i = 0; i < 2; i++)
        #pragma unroll
        for (int j = 0; j < 2; j++)
            wmma::fill_fragment(oacc[i][j], 0.0f);

    // K/V staging: 64 rows, 4 thr/row, 16 floats each
    const int kr = tid >> 2;
    const int kc = (tid & 3) * 16;
    const float* kgp = Kg + ((size_t)bh * S_ + kr) * DH_ + kc;
    const float* vgp = Vg + ((size_t)bh * S_ + kr) * DH_ + kc;

    float4 pk[4], pv[4];
    #pragma unroll
    for (int i = 0; i < 4; i++) {
        pk[i] = *(const float4*)(kgp + i * 4);
        pv[i] = *(const float4*)(vgp + i * 4);
    }

    const int NT = S_ / 64;
    for (int kt = 0; kt < NT; kt++) {
        // store K/V tile hi/lo
        #pragma unroll
        for (int i = 0; i < 4; i++) {
            const int c = kc + i * 4;
            float4 k4 = pk[i];
            *(unsigned int*)(kh + kr * FLDS + c)     = packbf(k4.x, k4.y);
            *(unsigned int*)(kh + kr * FLDS + c + 2) = packbf(k4.z, k4.w);
            *(unsigned int*)(kl + kr * FLDS + c)     = packbf(bfres(k4.x), bfres(k4.y));
            *(unsigned int*)(kl + kr * FLDS + c + 2) = packbf(bfres(k4.z), bfres(k4.w));
            float4 v4 = pv[i];
            *(unsigned int*)(vh + kr * FLDS + c)     = packbf(v4.x, v4.y);
            *(unsigned int*)(vh + kr * FLDS + c + 2) = packbf(v4.z, v4.w);
            *(unsigned int*)(vl + kr * FLDS + c)     = packbf(bfres(v4.x), bfres(v4.y));
            *(unsigned int*)(vl + kr * FLDS + c + 2) = packbf(bfres(v4.z), bfres(v4.w));
        }
        __syncthreads();

        // prefetch next K/V tile
        if (kt + 1 < NT) {
            const size_t adv = (size_t)(kt + 1) * 64 * DH_;
            #pragma unroll
            for (int i = 0; i < 4; i++) {
                pk[i] = *(const float4*)(kgp + adv + i * 4);
                pv[i] = *(const float4*)(vgp + adv + i * 4);
            }
        }

        // S = Q @ K^T (128x64), 3 split passes
        wmma::fragment<wmma::accumulator, 16, 16, 16, float> sacc[2][2];
        #pragma unroll
        for (int i = 0; i < 2; i++)
            #pragma unroll
            for (int j = 0; j < 2; j++)
                wmma::fill_fragment(sacc[i][j], 0.0f);

        #pragma unroll
        for (int ks = 0; ks < 4; ks++) {
            wmma::fragment<wmma::matrix_a, 16, 16, 16, __nv_bfloat16, wmma::row_major> aqh[2], aql[2];
            wmma::fragment<wmma::matrix_b, 16, 16, 16, __nv_bfloat16, wmma::col_major> bkh[2], bkl[2];
            #pragma unroll
            for (int i = 0; i < 2; i++) {
                wmma::load_matrix_sync(aqh[i], qh + (wr * 32 + i * 16) * FLDS + ks * 16, FLDS);
                wmma::load_matrix_sync(aql[i], ql + (wr * 32 + i * 16) * FLDS + ks * 16, FLDS);
            }
            #pragma unroll
            for (int j = 0; j < 2; j++) {
                wmma::load_matrix_sync(bkh[j], kh + (wc * 32 + j * 16) * FLDS + ks * 16, FLDS);
                wmma::load_matrix_sync(bkl[j], kl + (wc * 32 + j * 16) * FLDS + ks * 16, FLDS);
            }
            #pragma unroll
            for (int i = 0; i < 2; i++)
                #pragma unroll
                for (int j = 0; j < 2; j++) {
                    wmma::mma_sync(sacc[i][j], aqh[i], bkh[j], sacc[i][j]);
                    wmma::mma_sync(sacc[i][j], aqh[i], bkl[j], sacc[i][j]);
                    wmma::mma_sync(sacc[i][j], aql[i], bkh[j], sacc[i][j]);
                }
        }
        #pragma unroll
        for (int i = 0; i < 2; i++)
            #pragma unroll
            for (int j = 0; j < 2; j++)
                wmma::store_matrix_sync(sS + (wr * 32 + i * 16) * FLDF + wc * 32 + j * 16,
                                        sacc[i][j], FLDF, wmma::mem_row_major);
        __syncthreads();

        // exp + row-sum; write P hi/lo (overlays S after barrier)
        {
            const int r = tid >> 1;
            const int c0 = (tid & 1) * 32;
            const float* sr = sS + r * FLDF + c0;
            float pvreg[32];
            float lsum = 0.f;
            #pragma unroll
            for (int i = 0; i < 32; i++) {
                float p = __expf(sr[i]);
                pvreg[i] = p;
                lsum += p;
            }
            __syncthreads();   // all S reads done before overwriting as ph/pl
            #pragma unroll
            for (int i = 0; i < 16; i++) {
                float a = pvreg[2 * i], b = pvreg[2 * i + 1];
                *(unsigned int*)(ph + r * FLDS + c0 + 2 * i) = packbf(a, b);
                *(unsigned int*)(pl + r * FLDS + c0 + 2 * i) = packbf(bfres(a), bfres(b));
            }
            lsum += __shfl_xor_sync(0xffffffffu, lsum, 1);
            if ((tid & 1) == 0) sL[r] += lsum;
        }
        __syncthreads();

        // O += P @ V (128x64), 3 split passes
        #pragma unroll
        for (int ks = 0; ks < 4; ks++) {
            wmma::fragment<wmma::matrix_a, 16, 16, 16, __nv_bfloat16, wmma::row_major> aph[2], apl[2];
            wmma::fragment<wmma::matrix_b, 16, 16, 16, __nv_bfloat16, wmma::row_major> bvh[2], bvl[2];
            #pragma unroll
            for (int i = 0; i < 2; i++) {
                wmma::load_matrix_sync(aph[i], ph + (wr * 32 + i * 16) * FLDS + ks * 16, FLDS);
                wmma::load_matrix_sync(apl[i], pl + (wr * 32 + i * 16) * FLDS + ks * 16, FLDS);
            }
            #pragma unroll
            for (int j = 0; j < 2; j++) {
                wmma::load_matrix_sync(bvh[j], vh + (ks * 16) * FLDS + wc * 32 + j * 16, FLDS);
                wmma::load_matrix_sync(bvl[j], vl + (ks * 16) * FLDS + wc * 32 + j * 16, FLDS);
            }
            #pragma unroll
            for (int i = 0; i < 2; i++)
                #pragma unroll
                for (int j = 0; j < 2; j++) {
                    wmma::mma_sync(oacc[i][j], aph[i], bvh[j], oacc[i][j]);
                    wmma::mma_sync(oacc[i][j], apl[i], bvh[j], oacc[i][j]);
                    wmma::mma_sync(oacc[i][j], aph[i], bvl[j], oacc[i][j]);
                }
        }
        __syncthreads();
    }

    // epilogue: O / l -> gmem [b, s, h*64+d]
    #pragma unroll
    for (int i = 0; i < 2; i++)
        #pragma unroll
        for (int j = 0; j < 2; j++)
            wmma::store_matrix_sync(sS + (wr * 32 + i * 16) * FLDF + wc * 32 + j * 16,
                                    oacc[i][j], FLDF, wmma::mem_row_major);
    __syncthreads();

    {
        const int r = tid >> 1;
        const int c0 = (tid & 1) * 32;
        const float inv = 1.f / sL[r];
        const int qrow = qt * 128 + r;
        const int b = bh >> 4, h = bh & 15;
        float* op = O + ((size_t)(b * S_ + qrow)) * D_ + h * DH_ + c0;
        const float* pr = sS + r * FLDF + c0;
        #pragma unroll
        for (int i = 0; i < 8; i++) {
            float4 v = ((const float4*)pr)[i];
            v.x *= inv; v.y *= inv; v.z *= inv; v.w *= inv;
            ((float4*)op)[i] = v;
        }
    }
}

// ---------------- QKV transform: l2norm + scale + xpos rotary ---------------
__global__ __launch_bounds__(256) void transform_kernel(
    const float* __restrict__ qkv,
    const float* __restrict__ q_scale, const float* __restrict__ k_scale,
    float* __restrict__ Qo, float* __restrict__ Ko, float* __restrict__ Vo)
{
    const int gw   = (blockIdx.x * blockDim.x + threadIdx.x) >> 5;
    const int lane = threadIdx.x & 31;
    const int s  = gw & (S_ - 1);
    const int bh = gw >> 11;
    if (bh >= BH_) return;
    const int b = bh >> 4, h = bh & 15;

    const float* base = qkv + ((size_t)(b * S_ + s)) * (3 * D_) + h * (3 * DH_);
    float q0 = base[lane],       q1 = base[lane + 32];
    float k0 = base[64 + lane],  k1 = base[96 + lane];
    float v0 = base[128 + lane], v1 = base[160 + lane];

    float nq = q0 * q0 + q1 * q1;
    float nk = k0 * k0 + k1 * k1;
    #pragma unroll
    for (int off = 16; off; off >>= 1) {
        nq += __shfl_xor_sync(0xffffffffu, nq, off);
        nk += __shfl_xor_sync(0xffffffffu, nk, off);
    }
    nq = fmaxf(sqrtf(nq), 1e-12f);
    nk = fmaxf(sqrtf(nk), 1e-12f);

    q0 = q0 / nq * q_scale[lane]; q1 = q1 / nq * q_scale[lane + 32];
    k0 = k0 / nk * k_scale[lane]; k1 = k1 / nk * k_scale[lane + 32];

    const float d2 = 2.0f * (float)lane;
    const float inv_freq = exp2f(-d2 * (13.287712379549449f / 64.0f));
    const float fr = (float)s * inv_freq;
    float sn, c;
    sincosf(fr, &sn, &c);

    const float basev = (d2 + 0.4f * 64.0f) / (1.4f * 64.0f);
    const float power = ((float)s - (float)(S_ / 2)) / 512.0f;
    const float scale = exp2f(power * log2f(basev));
    const float iscale = 1.0f / scale;

    const float qo0 = (q0 * c - q1 * sn) * scale;
    const float qo1 = (q1 * c + q0 * sn) * scale;
    const float ko0 = (k0 * c - k1 * sn) * iscale;
    const float ko1 = (k1 * c + k0 * sn) * iscale;

    const size_t ob = ((size_t)bh * S_ + s) * DH_;
    Qo[ob + lane]      = qo0 * 0.125f;
    Qo[ob + lane + 32] = qo1 * 0.125f;
    Ko[ob + lane]      = ko0;
    Ko[ob + lane + 32] = ko1;
    Vo[ob + lane]      = v0;
    Vo[ob + lane + 32] = v1;
}

// ---------------- LayerNorm --------------------------------------------------
__global__ __launch_bounds__(256) void ln_kernel(
    const float* __restrict__ X, const float* __restrict__ g,
    const float* __restrict__ bb, float* __restrict__ Y)
{
    __shared__ float red[16];
    const int row = blockIdx.x;
    const int tid = threadIdx.x;
    const float* xp = X + (size_t)row * D_;

    float4 x4 = ((const float4*)xp)[tid];
    float s  = x4.x + x4.y + x4.z + x4.w;
    float ss = x4.x * x4.x + x4.y * x4.y + x4.z * x4.z + x4.w * x4.w;

    #pragma unroll
    for (int off = 16; off; off >>= 1) {
        s  += __shfl_xor_sync(0xffffffffu, s,  off);
        ss += __shfl_xor_sync(0xffffffffu, ss, off);
    }
    const int wid = tid >> 5, lane = tid & 31;
    if (lane == 0) { red[wid] = s; red[wid + 8] = ss; }
    __syncthreads();
    if (wid == 0) {
        float a = (lane < 8) ? red[lane] : 0.f;
        float bsum = (lane < 8) ? red[lane + 8] : 0.f;
        #pragma unroll
        for (int off = 4; off; off >>= 1) {
            a    += __shfl_xor_sync(0xffffffffu, a,    off);
            bsum += __shfl_xor_sync(0xffffffffu, bsum, off);
        }
        if (lane == 0) { red[0] = a; red[1] = bsum; }
    }
    __syncthreads();
    const float mu  = red[0] * (1.0f / D_);
    const float var = red[1] * (1.0f / D_) - mu * mu;
    const float rstd = rsqrtf(var + 1e-5f);

    float4 g4 = ((const float4*)g)[tid];
    float4 b4 = ((const float4*)bb)[tid];
    float4 y;
    y.x = (x4.x - mu) * rstd * g4.x + b4.x;
    y.y = (x4.y - mu) * rstd * g4.y + b4.y;
    y.z = (x4.z - mu) * rstd * g4.z + b4.z;
    y.w = (x4.w - mu) * rstd * g4.w + b4.w;
    ((float4*)(Y + (size_t)row * D_))[tid] = y;
}

// ---------------- launch -----------------------------------------------------
extern "C" void kernel_launch(void* const* d_in, const int* in_sizes, int n_in,
                              void* d_out, int out_size)
{
    const float* Q     = (const float*)d_in[0];
    const float* Wqkv  = (const float*)d_in[3];
    const float* bqkv  = (const float*)d_in[4];
    const float* q_sc  = (const float*)d_in[5];
    const float* k_sc  = (const float*)d_in[6];
    const float* ln_g  = (const float*)d_in[7];
    const float* ln_b  = (const float*)d_in[8];
    const float* W1    = (const float*)d_in[9];
    const float* b1    = (const float*)d_in[10];
    const float* W2    = (const float*)d_in[11];
    const float* b2    = (const float*)d_in[12];
    float* out = (float*)d_out;

    float *qkv, *qb, *kb, *vb, *att, *x, *h;
    cudaGetSymbolAddress((void**)&qkv, g_qkv);
    cudaGetSymbolAddress((void**)&qb,  g_q);
    cudaGetSymbolAddress((void**)&kb,  g_k);
    cudaGetSymbolAddress((void**)&vb,  g_v);
    cudaGetSymbolAddress((void**)&att, g_att);
    cudaGetSymbolAddress((void**)&x,   g_x);
    cudaGetSymbolAddress((void**)&h,   g_h);

    cudaFuncSetAttribute(fattn_kernel,
                         cudaFuncAttributeMaxDynamicSharedMemorySize, ATTN_SMEM);

    // 1) QKV projection: [8192,1024] @ [1024,3072]
    wmma_gemm<0><<<dim3(3 * D_ / 128, BS_ / 128), 256>>>(
        Q, Wqkv, bqkv, nullptr, qkv, BS_, 3 * D_, D_);

    // 2) l2norm + scale + rotary
    transform_kernel<<<BH_ * S_ / 8, 256>>>(qkv, q_sc, k_sc, qb, kb, vb);

    // 3) flash attention (split-bf16 tensor cores)
    fattn_kernel<<<dim3(S_ / 128, BH_), 256, ATTN_SMEM>>>(qb, kb, vb, att);

    // 4) LayerNorm
    ln_kernel<<<BS_, 256>>>(att, ln_g, ln_b, x);

    // 5) FF1 + SiLU
    wmma_gemm<1><<<dim3(FF_ / 128, BS_ / 128), 256>>>(
        x, W1, b1, nullptr, h, BS_, FF_, D_);

    // 6) FF2 + residual
    wmma_gemm<2><<<dim3(D_ / 128, BS_ / 128), 256>>>(
        h, W2, b2, x, out, BS_, D_, FF_);
}

// round 9
// speedup vs baseline: 2.2730x; 1.1717x over previous
#include <cuda_runtime.h>
#include <cuda_bf16.h>
#include <mma.h>
#include <math.h>
#include <stdint.h>

using namespace nvcuda;

#define B_   4
#define S_   2048
#define H_   16
#define DH_  64
#define D_   1024
#define FF_  2048
#define BS_  (B_*S_)
#define BH_  (B_*H_)

// ---------------- scratch (device globals; no runtime allocation) -----------
__device__ float g_qkv[(size_t)BS_ * 3 * D_];
__device__ __nv_bfloat16 g_qh[(size_t)BH_ * S_ * DH_];
__device__ __nv_bfloat16 g_ql[(size_t)BH_ * S_ * DH_];
__device__ __nv_bfloat16 g_kh[(size_t)BH_ * S_ * DH_];
__device__ __nv_bfloat16 g_kl[(size_t)BH_ * S_ * DH_];
__device__ __nv_bfloat16 g_vh[(size_t)BH_ * S_ * DH_];
__device__ __nv_bfloat16 g_vl[(size_t)BH_ * S_ * DH_];
__device__ float g_att[(size_t)BS_ * D_];
__device__ float g_x  [(size_t)BS_ * D_];
__device__ float g_h  [(size_t)BS_ * FF_];

// ---------------- split-bf16 helpers ----------------------------------------
__device__ __forceinline__ float bfres(float a) {
    return a - __bfloat162float(__float2bfloat16_rn(a));
}
__device__ __forceinline__ unsigned packbf(float a, float b) {
    __nv_bfloat162 t;
    t.x = __float2bfloat16_rn(a);
    t.y = __float2bfloat16_rn(b);
    return *reinterpret_cast<unsigned*>(&t);
}

// ---------------- PTX primitives ---------------------------------------------
__device__ __forceinline__ void ldsm4(unsigned* d, unsigned a) {
    asm volatile("ldmatrix.sync.aligned.m8n8.x4.shared.b16 {%0,%1,%2,%3}, [%4];"
                 : "=r"(d[0]), "=r"(d[1]), "=r"(d[2]), "=r"(d[3]) : "r"(a));
}
__device__ __forceinline__ void ldsm4t(unsigned* d, unsigned a) {
    asm volatile("ldmatrix.sync.aligned.m8n8.x4.trans.shared.b16 {%0,%1,%2,%3}, [%4];"
                 : "=r"(d[0]), "=r"(d[1]), "=r"(d[2]), "=r"(d[3]) : "r"(a));
}
__device__ __forceinline__ void mma_bf16(float* c, const unsigned* a,
                                         unsigned b0, unsigned b1) {
    asm volatile(
        "mma.sync.aligned.m16n8k16.row.col.f32.bf16.bf16.f32 "
        "{%0,%1,%2,%3}, {%4,%5,%6,%7}, {%8,%9}, {%0,%1,%2,%3};"
        : "+f"(c[0]), "+f"(c[1]), "+f"(c[2]), "+f"(c[3])
        : "r"(a[0]), "r"(a[1]), "r"(a[2]), "r"(a[3]), "r"(b0), "r"(b1));
}
__device__ __forceinline__ void cpa16(unsigned dst, const void* src) {
    asm volatile("cp.async.ca.shared.global [%0], [%1], 16;" :: "r"(dst), "l"(src));
}
__device__ __forceinline__ void cpa_commit() {
    asm volatile("cp.async.commit_group;");
}
__device__ __forceinline__ void cpa_wait0() {
    asm volatile("cp.async.wait_group 0;" ::: "memory");
}

// ============================================================================
// WMMA split-bf16 GEMM (measured fast in R4): C = act(A@B+bias)(+res)
// ============================================================================
#define LDA_ 40
#define LDB_ 136

template <int MODE>
__global__ __launch_bounds__(256, 2) void wmma_gemm(
    const float* __restrict__ A, const float* __restrict__ Bm,
    const float* __restrict__ bias, const float* __restrict__ res,
    float* __restrict__ C, int M, int N, int K)
{
    __shared__ __align__(16) unsigned char smem[38912];
    __nv_bfloat16* Ah = (__nv_bfloat16*)(smem);
    __nv_bfloat16* Al = (__nv_bfloat16*)(smem + 10240);
    __nv_bfloat16* Bh = (__nv_bfloat16*)(smem + 20480);
    __nv_bfloat16* Bl = (__nv_bfloat16*)(smem + 29184);
    float* fbuf = (float*)(smem);

    const int tid = threadIdx.x;
    const int wid = tid >> 5;
    const int wm  = wid & 3;
    const int wn  = wid >> 2;
    const int bx  = blockIdx.x, by = blockIdx.y;

    wmma::fragment<wmma::accumulator, 16, 16, 16, float> acc[2][4];
    #pragma unroll
    for (int i = 0; i < 2; i++)
        #pragma unroll
        for (int j = 0; j < 4; j++)
            wmma::fill_fragment(acc[i][j], 0.0f);

    const int ar = tid >> 1;
    const int af = (tid & 1) * 4;
    const int br = tid >> 3;
    const int bf = (tid & 7) * 4;

    const float* Ag = A + (size_t)(by * 128 + ar) * K;
    const float* Bg = Bm + (size_t)br * N + (size_t)bx * 128;

    float4 pa[4];
    float4 pb[4];
    #pragma unroll
    for (int j = 0; j < 4; j++) {
        pa[j] = *(const float4*)(Ag + (af + j) * 4);
        pb[j] = *(const float4*)(Bg + (bf + j) * 4);
    }

    for (int k0 = 0; k0 < K; k0 += 32) {
        #pragma unroll
        for (int j = 0; j < 4; j++) {
            const int ca = (af + j) * 4;
            float4 v = pa[j];
            *(unsigned*)(Ah + ar * LDA_ + ca)     = packbf(v.x, v.y);
            *(unsigned*)(Ah + ar * LDA_ + ca + 2) = packbf(v.z, v.w);
            *(unsigned*)(Al + ar * LDA_ + ca)     = packbf(bfres(v.x), bfres(v.y));
            *(unsigned*)(Al + ar * LDA_ + ca + 2) = packbf(bfres(v.z), bfres(v.w));
            const int cb = (bf + j) * 4;
            float4 w = pb[j];
            *(unsigned*)(Bh + br * LDB_ + cb)     = packbf(w.x, w.y);
            *(unsigned*)(Bh + br * LDB_ + cb + 2) = packbf(w.z, w.w);
            *(unsigned*)(Bl + br * LDB_ + cb)     = packbf(bfres(w.x), bfres(w.y));
            *(unsigned*)(Bl + br * LDB_ + cb + 2) = packbf(bfres(w.z), bfres(w.w));
        }
        __syncthreads();

        if (k0 + 32 < K) {
            #pragma unroll
            for (int j = 0; j < 4; j++) {
                pa[j] = *(const float4*)(Ag + k0 + 32 + (af + j) * 4);
                pb[j] = *(const float4*)(Bg + (size_t)(k0 + 32) * N + (bf + j) * 4);
            }
        }

        #pragma unroll
        for (int ks = 0; ks < 32; ks += 16) {
            wmma::fragment<wmma::matrix_a, 16, 16, 16, __nv_bfloat16, wmma::row_major> fah[2];
            wmma::fragment<wmma::matrix_a, 16, 16, 16, __nv_bfloat16, wmma::row_major> fal[2];
            wmma::fragment<wmma::matrix_b, 16, 16, 16, __nv_bfloat16, wmma::row_major> fbh[4];
            wmma::fragment<wmma::matrix_b, 16, 16, 16, __nv_bfloat16, wmma::row_major> fbl[4];
            #pragma unroll
            for (int i = 0; i < 2; i++) {
                wmma::load_matrix_sync(fah[i], Ah + (wm * 32 + i * 16) * LDA_ + ks, LDA_);
                wmma::load_matrix_sync(fal[i], Al + (wm * 32 + i * 16) * LDA_ + ks, LDA_);
            }
            #pragma unroll
            for (int j = 0; j < 4; j++) {
                wmma::load_matrix_sync(fbh[j], Bh + ks * LDB_ + wn * 64 + j * 16, LDB_);
                wmma::load_matrix_sync(fbl[j], Bl + ks * LDB_ + wn * 64 + j * 16, LDB_);
            }
            #pragma unroll
            for (int i = 0; i < 2; i++) {
                #pragma unroll
                for (int j = 0; j < 4; j++) {
                    wmma::mma_sync(acc[i][j], fah[i], fbh[j], acc[i][j]);
                    wmma::mma_sync(acc[i][j], fah[i], fbl[j], acc[i][j]);
                    wmma::mma_sync(acc[i][j], fal[i], fbh[j], acc[i][j]);
                }
            }
        }
        __syncthreads();
    }

    #pragma unroll
    for (int p = 0; p < 2; p++) {
        __syncthreads();
        if (wn == p) {
            #pragma unroll
            for (int i = 0; i < 2; i++)
                #pragma unroll
                for (int j = 0; j < 4; j++)
                    wmma::store_matrix_sync(fbuf + (wm * 32 + i * 16) * 68 + j * 16,
                                            acc[i][j], 68, wmma::mem_row_major);
        }
        __syncthreads();

        const int ncol0 = bx * 128 + p * 64;
        #pragma unroll
        for (int it = 0; it < 8; it++) {
            const int idx = tid + it * 256;
            const int r = idx >> 4;
            const int c = (idx & 15) * 4;
            float4 v = *(const float4*)(fbuf + r * 68 + c);
            float4 b4 = *(const float4*)(bias + ncol0 + c);
            v.x += b4.x; v.y += b4.y; v.z += b4.z; v.w += b4.w;
            if (MODE == 1) {
                v.x = v.x / (1.f + __expf(-v.x));
                v.y = v.y / (1.f + __expf(-v.y));
                v.z = v.z / (1.f + __expf(-v.z));
                v.w = v.w / (1.f + __expf(-v.w));
            }
            const size_t grow = (size_t)(by * 128 + r);
            if (MODE == 2) {
                float4 r4 = *(const float4*)(res + grow * N + ncol0 + c);
                v.x += r4.x; v.y += r4.y; v.z += r4.z; v.w += r4.w;
            }
            *(float4*)(C + grow * N + ncol0 + c) = v;
        }
    }
}

// ============================================================================
// Flash attention, register softmax (FA2 style), raw mma.m16n8k16 bf16 split.
// CTA: 128 q-rows x head, 8 warps x 16 rows. Key tile 32, cp.async dbl-buffer.
// SMEM (bytes): KV buf0 0..18432 (Kh,Kl,Vh,Vl planes of 4608), buf1 ..36864,
//               Qh 36864..55296, Ql 55296..73728
// ============================================================================
#define ALD 144            // bytes per SMEM row (72 bf16)
#define APLANE 4608        // 32*144
#define AKVBUF 18432
#define AQH 36864
#define AQL 55296
#define ATTN_SMEM 73728

__global__ __launch_bounds__(256, 2) void fattn_kernel(
    const __nv_bfloat16* __restrict__ Qh, const __nv_bfloat16* __restrict__ Ql,
    const __nv_bfloat16* __restrict__ Kh, const __nv_bfloat16* __restrict__ Kl,
    const __nv_bfloat16* __restrict__ Vh, const __nv_bfloat16* __restrict__ Vl,
    float* __restrict__ O)
{
    extern __shared__ unsigned char smc[];
    const unsigned sbase = (unsigned)__cvta_generic_to_shared(smc);

    const int tid = threadIdx.x;
    const int w   = tid >> 5;
    const int lane = tid & 31;
    const int bh = blockIdx.y;
    const int qt = blockIdx.x;

    const int lj = lane >> 3, lr = lane & 7;
    const int rowoff = (lj & 1) * 8 + lr;
    const int coloff = (lj >> 1) * 8;

    const size_t qbase  = ((size_t)bh * S_ + qt * 128) * DH_;
    const size_t kvbase = (size_t)bh * S_ * DH_;

    // issue Q (both planes) + KV tile 0
    #pragma unroll
    for (int i = 0; i < 8; i++) {
        int chunk = i * 256 + tid;            // 0..2047
        int plane = chunk >> 10;
        int rem = chunk & 1023;
        int row = rem >> 3;
        int c8 = (rem & 7) * 8;
        const __nv_bfloat16* src = (plane ? Ql : Qh) + qbase + (size_t)row * DH_ + c8;
        cpa16(sbase + (plane ? AQL : AQH) + row * ALD + c8 * 2, src);
    }
    #pragma unroll
    for (int i = 0; i < 4; i++) {
        int chunk = i * 256 + tid;            // 0..1023
        int plane = chunk >> 8;
        int rem = chunk & 255;
        int row = rem >> 3;
        int c8 = (rem & 7) * 8;
        const __nv_bfloat16* srcb =
            (plane == 0 ? Kh : plane == 1 ? Kl : plane == 2 ? Vh : Vl)
            + kvbase + (size_t)row * DH_ + c8;
        cpa16(sbase + plane * APLANE + row * ALD + c8 * 2, srcb);
    }
    cpa_commit();

    unsigned qfh[4][4], qfl[4][4];
    float oacc[8][4];
    #pragma unroll
    for (int t = 0; t < 8; t++) {
        oacc[t][0] = 0.f; oacc[t][1] = 0.f; oacc[t][2] = 0.f; oacc[t][3] = 0.f;
    }
    float lsum0 = 0.f, lsum1 = 0.f;

    const int NT = S_ / 32;
    for (int kt = 0; kt < NT; kt++) {
        cpa_wait0();
        __syncthreads();

        if (kt == 0) {
            #pragma unroll
            for (int ks = 0; ks < 4; ks++) {
                unsigned qoff = (unsigned)((w * 16 + rowoff) * ALD + (ks * 16 + coloff) * 2);
                ldsm4(qfh[ks], sbase + AQH + qoff);
                ldsm4(qfl[ks], sbase + AQL + qoff);
            }
        }

        const unsigned buf = sbase + (kt & 1) * AKVBUF;

        if (kt + 1 < NT) {
            const size_t tb = kvbase + (size_t)(kt + 1) * 32 * DH_;
            const unsigned dbuf = sbase + ((kt + 1) & 1) * AKVBUF;
            #pragma unroll
            for (int i = 0; i < 4; i++) {
                int chunk = i * 256 + tid;
                int plane = chunk >> 8;
                int rem = chunk & 255;
                int row = rem >> 3;
                int c8 = (rem & 7) * 8;
                const __nv_bfloat16* srcb =
                    (plane == 0 ? Kh : plane == 1 ? Kl : plane == 2 ? Vh : Vl)
                    + tb + (size_t)row * DH_ + c8;
                cpa16(dbuf + plane * APLANE + row * ALD + c8 * 2, srcb);
            }
            cpa_commit();
        }

        // ---- S = Q @ K^T (16 x 32 per warp) ----
        float sacc[4][4];
        #pragma unroll
        for (int nt = 0; nt < 4; nt++) {
            sacc[nt][0] = 0.f; sacc[nt][1] = 0.f; sacc[nt][2] = 0.f; sacc[nt][3] = 0.f;
        }
        #pragma unroll
        for (int ks = 0; ks < 4; ks++) {
            #pragma unroll
            for (int g2 = 0; g2 < 2; g2++) {
                unsigned kbh[4], kbl[4];
                unsigned off = buf + (unsigned)((g2 * 16 + rowoff) * ALD + (ks * 16 + coloff) * 2);
                ldsm4(kbh, off);                 // Kh plane
                ldsm4(kbl, off + APLANE);        // Kl plane
                mma_bf16(sacc[2 * g2],     qfh[ks], kbh[0], kbh[2]);
                mma_bf16(sacc[2 * g2],     qfh[ks], kbl[0], kbl[2]);
                mma_bf16(sacc[2 * g2],     qfl[ks], kbh[0], kbh[2]);
                mma_bf16(sacc[2 * g2 + 1], qfh[ks], kbh[1], kbh[3]);
                mma_bf16(sacc[2 * g2 + 1], qfh[ks], kbl[1], kbl[3]);
                mma_bf16(sacc[2 * g2 + 1], qfl[ks], kbh[1], kbh[3]);
            }
        }

        // ---- exp in registers (no max needed: |logit| bounded) ----
        #pragma unroll
        for (int nt = 0; nt < 4; nt++) {
            sacc[nt][0] = __expf(sacc[nt][0]); lsum0 += sacc[nt][0];
            sacc[nt][1] = __expf(sacc[nt][1]); lsum0 += sacc[nt][1];
            sacc[nt][2] = __expf(sacc[nt][2]); lsum1 += sacc[nt][2];
            sacc[nt][3] = __expf(sacc[nt][3]); lsum1 += sacc[nt][3];
        }

        // ---- O += P @ V ----
        #pragma unroll
        for (int ks2 = 0; ks2 < 2; ks2++) {
            unsigned aph[4], apl[4];
            const float* t0 = sacc[2 * ks2];
            const float* t1 = sacc[2 * ks2 + 1];
            aph[0] = packbf(t0[0], t0[1]); apl[0] = packbf(bfres(t0[0]), bfres(t0[1]));
            aph[1] = packbf(t0[2], t0[3]); apl[1] = packbf(bfres(t0[2]), bfres(t0[3]));
            aph[2] = packbf(t1[0], t1[1]); apl[2] = packbf(bfres(t1[0]), bfres(t1[1]));
            aph[3] = packbf(t1[2], t1[3]); apl[3] = packbf(bfres(t1[2]), bfres(t1[3]));
            #pragma unroll
            for (int g = 0; g < 4; g++) {
                unsigned vbh[4], vbl[4];
                unsigned off = buf + 2 * APLANE
                             + (unsigned)((ks2 * 16 + rowoff) * ALD + (g * 16 + coloff) * 2);
                ldsm4t(vbh, off);                // Vh plane
                ldsm4t(vbl, off + APLANE);       // Vl plane
                mma_bf16(oacc[2 * g],     aph, vbh[0], vbh[1]);
                mma_bf16(oacc[2 * g],     apl, vbh[0], vbh[1]);
                mma_bf16(oacc[2 * g],     aph, vbl[0], vbl[1]);
                mma_bf16(oacc[2 * g + 1], aph, vbh[2], vbh[3]);
                mma_bf16(oacc[2 * g + 1], apl, vbh[2], vbh[3]);
                mma_bf16(oacc[2 * g + 1], aph, vbl[2], vbl[3]);
            }
        }
    }

    // quad-reduce row sums, normalize, write out
    lsum0 += __shfl_xor_sync(0xffffffffu, lsum0, 1);
    lsum0 += __shfl_xor_sync(0xffffffffu, lsum0, 2);
    lsum1 += __shfl_xor_sync(0xffffffffu, lsum1, 1);
    lsum1 += __shfl_xor_sync(0xffffffffu, lsum1, 2);
    const float inv0 = 1.f / lsum0;
    const float inv1 = 1.f / lsum1;

    const int b = bh >> 4, h = bh & 15;
    const int g = lane >> 2, c2 = (lane & 3) * 2;
    const int r0 = qt * 128 + w * 16 + g;
    float* o0 = O + ((size_t)(b * S_) + r0) * D_ + h * DH_;
    float* o1 = o0 + (size_t)8 * D_;
    #pragma unroll
    for (int t = 0; t < 8; t++) {
        *(float2*)(o0 + t * 8 + c2) = make_float2(oacc[t][0] * inv0, oacc[t][1] * inv0);
        *(float2*)(o1 + t * 8 + c2) = make_float2(oacc[t][2] * inv1, oacc[t][3] * inv1);
    }
}

// ---------------- QKV transform: l2norm + scale + xpos rotary ---------------
// Outputs split-bf16 hi/lo planes for Q,K,V (consumed by fattn via cp.async).
__global__ __launch_bounds__(256) void transform_kernel(
    const float* __restrict__ qkv,
    const float* __restrict__ q_scale, const float* __restrict__ k_scale,
    __nv_bfloat16* __restrict__ Qh, __nv_bfloat16* __restrict__ Ql,
    __nv_bfloat16* __restrict__ Kh, __nv_bfloat16* __restrict__ Kl,
    __nv_bfloat16* __restrict__ Vh, __nv_bfloat16* __restrict__ Vl)
{
    const int gw   = (blockIdx.x * blockDim.x + threadIdx.x) >> 5;
    const int lane = threadIdx.x & 31;
    const int s  = gw & (S_ - 1);
    const int bh = gw >> 11;
    if (bh >= BH_) return;
    const int b = bh >> 4, h = bh & 15;

    const float* base = qkv + ((size_t)(b * S_ + s)) * (3 * D_) + h * (3 * DH_);
    float q0 = base[lane],       q1 = base[lane + 32];
    float k0 = base[64 + lane],  k1 = base[96 + lane];
    float v0 = base[128 + lane], v1 = base[160 + lane];

    float nq = q0 * q0 + q1 * q1;
    float nk = k0 * k0 + k1 * k1;
    #pragma unroll
    for (int off = 16; off; off >>= 1) {
        nq += __shfl_xor_sync(0xffffffffu, nq, off);
        nk += __shfl_xor_sync(0xffffffffu, nk, off);
    }
    nq = fmaxf(sqrtf(nq), 1e-12f);
    nk = fmaxf(sqrtf(nk), 1e-12f);

    q0 = q0 / nq * q_scale[lane]; q1 = q1 / nq * q_scale[lane + 32];
    k0 = k0 / nk * k_scale[lane]; k1 = k1 / nk * k_scale[lane + 32];

    const float d2 = 2.0f * (float)lane;
    const float inv_freq = exp2f(-d2 * (13.287712379549449f / 64.0f));
    const float fr = (float)s * inv_freq;
    float sn, c;
    sincosf(fr, &sn, &c);

    const float basev = (d2 + 0.4f * 64.0f) / (1.4f * 64.0f);
    const float power = ((float)s - (float)(S_ / 2)) / 512.0f;
    const float scale = exp2f(power * log2f(basev));
    const float iscale = 1.0f / scale;

    const float qo0 = (q0 * c - q1 * sn) * scale * 0.125f;
    const float qo1 = (q1 * c + q0 * sn) * scale * 0.125f;
    const float ko0 = (k0 * c - k1 * sn) * iscale;
    const float ko1 = (k1 * c + k0 * sn) * iscale;

    const size_t ob = ((size_t)bh * S_ + s) * DH_;
    Qh[ob + lane]      = __float2bfloat16_rn(qo0);
    Ql[ob + lane]      = __float2bfloat16_rn(bfres(qo0));
    Qh[ob + lane + 32] = __float2bfloat16_rn(qo1);
    Ql[ob + lane + 32] = __float2bfloat16_rn(bfres(qo1));
    Kh[ob + lane]      = __float2bfloat16_rn(ko0);
    Kl[ob + lane]      = __float2bfloat16_rn(bfres(ko0));
    Kh[ob + lane + 32] = __float2bfloat16_rn(ko1);
    Kl[ob + lane + 32] = __float2bfloat16_rn(bfres(ko1));
    Vh[ob + lane]      = __float2bfloat16_rn(v0);
    Vl[ob + lane]      = __float2bfloat16_rn(bfres(v0));
    Vh[ob + lane + 32] = __float2bfloat16_rn(v1);
    Vl[ob + lane + 32] = __float2bfloat16_rn(bfres(v1));
}

// ---------------- LayerNorm --------------------------------------------------
__global__ __launch_bounds__(256) void ln_kernel(
    const float* __restrict__ X, const float* __restrict__ g,
    const float* __restrict__ bb, float* __restrict__ Y)
{
    __shared__ float red[16];
    const int row = blockIdx.x;
    const int tid = threadIdx.x;
    const float* xp = X + (size_t)row * D_;

    float4 x4 = ((const float4*)xp)[tid];
    float s  = x4.x + x4.y + x4.z + x4.w;
    float ss = x4.x * x4.x + x4.y * x4.y + x4.z * x4.z + x4.w * x4.w;

    #pragma unroll
    for (int off = 16; off; off >>= 1) {
        s  += __shfl_xor_sync(0xffffffffu, s,  off);
        ss += __shfl_xor_sync(0xffffffffu, ss, off);
    }
    const int wid = tid >> 5, lane = tid & 31;
    if (lane == 0) { red[wid] = s; red[wid + 8] = ss; }
    __syncthreads();
    if (wid == 0) {
        float a = (lane < 8) ? red[lane] : 0.f;
        float bsum = (lane < 8) ? red[lane + 8] : 0.f;
        #pragma unroll
        for (int off = 4; off; off >>= 1) {
            a    += __shfl_xor_sync(0xffffffffu, a,    off);
            bsum += __shfl_xor_sync(0xffffffffu, bsum, off);
        }
        if (lane == 0) { red[0] = a; red[1] = bsum; }
    }
    __syncthreads();
    const float mu  = red[0] * (1.0f / D_);
    const float var = red[1] * (1.0f / D_) - mu * mu;
    const float rstd = rsqrtf(var + 1e-5f);

    float4 g4 = ((const float4*)g)[tid];
    float4 b4 = ((const float4*)bb)[tid];
    float4 y;
    y.x = (x4.x - mu) * rstd * g4.x + b4.x;
    y.y = (x4.y - mu) * rstd * g4.y + b4.y;
    y.z = (x4.z - mu) * rstd * g4.z + b4.z;
    y.w = (x4.w - mu) * rstd * g4.w + b4.w;
    ((float4*)(Y + (size_t)row * D_))[tid] = y;
}

// ---------------- launch -----------------------------------------------------
extern "C" void kernel_launch(void* const* d_in, const int* in_sizes, int n_in,
                              void* d_out, int out_size)
{
    const float* Q     = (const float*)d_in[0];
    const float* Wqkv  = (const float*)d_in[3];
    const float* bqkv  = (const float*)d_in[4];
    const float* q_sc  = (const float*)d_in[5];
    const float* k_sc  = (const float*)d_in[6];
    const float* ln_g  = (const float*)d_in[7];
    const float* ln_b  = (const float*)d_in[8];
    const float* W1    = (const float*)d_in[9];
    const float* b1    = (const float*)d_in[10];
    const float* W2    = (const float*)d_in[11];
    const float* b2    = (const float*)d_in[12];
    float* out = (float*)d_out;

    float *qkv, *att, *x, *h;
    __nv_bfloat16 *qh, *ql, *kh, *kl, *vh, *vl;
    cudaGetSymbolAddress((void**)&qkv, g_qkv);
    cudaGetSymbolAddress((void**)&qh,  g_qh);
    cudaGetSymbolAddress((void**)&ql,  g_ql);
    cudaGetSymbolAddress((void**)&kh,  g_kh);
    cudaGetSymbolAddress((void**)&kl,  g_kl);
    cudaGetSymbolAddress((void**)&vh,  g_vh);
    cudaGetSymbolAddress((void**)&vl,  g_vl);
    cudaGetSymbolAddress((void**)&att, g_att);
    cudaGetSymbolAddress((void**)&x,   g_x);
    cudaGetSymbolAddress((void**)&h,   g_h);

    cudaFuncSetAttribute(fattn_kernel,
                         cudaFuncAttributeMaxDynamicSharedMemorySize, ATTN_SMEM);

    // 1) QKV projection
    wmma_gemm<0><<<dim3(3 * D_ / 128, BS_ / 128), 256>>>(
        Q, Wqkv, bqkv, nullptr, qkv, BS_, 3 * D_, D_);

    // 2) l2norm + scale + rotary -> split-bf16 planes
    transform_kernel<<<BH_ * S_ / 8, 256>>>(qkv, q_sc, k_sc,
                                            qh, ql, kh, kl, vh, vl);

    // 3) flash attention (register softmax, split-bf16 mma)
    fattn_kernel<<<dim3(S_ / 128, BH_), 256, ATTN_SMEM>>>(
        qh, ql, kh, kl, vh, vl, att);

    // 4) LayerNorm
    ln_kernel<<<BS_, 256>>>(att, ln_g, ln_b, x);

    // 5) FF1 + SiLU
    wmma_gemm<1><<<dim3(FF_ / 128, BS_ / 128), 256>>>(
        x, W1, b1, nullptr, h, BS_, FF_, D_);

    // 6) FF2 + residual
    wmma_gemm<2><<<dim3(D_ / 128, BS_ / 128), 256>>>(
        h, W2, b2, x, out, BS_, D_, FF_);
}

// round 10
// speedup vs baseline: 2.5291x; 1.1127x over previous
#include <cuda_runtime.h>
#include <cuda_bf16.h>
#include <math.h>
#include <stdint.h>

#define B_   4
#define S_   2048
#define H_   16
#define DH_  64
#define D_   1024
#define FF_  2048
#define BS_  (B_*S_)
#define BH_  (B_*H_)

// ---------------- scratch (device globals; no runtime allocation) -----------
__device__ float g_qkv[(size_t)BS_ * 3 * D_];
__device__ __nv_bfloat16 g_qh[(size_t)BH_ * S_ * DH_];
__device__ __nv_bfloat16 g_ql[(size_t)BH_ * S_ * DH_];
__device__ __nv_bfloat16 g_kh[(size_t)BH_ * S_ * DH_];
__device__ __nv_bfloat16 g_kl[(size_t)BH_ * S_ * DH_];
__device__ __nv_bfloat16 g_vh[(size_t)BH_ * S_ * DH_];
__device__ __nv_bfloat16 g_vl[(size_t)BH_ * S_ * DH_];
__device__ float g_att[(size_t)BS_ * D_];
__device__ float g_x  [(size_t)BS_ * D_];
__device__ float g_h  [(size_t)BS_ * FF_];

// ---------------- split-bf16 helpers ----------------------------------------
__device__ __forceinline__ float bfres(float a) {
    return a - __bfloat162float(__float2bfloat16_rn(a));
}
__device__ __forceinline__ unsigned packbf(float a, float b) {
    __nv_bfloat162 t;
    t.x = __float2bfloat16_rn(a);
    t.y = __float2bfloat16_rn(b);
    return *reinterpret_cast<unsigned*>(&t);
}

// ---------------- PTX primitives ---------------------------------------------
__device__ __forceinline__ void ldsm4(unsigned* d, unsigned a) {
    asm volatile("ldmatrix.sync.aligned.m8n8.x4.shared.b16 {%0,%1,%2,%3}, [%4];"
                 : "=r"(d[0]), "=r"(d[1]), "=r"(d[2]), "=r"(d[3]) : "r"(a));
}
__device__ __forceinline__ void ldsm4t(unsigned* d, unsigned a) {
    asm volatile("ldmatrix.sync.aligned.m8n8.x4.trans.shared.b16 {%0,%1,%2,%3}, [%4];"
                 : "=r"(d[0]), "=r"(d[1]), "=r"(d[2]), "=r"(d[3]) : "r"(a));
}
__device__ __forceinline__ void mma_bf16(float* c, const unsigned* a,
                                         unsigned b0, unsigned b1) {
    asm volatile(
        "mma.sync.aligned.m16n8k16.row.col.f32.bf16.bf16.f32 "
        "{%0,%1,%2,%3}, {%4,%5,%6,%7}, {%8,%9}, {%0,%1,%2,%3};"
        : "+f"(c[0]), "+f"(c[1]), "+f"(c[2]), "+f"(c[3])
        : "r"(a[0]), "r"(a[1]), "r"(a[2]), "r"(a[3]), "r"(b0), "r"(b1));
}
__device__ __forceinline__ void cpa16(unsigned dst, const void* src) {
    asm volatile("cp.async.ca.shared.global [%0], [%1], 16;" :: "r"(dst), "l"(src));
}
__device__ __forceinline__ void cpa_commit() {
    asm volatile("cp.async.commit_group;");
}
__device__ __forceinline__ void cpa_wait0() {
    asm volatile("cp.async.wait_group 0;" ::: "memory");
}

// ============================================================================
// Raw-mma split-bf16 GEMM: C = act(A@B + bias) (+ residual)
// CTA 128x128, 8 warps (2m x 4n), warp tile 32x64, k-chunk 32.
// A planes [128][40bf16] stride 80B (conflict-free ldsm), B planes [32][136bf16]
// stride 272B (conflict-free ldsm4t). Double-buffered, 1 sync per chunk.
// Epilogue: accumulator regs -> gmem directly. MODE 0 plain/1 SiLU/2 +res.
// ============================================================================
#define GA_ 80            // A plane row stride bytes
#define GB_ 272           // B plane row stride bytes
#define GBUF 37888        // bytes per buffer: Ah 10240 + Al 10240 + Bh 8704 + Bl 8704
#define GEMM_SMEM (2 * GBUF)

template <int MODE>
__global__ __launch_bounds__(256, 2) void mma_gemm(
    const float* __restrict__ A, const float* __restrict__ Bm,
    const float* __restrict__ bias, const float* __restrict__ res,
    float* __restrict__ C, int M, int N, int K)
{
    extern __shared__ unsigned char smg[];
    const unsigned sb = (unsigned)__cvta_generic_to_shared(smg);

    const int tid = threadIdx.x;
    const int w = tid >> 5;
    const int lane = tid & 31;
    const int wm = w & 1;        // m offset wm*64? no: 2 m-warps? -> wm in {0,1}: 64 rows each? 
    // NOTE: warp grid: 2 (m) x 4 (n): warp tile 64x32? We want 32x64.
    // Use: wm = w >> 2 (0..1) -> 64-row half? Define cleanly below.
    const int wmr = w & 3;       // 4 m-warps: rows wmr*32 .. +32
    const int wnc = w >> 2;      // 2 n-warps: cols wnc*64 .. +64
    const int bx = blockIdx.x, by = blockIdx.y;

    const int lj = lane >> 3, lr = lane & 7;
    const int rowoff = (lj & 1) * 8 + lr;
    const int coloff = (lj >> 1) * 8;
    const int g = lane >> 2, c2 = (lane & 3) * 2;

    float acc[2][8][4];
    #pragma unroll
    for (int mt = 0; mt < 2; mt++)
        #pragma unroll
        for (int n = 0; n < 8; n++) {
            acc[mt][n][0] = 0.f; acc[mt][n][1] = 0.f;
            acc[mt][n][2] = 0.f; acc[mt][n][3] = 0.f;
        }

    // staging indices
    const int ar = tid >> 1;           // A row 0..127
    const int ac = (tid & 1) * 16;     // A col base
    const int brr = tid >> 3;          // B row 0..31
    const int bc = (tid & 7) * 16;     // B col base

    const float* Ag = A + (size_t)(by * 128 + ar) * K + ac;
    const float* Bg = Bm + (size_t)brr * N + (size_t)bx * 128 + bc;

    float4 pa[4], pb[4];
    #pragma unroll
    for (int j = 0; j < 4; j++) {
        pa[j] = *(const float4*)(Ag + j * 4);
        pb[j] = *(const float4*)(Bg + j * 4);
    }

    const int NC = K >> 5;
    for (int kc = 0; kc < NC; kc++) {
        const unsigned base = sb + (unsigned)((kc & 1) * GBUF);
        const unsigned uAh = base, uAl = base + 10240u;
        const unsigned uBh = base + 20480u, uBl = base + 29184u;

        // store staged tile (hi/lo)
        #pragma unroll
        for (int j = 0; j < 4; j++) {
            const unsigned offa = (unsigned)(ar * GA_ + (ac + j * 4) * 2);
            float4 v = pa[j];
            uint2 hi, lo;
            hi.x = packbf(v.x, v.y); hi.y = packbf(v.z, v.w);
            lo.x = packbf(bfres(v.x), bfres(v.y));
            lo.y = packbf(bfres(v.z), bfres(v.w));
            *(uint2*)(smg + (offa + (kc & 1) * GBUF))          = hi;
            *(uint2*)(smg + (offa + (kc & 1) * GBUF) + 10240)  = lo;
            const unsigned offb = (unsigned)(brr * GB_ + (bc + j * 4) * 2);
            float4 u = pb[j];
            uint2 bhi, blo;
            bhi.x = packbf(u.x, u.y); bhi.y = packbf(u.z, u.w);
            blo.x = packbf(bfres(u.x), bfres(u.y));
            blo.y = packbf(bfres(u.z), bfres(u.w));
            *(uint2*)(smg + (offb + (kc & 1) * GBUF) + 20480)  = bhi;
            *(uint2*)(smg + (offb + (kc & 1) * GBUF) + 29184)  = blo;
        }
        __syncthreads();

        // prefetch next chunk
        if (kc + 1 < NC) {
            const int k0 = (kc + 1) * 32;
            #pragma unroll
            for (int j = 0; j < 4; j++) {
                pa[j] = *(const float4*)(Ag + k0 + j * 4);
                pb[j] = *(const float4*)(Bg + (size_t)k0 * N + j * 4);
            }
        }

        // compute: 2 k16 steps
        #pragma unroll
        for (int ks = 0; ks < 2; ks++) {
            unsigned ah[2][4], al[2][4];
            #pragma unroll
            for (int mt = 0; mt < 2; mt++) {
                const unsigned addr = uAh
                    + (unsigned)((wmr * 32 + mt * 16 + rowoff) * GA_ + (ks * 16 + coloff) * 2);
                ldsm4(ah[mt], addr);
                ldsm4(al[mt], addr + 10240u);
            }
            #pragma unroll
            for (int gg = 0; gg < 4; gg++) {
                unsigned bhf[4], blf[4];
                const unsigned baddr = uBh
                    + (unsigned)((ks * 16 + rowoff) * GB_ + (wnc * 64 + gg * 16 + coloff) * 2);
                ldsm4t(bhf, baddr);
                ldsm4t(blf, baddr + 8704u);
                #pragma unroll
                for (int mt = 0; mt < 2; mt++) {
                    mma_bf16(acc[mt][2 * gg],     ah[mt], bhf[0], bhf[1]);
                    mma_bf16(acc[mt][2 * gg],     ah[mt], blf[0], blf[1]);
                    mma_bf16(acc[mt][2 * gg],     al[mt], bhf[0], bhf[1]);
                    mma_bf16(acc[mt][2 * gg + 1], ah[mt], bhf[2], bhf[3]);
                    mma_bf16(acc[mt][2 * gg + 1], ah[mt], blf[2], blf[3]);
                    mma_bf16(acc[mt][2 * gg + 1], al[mt], bhf[2], bhf[3]);
                }
            }
        }
    }

    // epilogue: regs -> gmem directly
    #pragma unroll
    for (int mt = 0; mt < 2; mt++) {
        #pragma unroll
        for (int n = 0; n < 8; n++) {
            const int row = by * 128 + wmr * 32 + mt * 16 + g;
            const int col = bx * 128 + wnc * 64 + n * 8 + c2;
            float2 bb2 = *(const float2*)(bias + col);
            float v0 = acc[mt][n][0] + bb2.x;
            float v1 = acc[mt][n][1] + bb2.y;
            float v2 = acc[mt][n][2] + bb2.x;
            float v3 = acc[mt][n][3] + bb2.y;
            if (MODE == 1) {
                v0 = v0 / (1.f + __expf(-v0));
                v1 = v1 / (1.f + __expf(-v1));
                v2 = v2 / (1.f + __expf(-v2));
                v3 = v3 / (1.f + __expf(-v3));
            }
            if (MODE == 2) {
                float2 r0 = *(const float2*)(res + (size_t)row * N + col);
                float2 r1 = *(const float2*)(res + (size_t)(row + 8) * N + col);
                v0 += r0.x; v1 += r0.y; v2 += r1.x; v3 += r1.y;
            }
            *(float2*)(C + (size_t)row * N + col)       = make_float2(v0, v1);
            *(float2*)(C + (size_t)(row + 8) * N + col) = make_float2(v2, v3);
        }
    }
}

// ============================================================================
// Flash attention, register softmax, raw mma split-bf16 (validated in R9).
// ============================================================================
#define ALD 144
#define APLANE 4608
#define AKVBUF 18432
#define AQH 36864
#define AQL 55296
#define ATTN_SMEM 73728

__global__ __launch_bounds__(256, 2) void fattn_kernel(
    const __nv_bfloat16* __restrict__ Qh, const __nv_bfloat16* __restrict__ Ql,
    const __nv_bfloat16* __restrict__ Kh, const __nv_bfloat16* __restrict__ Kl,
    const __nv_bfloat16* __restrict__ Vh, const __nv_bfloat16* __restrict__ Vl,
    float* __restrict__ O)
{
    extern __shared__ unsigned char smc[];
    const unsigned sbase = (unsigned)__cvta_generic_to_shared(smc);

    const int tid = threadIdx.x;
    const int w   = tid >> 5;
    const int lane = tid & 31;
    const int bh = blockIdx.y;
    const int qt = blockIdx.x;

    const int lj = lane >> 3, lr = lane & 7;
    const int rowoff = (lj & 1) * 8 + lr;
    const int coloff = (lj >> 1) * 8;

    const size_t qbase  = ((size_t)bh * S_ + qt * 128) * DH_;
    const size_t kvbase = (size_t)bh * S_ * DH_;

    #pragma unroll
    for (int i = 0; i < 8; i++) {
        int chunk = i * 256 + tid;
        int plane = chunk >> 10;
        int rem = chunk & 1023;
        int row = rem >> 3;
        int c8 = (rem & 7) * 8;
        const __nv_bfloat16* src = (plane ? Ql : Qh) + qbase + (size_t)row * DH_ + c8;
        cpa16(sbase + (plane ? AQL : AQH) + row * ALD + c8 * 2, src);
    }
    #pragma unroll
    for (int i = 0; i < 4; i++) {
        int chunk = i * 256 + tid;
        int plane = chunk >> 8;
        int rem = chunk & 255;
        int row = rem >> 3;
        int c8 = (rem & 7) * 8;
        const __nv_bfloat16* srcb =
            (plane == 0 ? Kh : plane == 1 ? Kl : plane == 2 ? Vh : Vl)
            + kvbase + (size_t)row * DH_ + c8;
        cpa16(sbase + plane * APLANE + row * ALD + c8 * 2, srcb);
    }
    cpa_commit();

    unsigned qfh[4][4], qfl[4][4];
    float oacc[8][4];
    #pragma unroll
    for (int t = 0; t < 8; t++) {
        oacc[t][0] = 0.f; oacc[t][1] = 0.f; oacc[t][2] = 0.f; oacc[t][3] = 0.f;
    }
    float lsum0 = 0.f, lsum1 = 0.f;

    const int NT = S_ / 32;
    for (int kt = 0; kt < NT; kt++) {
        cpa_wait0();
        __syncthreads();

        if (kt == 0) {
            #pragma unroll
            for (int ks = 0; ks < 4; ks++) {
                unsigned qoff = (unsigned)((w * 16 + rowoff) * ALD + (ks * 16 + coloff) * 2);
                ldsm4(qfh[ks], sbase + AQH + qoff);
                ldsm4(qfl[ks], sbase + AQL + qoff);
            }
        }

        const unsigned buf = sbase + (kt & 1) * AKVBUF;

        if (kt + 1 < NT) {
            const size_t tb = kvbase + (size_t)(kt + 1) * 32 * DH_;
            const unsigned dbuf = sbase + ((kt + 1) & 1) * AKVBUF;
            #pragma unroll
            for (int i = 0; i < 4; i++) {
                int chunk = i * 256 + tid;
                int plane = chunk >> 8;
                int rem = chunk & 255;
                int row = rem >> 3;
                int c8 = (rem & 7) * 8;
                const __nv_bfloat16* srcb =
                    (plane == 0 ? Kh : plane == 1 ? Kl : plane == 2 ? Vh : Vl)
                    + tb + (size_t)row * DH_ + c8;
                cpa16(dbuf + plane * APLANE + row * ALD + c8 * 2, srcb);
            }
            cpa_commit();
        }

        float sacc[4][4];
        #pragma unroll
        for (int nt = 0; nt < 4; nt++) {
            sacc[nt][0] = 0.f; sacc[nt][1] = 0.f; sacc[nt][2] = 0.f; sacc[nt][3] = 0.f;
        }
        #pragma unroll
        for (int ks = 0; ks < 4; ks++) {
            #pragma unroll
            for (int g2 = 0; g2 < 2; g2++) {
                unsigned kbh[4], kbl[4];
                unsigned off = buf + (unsigned)((g2 * 16 + rowoff) * ALD + (ks * 16 + coloff) * 2);
                ldsm4(kbh, off);
                ldsm4(kbl, off + APLANE);
                mma_bf16(sacc[2 * g2],     qfh[ks], kbh[0], kbh[2]);
                mma_bf16(sacc[2 * g2],     qfh[ks], kbl[0], kbl[2]);
                mma_bf16(sacc[2 * g2],     qfl[ks], kbh[0], kbh[2]);
                mma_bf16(sacc[2 * g2 + 1], qfh[ks], kbh[1], kbh[3]);
                mma_bf16(sacc[2 * g2 + 1], qfh[ks], kbl[1], kbl[3]);
                mma_bf16(sacc[2 * g2 + 1], qfl[ks], kbh[1], kbh[3]);
            }
        }

        #pragma unroll
        for (int nt = 0; nt < 4; nt++) {
            sacc[nt][0] = __expf(sacc[nt][0]); lsum0 += sacc[nt][0];
            sacc[nt][1] = __expf(sacc[nt][1]); lsum0 += sacc[nt][1];
            sacc[nt][2] = __expf(sacc[nt][2]); lsum1 += sacc[nt][2];
            sacc[nt][3] = __expf(sacc[nt][3]); lsum1 += sacc[nt][3];
        }

        #pragma unroll
        for (int ks2 = 0; ks2 < 2; ks2++) {
            unsigned aph[4], apl[4];
            const float* t0 = sacc[2 * ks2];
            const float* t1 = sacc[2 * ks2 + 1];
            aph[0] = packbf(t0[0], t0[1]); apl[0] = packbf(bfres(t0[0]), bfres(t0[1]));
            aph[1] = packbf(t0[2], t0[3]); apl[1] = packbf(bfres(t0[2]), bfres(t0[3]));
            aph[2] = packbf(t1[0], t1[1]); apl[2] = packbf(bfres(t1[0]), bfres(t1[1]));
            aph[3] = packbf(t1[2], t1[3]); apl[3] = packbf(bfres(t1[2]), bfres(t1[3]));
            #pragma unroll
            for (int gv = 0; gv < 4; gv++) {
                unsigned vbh[4], vbl[4];
                unsigned off = buf + 2 * APLANE
                             + (unsigned)((ks2 * 16 + rowoff) * ALD + (gv * 16 + coloff) * 2);
                ldsm4t(vbh, off);
                ldsm4t(vbl, off + APLANE);
                mma_bf16(oacc[2 * gv],     aph, vbh[0], vbh[1]);
                mma_bf16(oacc[2 * gv],     apl, vbh[0], vbh[1]);
                mma_bf16(oacc[2 * gv],     aph, vbl[0], vbl[1]);
                mma_bf16(oacc[2 * gv + 1], aph, vbh[2], vbh[3]);
                mma_bf16(oacc[2 * gv + 1], apl, vbh[2], vbh[3]);
                mma_bf16(oacc[2 * gv + 1], aph, vbl[2], vbl[3]);
            }
        }
    }

    lsum0 += __shfl_xor_sync(0xffffffffu, lsum0, 1);
    lsum0 += __shfl_xor_sync(0xffffffffu, lsum0, 2);
    lsum1 += __shfl_xor_sync(0xffffffffu, lsum1, 1);
    lsum1 += __shfl_xor_sync(0xffffffffu, lsum1, 2);
    const float inv0 = 1.f / lsum0;
    const float inv1 = 1.f / lsum1;

    const int b = bh >> 4, h = bh & 15;
    const int g = lane >> 2, c2 = (lane & 3) * 2;
    const int r0 = qt * 128 + w * 16 + g;
    float* o0 = O + ((size_t)(b * S_) + r0) * D_ + h * DH_;
    float* o1 = o0 + (size_t)8 * D_;
    #pragma unroll
    for (int t = 0; t < 8; t++) {
        *(float2*)(o0 + t * 8 + c2) = make_float2(oacc[t][0] * inv0, oacc[t][1] * inv0);
        *(float2*)(o1 + t * 8 + c2) = make_float2(oacc[t][2] * inv1, oacc[t][3] * inv1);
    }
}

// ---------------- QKV transform: l2norm + scale + xpos rotary ---------------
__global__ __launch_bounds__(256) void transform_kernel(
    const float* __restrict__ qkv,
    const float* __restrict__ q_scale, const float* __restrict__ k_scale,
    __nv_bfloat16* __restrict__ Qh, __nv_bfloat16* __restrict__ Ql,
    __nv_bfloat16* __restrict__ Kh, __nv_bfloat16* __restrict__ Kl,
    __nv_bfloat16* __restrict__ Vh, __nv_bfloat16* __restrict__ Vl)
{
    const int gw   = (blockIdx.x * blockDim.x + threadIdx.x) >> 5;
    const int lane = threadIdx.x & 31;
    const int s  = gw & (S_ - 1);
    const int bh = gw >> 11;
    if (bh >= BH_) return;
    const int b = bh >> 4, h = bh & 15;

    const float* base = qkv + ((size_t)(b * S_ + s)) * (3 * D_) + h * (3 * DH_);
    float q0 = base[lane],       q1 = base[lane + 32];
    float k0 = base[64 + lane],  k1 = base[96 + lane];
    float v0 = base[128 + lane], v1 = base[160 + lane];

    float nq = q0 * q0 + q1 * q1;
    float nk = k0 * k0 + k1 * k1;
    #pragma unroll
    for (int off = 16; off; off >>= 1) {
        nq += __shfl_xor_sync(0xffffffffu, nq, off);
        nk += __shfl_xor_sync(0xffffffffu, nk, off);
    }
    nq = fmaxf(sqrtf(nq), 1e-12f);
    nk = fmaxf(sqrtf(nk), 1e-12f);

    q0 = q0 / nq * q_scale[lane]; q1 = q1 / nq * q_scale[lane + 32];
    k0 = k0 / nk * k_scale[lane]; k1 = k1 / nk * k_scale[lane + 32];

    const float d2 = 2.0f * (float)lane;
    const float inv_freq = exp2f(-d2 * (13.287712379549449f / 64.0f));
    const float fr = (float)s * inv_freq;
    float sn, c;
    sincosf(fr, &sn, &c);

    const float basev = (d2 + 0.4f * 64.0f) / (1.4f * 64.0f);
    const float power = ((float)s - (float)(S_ / 2)) / 512.0f;
    const float scale = exp2f(power * log2f(basev));
    const float iscale = 1.0f / scale;

    const float qo0 = (q0 * c - q1 * sn) * scale * 0.125f;
    const float qo1 = (q1 * c + q0 * sn) * scale * 0.125f;
    const float ko0 = (k0 * c - k1 * sn) * iscale;
    const float ko1 = (k1 * c + k0 * sn) * iscale;

    const size_t ob = ((size_t)bh * S_ + s) * DH_;
    Qh[ob + lane]      = __float2bfloat16_rn(qo0);
    Ql[ob + lane]      = __float2bfloat16_rn(bfres(qo0));
    Qh[ob + lane + 32] = __float2bfloat16_rn(qo1);
    Ql[ob + lane + 32] = __float2bfloat16_rn(bfres(qo1));
    Kh[ob + lane]      = __float2bfloat16_rn(ko0);
    Kl[ob + lane]      = __float2bfloat16_rn(bfres(ko0));
    Kh[ob + lane + 32] = __float2bfloat16_rn(ko1);
    Kl[ob + lane + 32] = __float2bfloat16_rn(bfres(ko1));
    Vh[ob + lane]      = __float2bfloat16_rn(v0);
    Vl[ob + lane]      = __float2bfloat16_rn(bfres(v0));
    Vh[ob + lane + 32] = __float2bfloat16_rn(v1);
    Vl[ob + lane + 32] = __float2bfloat16_rn(bfres(v1));
}

// ---------------- LayerNorm --------------------------------------------------
__global__ __launch_bounds__(256) void ln_kernel(
    const float* __restrict__ X, const float* __restrict__ g,
    const float* __restrict__ bb, float* __restrict__ Y)
{
    __shared__ float red[16];
    const int row = blockIdx.x;
    const int tid = threadIdx.x;
    const float* xp = X + (size_t)row * D_;

    float4 x4 = ((const float4*)xp)[tid];
    float s  = x4.x + x4.y + x4.z + x4.w;
    float ss = x4.x * x4.x + x4.y * x4.y + x4.z * x4.z + x4.w * x4.w;

    #pragma unroll
    for (int off = 16; off; off >>= 1) {
        s  += __shfl_xor_sync(0xffffffffu, s,  off);
        ss += __shfl_xor_sync(0xffffffffu, ss, off);
    }
    const int wid = tid >> 5, lane = tid & 31;
    if (lane == 0) { red[wid] = s; red[wid + 8] = ss; }
    __syncthreads();
    if (wid == 0) {
        float a = (lane < 8) ? red[lane] : 0.f;
        float bsum = (lane < 8) ? red[lane + 8] : 0.f;
        #pragma unroll
        for (int off = 4; off; off >>= 1) {
            a    += __shfl_xor_sync(0xffffffffu, a,    off);
            bsum += __shfl_xor_sync(0xffffffffu, bsum, off);
        }
        if (lane == 0) { red[0] = a; red[1] = bsum; }
    }
    __syncthreads();
    const float mu  = red[0] * (1.0f / D_);
    const float var = red[1] * (1.0f / D_) - mu * mu;
    const float rstd = rsqrtf(var + 1e-5f);

    float4 g4 = ((const float4*)g)[tid];
    float4 b4 = ((const float4*)bb)[tid];
    float4 y;
    y.x = (x4.x - mu) * rstd * g4.x + b4.x;
    y.y = (x4.y - mu) * rstd * g4.y + b4.y;
    y.z = (x4.z - mu) * rstd * g4.z + b4.z;
    y.w = (x4.w - mu) * rstd * g4.w + b4.w;
    ((float4*)(Y + (size_t)row * D_))[tid] = y;
}

// ---------------- launch -----------------------------------------------------
extern "C" void kernel_launch(void* const* d_in, const int* in_sizes, int n_in,
                              void* d_out, int out_size)
{
    const float* Q     = (const float*)d_in[0];
    const float* Wqkv  = (const float*)d_in[3];
    const float* bqkv  = (const float*)d_in[4];
    const float* q_sc  = (const float*)d_in[5];
    const float* k_sc  = (const float*)d_in[6];
    const float* ln_g  = (const float*)d_in[7];
    const float* ln_b  = (const float*)d_in[8];
    const float* W1    = (const float*)d_in[9];
    const float* b1    = (const float*)d_in[10];
    const float* W2    = (const float*)d_in[11];
    const float* b2    = (const float*)d_in[12];
    float* out = (float*)d_out;

    float *qkv, *att, *x, *h;
    __nv_bfloat16 *qh, *ql, *kh, *kl, *vh, *vl;
    cudaGetSymbolAddress((void**)&qkv, g_qkv);
    cudaGetSymbolAddress((void**)&qh,  g_qh);
    cudaGetSymbolAddress((void**)&ql,  g_ql);
    cudaGetSymbolAddress((void**)&kh,  g_kh);
    cudaGetSymbolAddress((void**)&kl,  g_kl);
    cudaGetSymbolAddress((void**)&vh,  g_vh);
    cudaGetSymbolAddress((void**)&vl,  g_vl);
    cudaGetSymbolAddress((void**)&att, g_att);
    cudaGetSymbolAddress((void**)&x,   g_x);
    cudaGetSymbolAddress((void**)&h,   g_h);

    cudaFuncSetAttribute(fattn_kernel,
                         cudaFuncAttributeMaxDynamicSharedMemorySize, ATTN_SMEM);
    cudaFuncSetAttribute(mma_gemm<0>,
                         cudaFuncAttributeMaxDynamicSharedMemorySize, GEMM_SMEM);
    cudaFuncSetAttribute(mma_gemm<1>,
                         cudaFuncAttributeMaxDynamicSharedMemorySize, GEMM_SMEM);
    cudaFuncSetAttribute(mma_gemm<2>,
                         cudaFuncAttributeMaxDynamicSharedMemorySize, GEMM_SMEM);

    // 1) QKV projection
    mma_gemm<0><<<dim3(3 * D_ / 128, BS_ / 128), 256, GEMM_SMEM>>>(
        Q, Wqkv, bqkv, nullptr, qkv, BS_, 3 * D_, D_);

    // 2) l2norm + scale + rotary -> split-bf16 planes
    transform_kernel<<<BH_ * S_ / 8, 256>>>(qkv, q_sc, k_sc,
                                            qh, ql, kh, kl, vh, vl);

    // 3) flash attention
    fattn_kernel<<<dim3(S_ / 128, BH_), 256, ATTN_SMEM>>>(
        qh, ql, kh, kl, vh, vl, att);

    // 4) LayerNorm
    ln_kernel<<<BS_, 256>>>(att, ln_g, ln_b, x);

    // 5) FF1 + SiLU
    mma_gemm<1><<<dim3(FF_ / 128, BS_ / 128), 256, GEMM_SMEM>>>(
        x, W1, b1, nullptr, h, BS_, FF_, D_);

    // 6) FF2 + residual
    mma_gemm<2><<<dim3(D_ / 128, BS_ / 128), 256, GEMM_SMEM>>>(
        h, W2, b2, x, out, BS_, D_, FF_);
}

// round 11
// speedup vs baseline: 3.6127x; 1.4284x over previous
#include <cuda_runtime.h>
#include <cuda_bf16.h>
#include <math.h>
#include <stdint.h>

#define B_   4
#define S_   2048
#define H_   16
#define DH_  64
#define D_   1024
#define FF_  2048
#define BS_  (B_*S_)
#define BH_  (B_*H_)

// ---------------- scratch (device globals; no runtime allocation) -----------
__device__ float g_qkv[(size_t)BS_ * 3 * D_];
__device__ __nv_bfloat16 g_qih[(size_t)BS_ * D_];      // split input Q
__device__ __nv_bfloat16 g_qil[(size_t)BS_ * D_];
__device__ __nv_bfloat16 g_wqh[(size_t)D_ * 3 * D_];   // split Wqkv
__device__ __nv_bfloat16 g_wql[(size_t)D_ * 3 * D_];
__device__ __nv_bfloat16 g_w1h[(size_t)D_ * FF_];
__device__ __nv_bfloat16 g_w1l[(size_t)D_ * FF_];
__device__ __nv_bfloat16 g_w2h[(size_t)FF_ * D_];
__device__ __nv_bfloat16 g_w2l[(size_t)FF_ * D_];
__device__ __nv_bfloat16 g_qh[(size_t)BH_ * S_ * DH_];
__device__ __nv_bfloat16 g_ql[(size_t)BH_ * S_ * DH_];
__device__ __nv_bfloat16 g_kh[(size_t)BH_ * S_ * DH_];
__device__ __nv_bfloat16 g_kl[(size_t)BH_ * S_ * DH_];
__device__ __nv_bfloat16 g_vh[(size_t)BH_ * S_ * DH_];
__device__ __nv_bfloat16 g_vl[(size_t)BH_ * S_ * DH_];
__device__ float g_att[(size_t)BS_ * D_];
__device__ float g_x  [(size_t)BS_ * D_];
__device__ __nv_bfloat16 g_xh[(size_t)BS_ * D_];
__device__ __nv_bfloat16 g_xl[(size_t)BS_ * D_];
__device__ __nv_bfloat16 g_hh[(size_t)BS_ * FF_];
__device__ __nv_bfloat16 g_hl[(size_t)BS_ * FF_];

// ---------------- split-bf16 helpers ----------------------------------------
__device__ __forceinline__ float bfres(float a) {
    return a - __bfloat162float(__float2bfloat16_rn(a));
}
__device__ __forceinline__ unsigned packbf(float a, float b) {
    __nv_bfloat162 t;
    t.x = __float2bfloat16_rn(a);
    t.y = __float2bfloat16_rn(b);
    return *reinterpret_cast<unsigned*>(&t);
}

// ---------------- PTX primitives ---------------------------------------------
__device__ __forceinline__ void ldsm4(unsigned* d, unsigned a) {
    asm volatile("ldmatrix.sync.aligned.m8n8.x4.shared.b16 {%0,%1,%2,%3}, [%4];"
                 : "=r"(d[0]), "=r"(d[1]), "=r"(d[2]), "=r"(d[3]) : "r"(a));
}
__device__ __forceinline__ void ldsm4t(unsigned* d, unsigned a) {
    asm volatile("ldmatrix.sync.aligned.m8n8.x4.trans.shared.b16 {%0,%1,%2,%3}, [%4];"
                 : "=r"(d[0]), "=r"(d[1]), "=r"(d[2]), "=r"(d[3]) : "r"(a));
}
__device__ __forceinline__ void mma_bf16(float* c, const unsigned* a,
                                         unsigned b0, unsigned b1) {
    asm volatile(
        "mma.sync.aligned.m16n8k16.row.col.f32.bf16.bf16.f32 "
        "{%0,%1,%2,%3}, {%4,%5,%6,%7}, {%8,%9}, {%0,%1,%2,%3};"
        : "+f"(c[0]), "+f"(c[1]), "+f"(c[2]), "+f"(c[3])
        : "r"(a[0]), "r"(a[1]), "r"(a[2]), "r"(a[3]), "r"(b0), "r"(b1));
}
__device__ __forceinline__ void cpa16(unsigned dst, const void* src) {
    asm volatile("cp.async.ca.shared.global [%0], [%1], 16;" :: "r"(dst), "l"(src));
}
__device__ __forceinline__ void cpa_commit() {
    asm volatile("cp.async.commit_group;");
}
__device__ __forceinline__ void cpa_wait0() {
    asm volatile("cp.async.wait_group 0;" ::: "memory");
}

// ============================================================================
// split_kernel: fp32 -> bf16 hi/lo planes (vectorized, grid-stride)
// ============================================================================
__global__ __launch_bounds__(256) void split_kernel(
    const float* __restrict__ X,
    __nv_bfloat16* __restrict__ Xh, __nv_bfloat16* __restrict__ Xl, int n4)
{
    const int stride = gridDim.x * blockDim.x;
    for (int i = blockIdx.x * blockDim.x + threadIdx.x; i < n4; i += stride) {
        float4 v = ((const float4*)X)[i];
        ((uint2*)Xh)[i] = make_uint2(packbf(v.x, v.y), packbf(v.z, v.w));
        ((uint2*)Xl)[i] = make_uint2(packbf(bfres(v.x), bfres(v.y)),
                                     packbf(bfres(v.z), bfres(v.w)));
    }
}

// ============================================================================
// Raw-mma split-bf16 GEMM, pre-split operands, cp.async double-buffer.
// CTA 128x128, 8 warps (4m x 2n), warp tile 32x64, k-chunk 32, 1 sync/chunk.
// MODE 0: C fp32.  MODE 1: SiLU -> Ch/Cl bf16 planes.  MODE 2: +res -> C fp32.
// Buffer layout (37888 B): Ah[128][40] 10240 | Al 10240 | Bh[32][136] 8704 | Bl 8704
// ============================================================================
#define GA_ 80
#define GB_ 272
#define GBUF 37888
#define GEMM_SMEM (2 * GBUF)

template <int MODE>
__global__ __launch_bounds__(256, 2) void mma_gemm(
    const __nv_bfloat16* __restrict__ Ah, const __nv_bfloat16* __restrict__ Al,
    const __nv_bfloat16* __restrict__ Bh, const __nv_bfloat16* __restrict__ Bl,
    const float* __restrict__ bias, const float* __restrict__ res,
    float* __restrict__ C,
    __nv_bfloat16* __restrict__ Ch, __nv_bfloat16* __restrict__ Cl,
    int M, int N, int K)
{
    extern __shared__ unsigned char smg[];
    const unsigned sb = (unsigned)__cvta_generic_to_shared(smg);

    const int tid = threadIdx.x;
    const int w = tid >> 5;
    const int lane = tid & 31;
    const int wmr = w & 3;       // 4 m-warps: rows wmr*32..+32
    const int wnc = w >> 2;      // 2 n-warps: cols wnc*64..+64
    const int bx = blockIdx.x, by = blockIdx.y;

    const int lj = lane >> 3, lr = lane & 7;
    const int rowoff = (lj & 1) * 8 + lr;
    const int coloff = (lj >> 1) * 8;
    const int g = lane >> 2, c2 = (lane & 3) * 2;

    float acc[2][8][4];
    #pragma unroll
    for (int mt = 0; mt < 2; mt++)
        #pragma unroll
        for (int n = 0; n < 8; n++) {
            acc[mt][n][0] = 0.f; acc[mt][n][1] = 0.f;
            acc[mt][n][2] = 0.f; acc[mt][n][3] = 0.f;
        }

    // cp.async staging: 2048 16B-chunks per buffer, 8 per thread
    // chunks 0..1023: A (plane, row 0..127, quad 0..3)
    // chunks 1024..2047: B (plane, row 0..31, oct 0..15)
    const int NC = K >> 5;

    // stage chunk kc into buffer buf
    auto stage = [&](int kc, unsigned bufo) {
        const int k0 = kc * 32;
        #pragma unroll
        for (int i = 0; i < 8; i++) {
            int chunk = i * 256 + tid;
            if (chunk < 1024) {
                int plane = chunk >> 9;
                int rem = chunk & 511;
                int row = rem >> 2;
                int q = rem & 3;
                const __nv_bfloat16* src = (plane ? Al : Ah)
                    + (size_t)(by * 128 + row) * K + k0 + q * 8;
                cpa16(sb + bufo + plane * 10240u + row * GA_ + q * 16, src);
            } else {
                int c = chunk - 1024;
                int plane = c >> 9;
                int rem = c & 511;
                int row = rem >> 4;
                int o = rem & 15;
                const __nv_bfloat16* src = (plane ? Bl : Bh)
                    + (size_t)(k0 + row) * N + bx * 128 + o * 8;
                cpa16(sb + bufo + 20480u + plane * 8704u + row * GB_ + o * 16, src);
            }
        }
    };

    stage(0, 0u);
    cpa_commit();

    for (int kc = 0; kc < NC; kc++) {
        cpa_wait0();
        __syncthreads();

        const unsigned buf = (unsigned)((kc & 1) * GBUF);
        if (kc + 1 < NC) {
            stage(kc + 1, (unsigned)(((kc + 1) & 1) * GBUF));
            cpa_commit();
        }

        const unsigned uAh = sb + buf, uBh = sb + buf + 20480u;

        #pragma unroll
        for (int ks = 0; ks < 2; ks++) {
            unsigned ah[2][4], al[2][4];
            #pragma unroll
            for (int mt = 0; mt < 2; mt++) {
                const unsigned addr = uAh
                    + (unsigned)((wmr * 32 + mt * 16 + rowoff) * GA_ + (ks * 16 + coloff) * 2);
                ldsm4(ah[mt], addr);
                ldsm4(al[mt], addr + 10240u);
            }
            #pragma unroll
            for (int gg = 0; gg < 4; gg++) {
                unsigned bhf[4], blf[4];
                const unsigned baddr = uBh
                    + (unsigned)((ks * 16 + rowoff) * GB_ + (wnc * 64 + gg * 16 + coloff) * 2);
                ldsm4t(bhf, baddr);
                ldsm4t(blf, baddr + 8704u);
                #pragma unroll
                for (int mt = 0; mt < 2; mt++) {
                    mma_bf16(acc[mt][2 * gg],     ah[mt], bhf[0], bhf[1]);
                    mma_bf16(acc[mt][2 * gg],     ah[mt], blf[0], blf[1]);
                    mma_bf16(acc[mt][2 * gg],     al[mt], bhf[0], bhf[1]);
                    mma_bf16(acc[mt][2 * gg + 1], ah[mt], bhf[2], bhf[3]);
                    mma_bf16(acc[mt][2 * gg + 1], ah[mt], blf[2], blf[3]);
                    mma_bf16(acc[mt][2 * gg + 1], al[mt], bhf[2], bhf[3]);
                }
            }
        }
    }

    // epilogue: regs -> gmem directly
    #pragma unroll
    for (int mt = 0; mt < 2; mt++) {
        #pragma unroll
        for (int n = 0; n < 8; n++) {
            const int row = by * 128 + wmr * 32 + mt * 16 + g;
            const int col = bx * 128 + wnc * 64 + n * 8 + c2;
            float2 bb2 = *(const float2*)(bias + col);
            float v0 = acc[mt][n][0] + bb2.x;
            float v1 = acc[mt][n][1] + bb2.y;
            float v2 = acc[mt][n][2] + bb2.x;
            float v3 = acc[mt][n][3] + bb2.y;
            if (MODE == 1) {
                v0 = v0 / (1.f + __expf(-v0));
                v1 = v1 / (1.f + __expf(-v1));
                v2 = v2 / (1.f + __expf(-v2));
                v3 = v3 / (1.f + __expf(-v3));
                *(unsigned*)(Ch + (size_t)row * N + col) = packbf(v0, v1);
                *(unsigned*)(Cl + (size_t)row * N + col) = packbf(bfres(v0), bfres(v1));
                *(unsigned*)(Ch + (size_t)(row + 8) * N + col) = packbf(v2, v3);
                *(unsigned*)(Cl + (size_t)(row + 8) * N + col) = packbf(bfres(v2), bfres(v3));
            } else {
                if (MODE == 2) {
                    float2 r0 = *(const float2*)(res + (size_t)row * N + col);
                    float2 r1 = *(const float2*)(res + (size_t)(row + 8) * N + col);
                    v0 += r0.x; v1 += r0.y; v2 += r1.x; v3 += r1.y;
                }
                *(float2*)(C + (size_t)row * N + col)       = make_float2(v0, v1);
                *(float2*)(C + (size_t)(row + 8) * N + col) = make_float2(v2, v3);
            }
        }
    }
}

// ============================================================================
// Flash attention, register softmax, raw mma split-bf16 (validated R9/R10).
// ============================================================================
#define ALD 144
#define APLANE 4608
#define AKVBUF 18432
#define AQH 36864
#define AQL 55296
#define ATTN_SMEM 73728

__global__ __launch_bounds__(256, 2) void fattn_kernel(
    const __nv_bfloat16* __restrict__ Qh, const __nv_bfloat16* __restrict__ Ql,
    const __nv_bfloat16* __restrict__ Kh, const __nv_bfloat16* __restrict__ Kl,
    const __nv_bfloat16* __restrict__ Vh, const __nv_bfloat16* __restrict__ Vl,
    float* __restrict__ O)
{
    extern __shared__ unsigned char smc[];
    const unsigned sbase = (unsigned)__cvta_generic_to_shared(smc);

    const int tid = threadIdx.x;
    const int w   = tid >> 5;
    const int lane = tid & 31;
    const int bh = blockIdx.y;
    const int qt = blockIdx.x;

    const int lj = lane >> 3, lr = lane & 7;
    const int rowoff = (lj & 1) * 8 + lr;
    const int coloff = (lj >> 1) * 8;

    const size_t qbase  = ((size_t)bh * S_ + qt * 128) * DH_;
    const size_t kvbase = (size_t)bh * S_ * DH_;

    #pragma unroll
    for (int i = 0; i < 8; i++) {
        int chunk = i * 256 + tid;
        int plane = chunk >> 10;
        int rem = chunk & 1023;
        int row = rem >> 3;
        int c8 = (rem & 7) * 8;
        const __nv_bfloat16* src = (plane ? Ql : Qh) + qbase + (size_t)row * DH_ + c8;
        cpa16(sbase + (plane ? AQL : AQH) + row * ALD + c8 * 2, src);
    }
    #pragma unroll
    for (int i = 0; i < 4; i++) {
        int chunk = i * 256 + tid;
        int plane = chunk >> 8;
        int rem = chunk & 255;
        int row = rem >> 3;
        int c8 = (rem & 7) * 8;
        const __nv_bfloat16* srcb =
            (plane == 0 ? Kh : plane == 1 ? Kl : plane == 2 ? Vh : Vl)
            + kvbase + (size_t)row * DH_ + c8;
        cpa16(sbase + plane * APLANE + row * ALD + c8 * 2, srcb);
    }
    cpa_commit();

    unsigned qfh[4][4], qfl[4][4];
    float oacc[8][4];
    #pragma unroll
    for (int t = 0; t < 8; t++) {
        oacc[t][0] = 0.f; oacc[t][1] = 0.f; oacc[t][2] = 0.f; oacc[t][3] = 0.f;
    }
    float lsum0 = 0.f, lsum1 = 0.f;

    const int NT = S_ / 32;
    for (int kt = 0; kt < NT; kt++) {
        cpa_wait0();
        __syncthreads();

        if (kt == 0) {
            #pragma unroll
            for (int ks = 0; ks < 4; ks++) {
                unsigned qoff = (unsigned)((w * 16 + rowoff) * ALD + (ks * 16 + coloff) * 2);
                ldsm4(qfh[ks], sbase + AQH + qoff);
                ldsm4(qfl[ks], sbase + AQL + qoff);
            }
        }

        const unsigned buf = sbase + (kt & 1) * AKVBUF;

        if (kt + 1 < NT) {
            const size_t tb = kvbase + (size_t)(kt + 1) * 32 * DH_;
            const unsigned dbuf = sbase + ((kt + 1) & 1) * AKVBUF;
            #pragma unroll
            for (int i = 0; i < 4; i++) {
                int chunk = i * 256 + tid;
                int plane = chunk >> 8;
                int rem = chunk & 255;
                int row = rem >> 3;
                int c8 = (rem & 7) * 8;
                const __nv_bfloat16* srcb =
                    (plane == 0 ? Kh : plane == 1 ? Kl : plane == 2 ? Vh : Vl)
                    + tb + (size_t)row * DH_ + c8;
                cpa16(dbuf + plane * APLANE + row * ALD + c8 * 2, srcb);
            }
            cpa_commit();
        }

        float sacc[4][4];
        #pragma unroll
        for (int nt = 0; nt < 4; nt++) {
            sacc[nt][0] = 0.f; sacc[nt][1] = 0.f; sacc[nt][2] = 0.f; sacc[nt][3] = 0.f;
        }
        #pragma unroll
        for (int ks = 0; ks < 4; ks++) {
            #pragma unroll
            for (int g2 = 0; g2 < 2; g2++) {
                unsigned kbh[4], kbl[4];
                unsigned off = buf + (unsigned)((g2 * 16 + rowoff) * ALD + (ks * 16 + coloff) * 2);
                ldsm4(kbh, off);
                ldsm4(kbl, off + APLANE);
                mma_bf16(sacc[2 * g2],     qfh[ks], kbh[0], kbh[2]);
                mma_bf16(sacc[2 * g2],     qfh[ks], kbl[0], kbl[2]);
                mma_bf16(sacc[2 * g2],     qfl[ks], kbh[0], kbh[2]);
                mma_bf16(sacc[2 * g2 + 1], qfh[ks], kbh[1], kbh[3]);
                mma_bf16(sacc[2 * g2 + 1], qfh[ks], kbl[1], kbl[3]);
                mma_bf16(sacc[2 * g2 + 1], qfl[ks], kbh[1], kbh[3]);
            }
        }

        #pragma unroll
        for (int nt = 0; nt < 4; nt++) {
            sacc[nt][0] = __expf(sacc[nt][0]); lsum0 += sacc[nt][0];
            sacc[nt][1] = __expf(sacc[nt][1]); lsum0 += sacc[nt][1];
            sacc[nt][2] = __expf(sacc[nt][2]); lsum1 += sacc[nt][2];
            sacc[nt][3] = __expf(sacc[nt][3]); lsum1 += sacc[nt][3];
        }

        #pragma unroll
        for (int ks2 = 0; ks2 < 2; ks2++) {
            unsigned aph[4], apl[4];
            const float* t0 = sacc[2 * ks2];
            const float* t1 = sacc[2 * ks2 + 1];
            aph[0] = packbf(t0[0], t0[1]); apl[0] = packbf(bfres(t0[0]), bfres(t0[1]));
            aph[1] = packbf(t0[2], t0[3]); apl[1] = packbf(bfres(t0[2]), bfres(t0[3]));
            aph[2] = packbf(t1[0], t1[1]); apl[2] = packbf(bfres(t1[0]), bfres(t1[1]));
            aph[3] = packbf(t1[2], t1[3]); apl[3] = packbf(bfres(t1[2]), bfres(t1[3]));
            #pragma unroll
            for (int gv = 0; gv < 4; gv++) {
                unsigned vbh[4], vbl[4];
                unsigned off = buf + 2 * APLANE
                             + (unsigned)((ks2 * 16 + rowoff) * ALD + (gv * 16 + coloff) * 2);
                ldsm4t(vbh, off);
                ldsm4t(vbl, off + APLANE);
                mma_bf16(oacc[2 * gv],     aph, vbh[0], vbh[1]);
                mma_bf16(oacc[2 * gv],     apl, vbh[0], vbh[1]);
                mma_bf16(oacc[2 * gv],     aph, vbl[0], vbl[1]);
                mma_bf16(oacc[2 * gv + 1], aph, vbh[2], vbh[3]);
                mma_bf16(oacc[2 * gv + 1], apl, vbh[2], vbh[3]);
                mma_bf16(oacc[2 * gv + 1], aph, vbl[2], vbl[3]);
            }
        }
    }

    lsum0 += __shfl_xor_sync(0xffffffffu, lsum0, 1);
    lsum0 += __shfl_xor_sync(0xffffffffu, lsum0, 2);
    lsum1 += __shfl_xor_sync(0xffffffffu, lsum1, 1);
    lsum1 += __shfl_xor_sync(0xffffffffu, lsum1, 2);
    const float inv0 = 1.f / lsum0;
    const float inv1 = 1.f / lsum1;

    const int b = bh >> 4, h = bh & 15;
    const int g = lane >> 2, c2 = (lane & 3) * 2;
    const int r0 = qt * 128 + w * 16 + g;
    float* o0 = O + ((size_t)(b * S_) + r0) * D_ + h * DH_;
    float* o1 = o0 + (size_t)8 * D_;
    #pragma unroll
    for (int t = 0; t < 8; t++) {
        *(float2*)(o0 + t * 8 + c2) = make_float2(oacc[t][0] * inv0, oacc[t][1] * inv0);
        *(float2*)(o1 + t * 8 + c2) = make_float2(oacc[t][2] * inv1, oacc[t][3] * inv1);
    }
}

// ---------------- QKV transform: l2norm + scale + xpos rotary ---------------
__global__ __launch_bounds__(256) void transform_kernel(
    const float* __restrict__ qkv,
    const float* __restrict__ q_scale, const float* __restrict__ k_scale,
    __nv_bfloat16* __restrict__ Qh, __nv_bfloat16* __restrict__ Ql,
    __nv_bfloat16* __restrict__ Kh, __nv_bfloat16* __restrict__ Kl,
    __nv_bfloat16* __restrict__ Vh, __nv_bfloat16* __restrict__ Vl)
{
    const int gw   = (blockIdx.x * blockDim.x + threadIdx.x) >> 5;
    const int lane = threadIdx.x & 31;
    const int s  = gw & (S_ - 1);
    const int bh = gw >> 11;
    if (bh >= BH_) return;
    const int b = bh >> 4, h = bh & 15;

    const float* base = qkv + ((size_t)(b * S_ + s)) * (3 * D_) + h * (3 * DH_);
    float q0 = base[lane],       q1 = base[lane + 32];
    float k0 = base[64 + lane],  k1 = base[96 + lane];
    float v0 = base[128 + lane], v1 = base[160 + lane];

    float nq = q0 * q0 + q1 * q1;
    float nk = k0 * k0 + k1 * k1;
    #pragma unroll
    for (int off = 16; off; off >>= 1) {
        nq += __shfl_xor_sync(0xffffffffu, nq, off);
        nk += __shfl_xor_sync(0xffffffffu, nk, off);
    }
    nq = fmaxf(sqrtf(nq), 1e-12f);
    nk = fmaxf(sqrtf(nk), 1e-12f);

    q0 = q0 / nq * q_scale[lane]; q1 = q1 / nq * q_scale[lane + 32];
    k0 = k0 / nk * k_scale[lane]; k1 = k1 / nk * k_scale[lane + 32];

    const float d2 = 2.0f * (float)lane;
    const float inv_freq = exp2f(-d2 * (13.287712379549449f / 64.0f));
    const float fr = (float)s * inv_freq;
    float sn, c;
    sincosf(fr, &sn, &c);

    const float basev = (d2 + 0.4f * 64.0f) / (1.4f * 64.0f);
    const float power = ((float)s - (float)(S_ / 2)) / 512.0f;
    const float scale = exp2f(power * log2f(basev));
    const float iscale = 1.0f / scale;

    const float qo0 = (q0 * c - q1 * sn) * scale * 0.125f;
    const float qo1 = (q1 * c + q0 * sn) * scale * 0.125f;
    const float ko0 = (k0 * c - k1 * sn) * iscale;
    const float ko1 = (k1 * c + k0 * sn) * iscale;

    const size_t ob = ((size_t)bh * S_ + s) * DH_;
    Qh[ob + lane]      = __float2bfloat16_rn(qo0);
    Ql[ob + lane]      = __float2bfloat16_rn(bfres(qo0));
    Qh[ob + lane + 32] = __float2bfloat16_rn(qo1);
    Ql[ob + lane + 32] = __float2bfloat16_rn(bfres(qo1));
    Kh[ob + lane]      = __float2bfloat16_rn(ko0);
    Kl[ob + lane]      = __float2bfloat16_rn(bfres(ko0));
    Kh[ob + lane + 32] = __float2bfloat16_rn(ko1);
    Kl[ob + lane + 32] = __float2bfloat16_rn(bfres(ko1));
    Vh[ob + lane]      = __float2bfloat16_rn(v0);
    Vl[ob + lane]      = __float2bfloat16_rn(bfres(v0));
    Vh[ob + lane + 32] = __float2bfloat16_rn(v1);
    Vl[ob + lane + 32] = __float2bfloat16_rn(bfres(v1));
}

// ---------------- LayerNorm (emits fp32 + hi/lo planes) ----------------------
__global__ __launch_bounds__(256) void ln_kernel(
    const float* __restrict__ X, const float* __restrict__ g,
    const float* __restrict__ bb, float* __restrict__ Y,
    __nv_bfloat16* __restrict__ Yh, __nv_bfloat16* __restrict__ Yl)
{
    __shared__ float red[16];
    const int row = blockIdx.x;
    const int tid = threadIdx.x;
    const float* xp = X + (size_t)row * D_;

    float4 x4 = ((const float4*)xp)[tid];
    float s  = x4.x + x4.y + x4.z + x4.w;
    float ss = x4.x * x4.x + x4.y * x4.y + x4.z * x4.z + x4.w * x4.w;

    #pragma unroll
    for (int off = 16; off; off >>= 1) {
        s  += __shfl_xor_sync(0xffffffffu, s,  off);
        ss += __shfl_xor_sync(0xffffffffu, ss, off);
    }
    const int wid = tid >> 5, lane = tid & 31;
    if (lane == 0) { red[wid] = s; red[wid + 8] = ss; }
    __syncthreads();
    if (wid == 0) {
        float a = (lane < 8) ? red[lane] : 0.f;
        float bsum = (lane < 8) ? red[lane + 8] : 0.f;
        #pragma unroll
        for (int off = 4; off; off >>= 1) {
            a    += __shfl_xor_sync(0xffffffffu, a,    off);
            bsum += __shfl_xor_sync(0xffffffffu, bsum, off);
        }
        if (lane == 0) { red[0] = a; red[1] = bsum; }
    }
    __syncthreads();
    const float mu  = red[0] * (1.0f / D_);
    const float var = red[1] * (1.0f / D_) - mu * mu;
    const float rstd = rsqrtf(var + 1e-5f);

    float4 g4 = ((const float4*)g)[tid];
    float4 b4 = ((const float4*)bb)[tid];
    float4 y;
    y.x = (x4.x - mu) * rstd * g4.x + b4.x;
    y.y = (x4.y - mu) * rstd * g4.y + b4.y;
    y.z = (x4.z - mu) * rstd * g4.z + b4.z;
    y.w = (x4.w - mu) * rstd * g4.w + b4.w;
    ((float4*)(Y + (size_t)row * D_))[tid] = y;
    ((uint2*)(Yh + (size_t)row * D_))[tid] =
        make_uint2(packbf(y.x, y.y), packbf(y.z, y.w));
    ((uint2*)(Yl + (size_t)row * D_))[tid] =
        make_uint2(packbf(bfres(y.x), bfres(y.y)), packbf(bfres(y.z), bfres(y.w)));
}

// ---------------- launch -----------------------------------------------------
extern "C" void kernel_launch(void* const* d_in, const int* in_sizes, int n_in,
                              void* d_out, int out_size)
{
    const float* Q     = (const float*)d_in[0];
    const float* Wqkv  = (const float*)d_in[3];
    const float* bqkv  = (const float*)d_in[4];
    const float* q_sc  = (const float*)d_in[5];
    const float* k_sc  = (const float*)d_in[6];
    const float* ln_g  = (const float*)d_in[7];
    const float* ln_b  = (const float*)d_in[8];
    const float* W1    = (const float*)d_in[9];
    const float* b1    = (const float*)d_in[10];
    const float* W2    = (const float*)d_in[11];
    const float* b2    = (const float*)d_in[12];
    float* out = (float*)d_out;

    float *qkv, *att, *x;
    __nv_bfloat16 *qih, *qil, *wqh, *wql, *w1h, *w1l, *w2h, *w2l;
    __nv_bfloat16 *qh, *ql, *kh, *kl, *vh, *vl, *xh, *xl, *hh, *hl;
    cudaGetSymbolAddress((void**)&qkv, g_qkv);
    cudaGetSymbolAddress((void**)&qih, g_qih);
    cudaGetSymbolAddress((void**)&qil, g_qil);
    cudaGetSymbolAddress((void**)&wqh, g_wqh);
    cudaGetSymbolAddress((void**)&wql, g_wql);
    cudaGetSymbolAddress((void**)&w1h, g_w1h);
    cudaGetSymbolAddress((void**)&w1l, g_w1l);
    cudaGetSymbolAddress((void**)&w2h, g_w2h);
    cudaGetSymbolAddress((void**)&w2l, g_w2l);
    cudaGetSymbolAddress((void**)&qh,  g_qh);
    cudaGetSymbolAddress((void**)&ql,  g_ql);
    cudaGetSymbolAddress((void**)&kh,  g_kh);
    cudaGetSymbolAddress((void**)&kl,  g_kl);
    cudaGetSymbolAddress((void**)&vh,  g_vh);
    cudaGetSymbolAddress((void**)&vl,  g_vl);
    cudaGetSymbolAddress((void**)&att, g_att);
    cudaGetSymbolAddress((void**)&x,   g_x);
    cudaGetSymbolAddress((void**)&xh,  g_xh);
    cudaGetSymbolAddress((void**)&xl,  g_xl);
    cudaGetSymbolAddress((void**)&hh,  g_hh);
    cudaGetSymbolAddress((void**)&hl,  g_hl);

    cudaFuncSetAttribute(fattn_kernel,
                         cudaFuncAttributeMaxDynamicSharedMemorySize, ATTN_SMEM);
    cudaFuncSetAttribute(mma_gemm<0>,
                         cudaFuncAttributeMaxDynamicSharedMemorySize, GEMM_SMEM);
    cudaFuncSetAttribute(mma_gemm<1>,
                         cudaFuncAttributeMaxDynamicSharedMemorySize, GEMM_SMEM);
    cudaFuncSetAttribute(mma_gemm<2>,
                         cudaFuncAttributeMaxDynamicSharedMemorySize, GEMM_SMEM);

    // 0) pre-split inputs and weights into bf16 hi/lo planes
    split_kernel<<<2048, 256>>>(Q, qih, qil, BS_ * D_ / 4);
    split_kernel<<<2048, 256>>>(Wqkv, wqh, wql, D_ * 3 * D_ / 4);
    split_kernel<<<2048, 256>>>(W1, w1h, w1l, D_ * FF_ / 4);
    split_kernel<<<2048, 256>>>(W2, w2h, w2l, FF_ * D_ / 4);

    // 1) QKV projection
    mma_gemm<0><<<dim3(3 * D_ / 128, BS_ / 128), 256, GEMM_SMEM>>>(
        qih, qil, wqh, wql, bqkv, nullptr, qkv, nullptr, nullptr,
        BS_, 3 * D_, D_);

    // 2) l2norm + scale + rotary -> split-bf16 planes
    transform_kernel<<<BH_ * S_ / 8, 256>>>(qkv, q_sc, k_sc,
                                            qh, ql, kh, kl, vh, vl);

    // 3) flash attention
    fattn_kernel<<<dim3(S_ / 128, BH_), 256, ATTN_SMEM>>>(
        qh, ql, kh, kl, vh, vl, att);

    // 4) LayerNorm -> x fp32 + hi/lo planes
    ln_kernel<<<BS_, 256>>>(att, ln_g, ln_b, x, xh, xl);

    // 5) FF1 + SiLU -> h hi/lo planes
    mma_gemm<1><<<dim3(FF_ / 128, BS_ / 128), 256, GEMM_SMEM>>>(
        xh, xl, w1h, w1l, b1, nullptr, nullptr, hh, hl,
        BS_, FF_, D_);

    // 6) FF2 + residual -> out fp32
    mma_gemm<2><<<dim3(D_ / 128, BS_ / 128), 256, GEMM_SMEM>>>(
        hh, hl, w2h, w2l, b2, x, out, nullptr, nullptr,
        BS_, D_, FF_);
}

// round 12
// speedup vs baseline: 3.7290x; 1.0322x over previous
#include <cuda_runtime.h>
#include <cuda_bf16.h>
#include <math.h>
#include <stdint.h>

#define B_   4
#define S_   2048
#define H_   16
#define DH_  64
#define D_   1024
#define FF_  2048
#define BS_  (B_*S_)
#define BH_  (B_*H_)

// ---------------- scratch (device globals; no runtime allocation) -----------
__device__ float g_qkv[(size_t)BS_ * 3 * D_];
__device__ __nv_bfloat16 g_qih[(size_t)BS_ * D_];
__device__ __nv_bfloat16 g_qil[(size_t)BS_ * D_];
__device__ __nv_bfloat16 g_wqh[(size_t)D_ * 3 * D_];
__device__ __nv_bfloat16 g_wql[(size_t)D_ * 3 * D_];
__device__ __nv_bfloat16 g_w1h[(size_t)D_ * FF_];
__device__ __nv_bfloat16 g_w1l[(size_t)D_ * FF_];
__device__ __nv_bfloat16 g_w2h[(size_t)FF_ * D_];
__device__ __nv_bfloat16 g_w2l[(size_t)FF_ * D_];
__device__ __nv_bfloat16 g_qh[(size_t)BH_ * S_ * DH_];
__device__ __nv_bfloat16 g_ql[(size_t)BH_ * S_ * DH_];
__device__ __nv_bfloat16 g_kh[(size_t)BH_ * S_ * DH_];
__device__ __nv_bfloat16 g_kl[(size_t)BH_ * S_ * DH_];
__device__ __nv_bfloat16 g_vh[(size_t)BH_ * S_ * DH_];
__device__ __nv_bfloat16 g_vl[(size_t)BH_ * S_ * DH_];
__device__ float g_att[(size_t)BS_ * D_];
__device__ float g_x  [(size_t)BS_ * D_];
__device__ __nv_bfloat16 g_xh[(size_t)BS_ * D_];
__device__ __nv_bfloat16 g_xl[(size_t)BS_ * D_];
__device__ __nv_bfloat16 g_hh[(size_t)BS_ * FF_];
__device__ __nv_bfloat16 g_hl[(size_t)BS_ * FF_];

// ---------------- split-bf16 helpers ----------------------------------------
__device__ __forceinline__ float bfres(float a) {
    return a - __bfloat162float(__float2bfloat16_rn(a));
}
__device__ __forceinline__ unsigned packbf(float a, float b) {
    __nv_bfloat162 t;
    t.x = __float2bfloat16_rn(a);
    t.y = __float2bfloat16_rn(b);
    return *reinterpret_cast<unsigned*>(&t);
}

// ---------------- PTX primitives ---------------------------------------------
__device__ __forceinline__ void ldsm4(unsigned* d, unsigned a) {
    asm volatile("ldmatrix.sync.aligned.m8n8.x4.shared.b16 {%0,%1,%2,%3}, [%4];"
                 : "=r"(d[0]), "=r"(d[1]), "=r"(d[2]), "=r"(d[3]) : "r"(a));
}
__device__ __forceinline__ void ldsm4t(unsigned* d, unsigned a) {
    asm volatile("ldmatrix.sync.aligned.m8n8.x4.trans.shared.b16 {%0,%1,%2,%3}, [%4];"
                 : "=r"(d[0]), "=r"(d[1]), "=r"(d[2]), "=r"(d[3]) : "r"(a));
}
__device__ __forceinline__ void mma_bf16(float* c, const unsigned* a,
                                         unsigned b0, unsigned b1) {
    asm volatile(
        "mma.sync.aligned.m16n8k16.row.col.f32.bf16.bf16.f32 "
        "{%0,%1,%2,%3}, {%4,%5,%6,%7}, {%8,%9}, {%0,%1,%2,%3};"
        : "+f"(c[0]), "+f"(c[1]), "+f"(c[2]), "+f"(c[3])
        : "r"(a[0]), "r"(a[1]), "r"(a[2]), "r"(a[3]), "r"(b0), "r"(b1));
}
__device__ __forceinline__ void cpa16(unsigned dst, const void* src) {
    asm volatile("cp.async.ca.shared.global [%0], [%1], 16;" :: "r"(dst), "l"(src));
}
__device__ __forceinline__ void cpa_commit() {
    asm volatile("cp.async.commit_group;");
}
__device__ __forceinline__ void cpa_wait0() {
    asm volatile("cp.async.wait_group 0;" ::: "memory");
}

// ============================================================================
// split_kernel: fp32 -> bf16 hi/lo planes
// ============================================================================
__global__ __launch_bounds__(256) void split_kernel(
    const float* __restrict__ X,
    __nv_bfloat16* __restrict__ Xh, __nv_bfloat16* __restrict__ Xl, int n4)
{
    const int stride = gridDim.x * blockDim.x;
    for (int i = blockIdx.x * blockDim.x + threadIdx.x; i < n4; i += stride) {
        float4 v = ((const float4*)X)[i];
        ((uint2*)Xh)[i] = make_uint2(packbf(v.x, v.y), packbf(v.z, v.w));
        ((uint2*)Xl)[i] = make_uint2(packbf(bfres(v.x), bfres(v.y)),
                                     packbf(bfres(v.z), bfres(v.w)));
    }
}

// ============================================================================
// Raw-mma split-bf16 GEMM (pre-split operands, cp.async double-buffer).
// CTA 128x128, 8 warps (4m x 2n), warp tile 32x64, k-chunk 32, 1 sync/chunk.
// MODE 0: C fp32.  MODE 1: SiLU -> Ch/Cl bf16 planes.  MODE 2: +res -> C fp32.
// ============================================================================
#define GA_ 80
#define GB_ 272
#define GBUF 37888
#define GEMM_SMEM (2 * GBUF)

template <int MODE>
__global__ __launch_bounds__(256, 2) void mma_gemm(
    const __nv_bfloat16* __restrict__ Ah, const __nv_bfloat16* __restrict__ Al,
    const __nv_bfloat16* __restrict__ Bh, const __nv_bfloat16* __restrict__ Bl,
    const float* __restrict__ bias, const float* __restrict__ res,
    float* __restrict__ C,
    __nv_bfloat16* __restrict__ Ch, __nv_bfloat16* __restrict__ Cl,
    int M, int N, int K)
{
    extern __shared__ unsigned char smg[];
    const unsigned sb = (unsigned)__cvta_generic_to_shared(smg);

    const int tid = threadIdx.x;
    const int w = tid >> 5;
    const int lane = tid & 31;
    const int wmr = w & 3;
    const int wnc = w >> 2;
    const int bx = blockIdx.x, by = blockIdx.y;

    const int lj = lane >> 3, lr = lane & 7;
    const int rowoff = (lj & 1) * 8 + lr;
    const int coloff = (lj >> 1) * 8;
    const int g = lane >> 2, c2 = (lane & 3) * 2;

    float acc[2][8][4];
    #pragma unroll
    for (int mt = 0; mt < 2; mt++)
        #pragma unroll
        for (int n = 0; n < 8; n++) {
            acc[mt][n][0] = 0.f; acc[mt][n][1] = 0.f;
            acc[mt][n][2] = 0.f; acc[mt][n][3] = 0.f;
        }

    const int NC = K >> 5;

    auto stage = [&](int kc, unsigned bufo) {
        const int k0 = kc * 32;
        #pragma unroll
        for (int i = 0; i < 8; i++) {
            int chunk = i * 256 + tid;
            if (chunk < 1024) {
                int plane = chunk >> 9;
                int rem = chunk & 511;
                int row = rem >> 2;
                int q = rem & 3;
                const __nv_bfloat16* src = (plane ? Al : Ah)
                    + (size_t)(by * 128 + row) * K + k0 + q * 8;
                cpa16(sb + bufo + plane * 10240u + row * GA_ + q * 16, src);
            } else {
                int c = chunk - 1024;
                int plane = c >> 9;
                int rem = c & 511;
                int row = rem >> 4;
                int o = rem & 15;
                const __nv_bfloat16* src = (plane ? Bl : Bh)
                    + (size_t)(k0 + row) * N + bx * 128 + o * 8;
                cpa16(sb + bufo + 20480u + plane * 8704u + row * GB_ + o * 16, src);
            }
        }
    };

    stage(0, 0u);
    cpa_commit();

    for (int kc = 0; kc < NC; kc++) {
        cpa_wait0();
        __syncthreads();

        const unsigned buf = (unsigned)((kc & 1) * GBUF);
        if (kc + 1 < NC) {
            stage(kc + 1, (unsigned)(((kc + 1) & 1) * GBUF));
            cpa_commit();
        }

        const unsigned uAh = sb + buf, uBh = sb + buf + 20480u;

        #pragma unroll
        for (int ks = 0; ks < 2; ks++) {
            unsigned ah[2][4], al[2][4];
            #pragma unroll
            for (int mt = 0; mt < 2; mt++) {
                const unsigned addr = uAh
                    + (unsigned)((wmr * 32 + mt * 16 + rowoff) * GA_ + (ks * 16 + coloff) * 2);
                ldsm4(ah[mt], addr);
                ldsm4(al[mt], addr + 10240u);
            }
            #pragma unroll
            for (int gg = 0; gg < 4; gg++) {
                unsigned bhf[4], blf[4];
                const unsigned baddr = uBh
                    + (unsigned)((ks * 16 + rowoff) * GB_ + (wnc * 64 + gg * 16 + coloff) * 2);
                ldsm4t(bhf, baddr);
                ldsm4t(blf, baddr + 8704u);
                #pragma unroll
                for (int mt = 0; mt < 2; mt++) {
                    mma_bf16(acc[mt][2 * gg],     ah[mt], bhf[0], bhf[1]);
                    mma_bf16(acc[mt][2 * gg],     ah[mt], blf[0], blf[1]);
                    mma_bf16(acc[mt][2 * gg],     al[mt], bhf[0], bhf[1]);
                    mma_bf16(acc[mt][2 * gg + 1], ah[mt], bhf[2], bhf[3]);
                    mma_bf16(acc[mt][2 * gg + 1], ah[mt], blf[2], blf[3]);
                    mma_bf16(acc[mt][2 * gg + 1], al[mt], bhf[2], bhf[3]);
                }
            }
        }
    }

    #pragma unroll
    for (int mt = 0; mt < 2; mt++) {
        #pragma unroll
        for (int n = 0; n < 8; n++) {
            const int row = by * 128 + wmr * 32 + mt * 16 + g;
            const int col = bx * 128 + wnc * 64 + n * 8 + c2;
            float2 bb2 = *(const float2*)(bias + col);
            float v0 = acc[mt][n][0] + bb2.x;
            float v1 = acc[mt][n][1] + bb2.y;
            float v2 = acc[mt][n][2] + bb2.x;
            float v3 = acc[mt][n][3] + bb2.y;
            if (MODE == 1) {
                v0 = v0 / (1.f + __expf(-v0));
                v1 = v1 / (1.f + __expf(-v1));
                v2 = v2 / (1.f + __expf(-v2));
                v3 = v3 / (1.f + __expf(-v3));
                *(unsigned*)(Ch + (size_t)row * N + col) = packbf(v0, v1);
                *(unsigned*)(Cl + (size_t)row * N + col) = packbf(bfres(v0), bfres(v1));
                *(unsigned*)(Ch + (size_t)(row + 8) * N + col) = packbf(v2, v3);
                *(unsigned*)(Cl + (size_t)(row + 8) * N + col) = packbf(bfres(v2), bfres(v3));
            } else {
                if (MODE == 2) {
                    float2 r0 = *(const float2*)(res + (size_t)row * N + col);
                    float2 r1 = *(const float2*)(res + (size_t)(row + 8) * N + col);
                    v0 += r0.x; v1 += r0.y; v2 += r1.x; v3 += r1.y;
                }
                *(float2*)(C + (size_t)row * N + col)       = make_float2(v0, v1);
                *(float2*)(C + (size_t)(row + 8) * N + col) = make_float2(v2, v3);
            }
        }
    }
}

// ============================================================================
// Flash attention, register softmax, split-bf16 mma.
// R12: 4 warps x 32 q-rows (register m-blocking) -> K/V fragment loads shared
// across 2 m-subtiles, halving LDS traffic. CTA = 128 threads.
// SMEM: KV buf0 0..18432 (Kh,Kl,Vh,Vl planes of 4608), buf1 ..36864,
//       Qh 36864..55296, Ql 55296..73728
// ============================================================================
#define ALD 144
#define APLANE 4608
#define AKVBUF 18432
#define AQH 36864
#define AQL 55296
#define ATTN_SMEM 73728

__global__ __launch_bounds__(128, 2) void fattn_kernel(
    const __nv_bfloat16* __restrict__ Qh, const __nv_bfloat16* __restrict__ Ql,
    const __nv_bfloat16* __restrict__ Kh, const __nv_bfloat16* __restrict__ Kl,
    const __nv_bfloat16* __restrict__ Vh, const __nv_bfloat16* __restrict__ Vl,
    float* __restrict__ O)
{
    extern __shared__ unsigned char smc[];
    const unsigned sbase = (unsigned)__cvta_generic_to_shared(smc);

    const int tid = threadIdx.x;
    const int w   = tid >> 5;          // 0..3, rows w*32..w*32+31
    const int lane = tid & 31;
    const int bh = blockIdx.y;
    const int qt = blockIdx.x;

    const int lj = lane >> 3, lr = lane & 7;
    const int rowoff = (lj & 1) * 8 + lr;
    const int coloff = (lj >> 1) * 8;

    const size_t qbase  = ((size_t)bh * S_ + qt * 128) * DH_;
    const size_t kvbase = (size_t)bh * S_ * DH_;

    // issue Q (both planes): 2048 16B chunks, 128 threads -> 16 each
    #pragma unroll
    for (int i = 0; i < 16; i++) {
        int chunk = i * 128 + tid;
        int plane = chunk >> 10;
        int rem = chunk & 1023;
        int row = rem >> 3;
        int c8 = (rem & 7) * 8;
        const __nv_bfloat16* src = (plane ? Ql : Qh) + qbase + (size_t)row * DH_ + c8;
        cpa16(sbase + (plane ? AQL : AQH) + row * ALD + c8 * 2, src);
    }
    // KV tile 0: 1024 chunks -> 8 each
    #pragma unroll
    for (int i = 0; i < 8; i++) {
        int chunk = i * 128 + tid;
        int plane = chunk >> 8;
        int rem = chunk & 255;
        int row = rem >> 3;
        int c8 = (rem & 7) * 8;
        const __nv_bfloat16* srcb =
            (plane == 0 ? Kh : plane == 1 ? Kl : plane == 2 ? Vh : Vl)
            + kvbase + (size_t)row * DH_ + c8;
        cpa16(sbase + plane * APLANE + row * ALD + c8 * 2, srcb);
    }
    cpa_commit();

    unsigned qfh[2][4][4], qfl[2][4][4];
    float oacc[2][8][4];
    #pragma unroll
    for (int mt = 0; mt < 2; mt++)
        #pragma unroll
        for (int t = 0; t < 8; t++) {
            oacc[mt][t][0] = 0.f; oacc[mt][t][1] = 0.f;
            oacc[mt][t][2] = 0.f; oacc[mt][t][3] = 0.f;
        }
    float lsum[2][2];
    lsum[0][0] = 0.f; lsum[0][1] = 0.f; lsum[1][0] = 0.f; lsum[1][1] = 0.f;

    const int NT = S_ / 32;
    for (int kt = 0; kt < NT; kt++) {
        cpa_wait0();
        __syncthreads();

        if (kt == 0) {
            #pragma unroll
            for (int mt = 0; mt < 2; mt++)
                #pragma unroll
                for (int ks = 0; ks < 4; ks++) {
                    unsigned qoff = (unsigned)((w * 32 + mt * 16 + rowoff) * ALD
                                               + (ks * 16 + coloff) * 2);
                    ldsm4(qfh[mt][ks], sbase + AQH + qoff);
                    ldsm4(qfl[mt][ks], sbase + AQL + qoff);
                }
        }

        const unsigned buf = sbase + (kt & 1) * AKVBUF;

        if (kt + 1 < NT) {
            const size_t tb = kvbase + (size_t)(kt + 1) * 32 * DH_;
            const unsigned dbuf = sbase + ((kt + 1) & 1) * AKVBUF;
            #pragma unroll
            for (int i = 0; i < 8; i++) {
                int chunk = i * 128 + tid;
                int plane = chunk >> 8;
                int rem = chunk & 255;
                int row = rem >> 3;
                int c8 = (rem & 7) * 8;
                const __nv_bfloat16* srcb =
                    (plane == 0 ? Kh : plane == 1 ? Kl : plane == 2 ? Vh : Vl)
                    + tb + (size_t)row * DH_ + c8;
                cpa16(dbuf + plane * APLANE + row * ALD + c8 * 2, srcb);
            }
            cpa_commit();
        }

        // ---- S = Q @ K^T (32 x 32 per warp, K frags shared by both mt) ----
        float sacc[2][4][4];
        #pragma unroll
        for (int mt = 0; mt < 2; mt++)
            #pragma unroll
            for (int nt = 0; nt < 4; nt++) {
                sacc[mt][nt][0] = 0.f; sacc[mt][nt][1] = 0.f;
                sacc[mt][nt][2] = 0.f; sacc[mt][nt][3] = 0.f;
            }
        #pragma unroll
        for (int ks = 0; ks < 4; ks++) {
            #pragma unroll
            for (int g2 = 0; g2 < 2; g2++) {
                unsigned kbh[4], kbl[4];
                unsigned off = buf + (unsigned)((g2 * 16 + rowoff) * ALD + (ks * 16 + coloff) * 2);
                ldsm4(kbh, off);
                ldsm4(kbl, off + APLANE);
                #pragma unroll
                for (int mt = 0; mt < 2; mt++) {
                    mma_bf16(sacc[mt][2 * g2],     qfh[mt][ks], kbh[0], kbh[2]);
                    mma_bf16(sacc[mt][2 * g2],     qfh[mt][ks], kbl[0], kbl[2]);
                    mma_bf16(sacc[mt][2 * g2],     qfl[mt][ks], kbh[0], kbh[2]);
                    mma_bf16(sacc[mt][2 * g2 + 1], qfh[mt][ks], kbh[1], kbh[3]);
                    mma_bf16(sacc[mt][2 * g2 + 1], qfh[mt][ks], kbl[1], kbl[3]);
                    mma_bf16(sacc[mt][2 * g2 + 1], qfl[mt][ks], kbh[1], kbh[3]);
                }
            }
        }

        // ---- exp in registers ----
        #pragma unroll
        for (int mt = 0; mt < 2; mt++)
            #pragma unroll
            for (int nt = 0; nt < 4; nt++) {
                sacc[mt][nt][0] = __expf(sacc[mt][nt][0]); lsum[mt][0] += sacc[mt][nt][0];
                sacc[mt][nt][1] = __expf(sacc[mt][nt][1]); lsum[mt][0] += sacc[mt][nt][1];
                sacc[mt][nt][2] = __expf(sacc[mt][nt][2]); lsum[mt][1] += sacc[mt][nt][2];
                sacc[mt][nt][3] = __expf(sacc[mt][nt][3]); lsum[mt][1] += sacc[mt][nt][3];
            }

        // ---- O += P @ V (V frags shared by both mt) ----
        #pragma unroll
        for (int ks2 = 0; ks2 < 2; ks2++) {
            unsigned aph[2][4], apl[2][4];
            #pragma unroll
            for (int mt = 0; mt < 2; mt++) {
                const float* t0 = sacc[mt][2 * ks2];
                const float* t1 = sacc[mt][2 * ks2 + 1];
                aph[mt][0] = packbf(t0[0], t0[1]); apl[mt][0] = packbf(bfres(t0[0]), bfres(t0[1]));
                aph[mt][1] = packbf(t0[2], t0[3]); apl[mt][1] = packbf(bfres(t0[2]), bfres(t0[3]));
                aph[mt][2] = packbf(t1[0], t1[1]); apl[mt][2] = packbf(bfres(t1[0]), bfres(t1[1]));
                aph[mt][3] = packbf(t1[2], t1[3]); apl[mt][3] = packbf(bfres(t1[2]), bfres(t1[3]));
            }
            #pragma unroll
            for (int gv = 0; gv < 4; gv++) {
                unsigned vbh[4], vbl[4];
                unsigned off = buf + 2 * APLANE
                             + (unsigned)((ks2 * 16 + rowoff) * ALD + (gv * 16 + coloff) * 2);
                ldsm4t(vbh, off);
                ldsm4t(vbl, off + APLANE);
                #pragma unroll
                for (int mt = 0; mt < 2; mt++) {
                    mma_bf16(oacc[mt][2 * gv],     aph[mt], vbh[0], vbh[1]);
                    mma_bf16(oacc[mt][2 * gv],     apl[mt], vbh[0], vbh[1]);
                    mma_bf16(oacc[mt][2 * gv],     aph[mt], vbl[0], vbl[1]);
                    mma_bf16(oacc[mt][2 * gv + 1], aph[mt], vbh[2], vbh[3]);
                    mma_bf16(oacc[mt][2 * gv + 1], apl[mt], vbh[2], vbh[3]);
                    mma_bf16(oacc[mt][2 * gv + 1], aph[mt], vbl[2], vbl[3]);
                }
            }
        }
    }

    // reduce row sums within quads, normalize, write out
    #pragma unroll
    for (int mt = 0; mt < 2; mt++) {
        lsum[mt][0] += __shfl_xor_sync(0xffffffffu, lsum[mt][0], 1);
        lsum[mt][0] += __shfl_xor_sync(0xffffffffu, lsum[mt][0], 2);
        lsum[mt][1] += __shfl_xor_sync(0xffffffffu, lsum[mt][1], 1);
        lsum[mt][1] += __shfl_xor_sync(0xffffffffu, lsum[mt][1], 2);
    }

    const int b = bh >> 4, h = bh & 15;
    const int g = lane >> 2, c2 = (lane & 3) * 2;
    #pragma unroll
    for (int mt = 0; mt < 2; mt++) {
        const float inv0 = 1.f / lsum[mt][0];
        const float inv1 = 1.f / lsum[mt][1];
        const int r0 = qt * 128 + w * 32 + mt * 16 + g;
        float* o0 = O + ((size_t)(b * S_) + r0) * D_ + h * DH_;
        float* o1 = o0 + (size_t)8 * D_;
        #pragma unroll
        for (int t = 0; t < 8; t++) {
            *(float2*)(o0 + t * 8 + c2) =
                make_float2(oacc[mt][t][0] * inv0, oacc[mt][t][1] * inv0);
            *(float2*)(o1 + t * 8 + c2) =
                make_float2(oacc[mt][t][2] * inv1, oacc[mt][t][3] * inv1);
        }
    }
}

// ---------------- QKV transform: l2norm + scale + xpos rotary ---------------
__global__ __launch_bounds__(256) void transform_kernel(
    const float* __restrict__ qkv,
    const float* __restrict__ q_scale, const float* __restrict__ k_scale,
    __nv_bfloat16* __restrict__ Qh, __nv_bfloat16* __restrict__ Ql,
    __nv_bfloat16* __restrict__ Kh, __nv_bfloat16* __restrict__ Kl,
    __nv_bfloat16* __restrict__ Vh, __nv_bfloat16* __restrict__ Vl)
{
    const int gw   = (blockIdx.x * blockDim.x + threadIdx.x) >> 5;
    const int lane = threadIdx.x & 31;
    const int s  = gw & (S_ - 1);
    const int bh = gw >> 11;
    if (bh >= BH_) return;
    const int b = bh >> 4, h = bh & 15;

    const float* base = qkv + ((size_t)(b * S_ + s)) * (3 * D_) + h * (3 * DH_);
    float q0 = base[lane],       q1 = base[lane + 32];
    float k0 = base[64 + lane],  k1 = base[96 + lane];
    float v0 = base[128 + lane], v1 = base[160 + lane];

    float nq = q0 * q0 + q1 * q1;
    float nk = k0 * k0 + k1 * k1;
    #pragma unroll
    for (int off = 16; off; off >>= 1) {
        nq += __shfl_xor_sync(0xffffffffu, nq, off);
        nk += __shfl_xor_sync(0xffffffffu, nk, off);
    }
    nq = fmaxf(sqrtf(nq), 1e-12f);
    nk = fmaxf(sqrtf(nk), 1e-12f);

    q0 = q0 / nq * q_scale[lane]; q1 = q1 / nq * q_scale[lane + 32];
    k0 = k0 / nk * k_scale[lane]; k1 = k1 / nk * k_scale[lane + 32];

    const float d2 = 2.0f * (float)lane;
    const float inv_freq = exp2f(-d2 * (13.287712379549449f / 64.0f));
    const float fr = (float)s * inv_freq;
    float sn, c;
    sincosf(fr, &sn, &c);

    const float basev = (d2 + 0.4f * 64.0f) / (1.4f * 64.0f);
    const float power = ((float)s - (float)(S_ / 2)) / 512.0f;
    const float scale = exp2f(power * log2f(basev));
    const float iscale = 1.0f / scale;

    const float qo0 = (q0 * c - q1 * sn) * scale * 0.125f;
    const float qo1 = (q1 * c + q0 * sn) * scale * 0.125f;
    const float ko0 = (k0 * c - k1 * sn) * iscale;
    const float ko1 = (k1 * c + k0 * sn) * iscale;

    const size_t ob = ((size_t)bh * S_ + s) * DH_;
    Qh[ob + lane]      = __float2bfloat16_rn(qo0);
    Ql[ob + lane]      = __float2bfloat16_rn(bfres(qo0));
    Qh[ob + lane + 32] = __float2bfloat16_rn(qo1);
    Ql[ob + lane + 32] = __float2bfloat16_rn(bfres(qo1));
    Kh[ob + lane]      = __float2bfloat16_rn(ko0);
    Kl[ob + lane]      = __float2bfloat16_rn(bfres(ko0));
    Kh[ob + lane + 32] = __float2bfloat16_rn(ko1);
    Kl[ob + lane + 32] = __float2bfloat16_rn(bfres(ko1));
    Vh[ob + lane]      = __float2bfloat16_rn(v0);
    Vl[ob + lane]      = __float2bfloat16_rn(bfres(v0));
    Vh[ob + lane + 32] = __float2bfloat16_rn(v1);
    Vl[ob + lane + 32] = __float2bfloat16_rn(bfres(v1));
}

// ---------------- LayerNorm (emits fp32 + hi/lo planes) ----------------------
__global__ __launch_bounds__(256) void ln_kernel(
    const float* __restrict__ X, const float* __restrict__ g,
    const float* __restrict__ bb, float* __restrict__ Y,
    __nv_bfloat16* __restrict__ Yh, __nv_bfloat16* __restrict__ Yl)
{
    __shared__ float red[16];
    const int row = blockIdx.x;
    const int tid = threadIdx.x;
    const float* xp = X + (size_t)row * D_;

    float4 x4 = ((const float4*)xp)[tid];
    float s  = x4.x + x4.y + x4.z + x4.w;
    float ss = x4.x * x4.x + x4.y * x4.y + x4.z * x4.z + x4.w * x4.w;

    #pragma unroll
    for (int off = 16; off; off >>= 1) {
        s  += __shfl_xor_sync(0xffffffffu, s,  off);
        ss += __shfl_xor_sync(0xffffffffu, ss, off);
    }
    const int wid = tid >> 5, lane = tid & 31;
    if (lane == 0) { red[wid] = s; red[wid + 8] = ss; }
    __syncthreads();
    if (wid == 0) {
        float a = (lane < 8) ? red[lane] : 0.f;
        float bsum = (lane < 8) ? red[lane + 8] : 0.f;
        #pragma unroll
        for (int off = 4; off; off >>= 1) {
            a    += __shfl_xor_sync(0xffffffffu, a,    off);
            bsum += __shfl_xor_sync(0xffffffffu, bsum, off);
        }
        if (lane == 0) { red[0] = a; red[1] = bsum; }
    }
    __syncthreads();
    const float mu  = red[0] * (1.0f / D_);
    const float var = red[1] * (1.0f / D_) - mu * mu;
    const float rstd = rsqrtf(var + 1e-5f);

    float4 g4 = ((const float4*)g)[tid];
    float4 b4 = ((const float4*)bb)[tid];
    float4 y;
    y.x = (x4.x - mu) * rstd * g4.x + b4.x;
    y.y = (x4.y - mu) * rstd * g4.y + b4.y;
    y.z = (x4.z - mu) * rstd * g4.z + b4.z;
    y.w = (x4.w - mu) * rstd * g4.w + b4.w;
    ((float4*)(Y + (size_t)row * D_))[tid] = y;
    ((uint2*)(Yh + (size_t)row * D_))[tid] =
        make_uint2(packbf(y.x, y.y), packbf(y.z, y.w));
    ((uint2*)(Yl + (size_t)row * D_))[tid] =
        make_uint2(packbf(bfres(y.x), bfres(y.y)), packbf(bfres(y.z), bfres(y.w)));
}

// ---------------- launch -----------------------------------------------------
extern "C" void kernel_launch(void* const* d_in, const int* in_sizes, int n_in,
                              void* d_out, int out_size)
{
    const float* Q     = (const float*)d_in[0];
    const float* Wqkv  = (const float*)d_in[3];
    const float* bqkv  = (const float*)d_in[4];
    const float* q_sc  = (const float*)d_in[5];
    const float* k_sc  = (const float*)d_in[6];
    const float* ln_g  = (const float*)d_in[7];
    const float* ln_b  = (const float*)d_in[8];
    const float* W1    = (const float*)d_in[9];
    const float* b1    = (const float*)d_in[10];
    const float* W2    = (const float*)d_in[11];
    const float* b2    = (const float*)d_in[12];
    float* out = (float*)d_out;

    float *qkv, *att, *x;
    __nv_bfloat16 *qih, *qil, *wqh, *wql, *w1h, *w1l, *w2h, *w2l;
    __nv_bfloat16 *qh, *ql, *kh, *kl, *vh, *vl, *xh, *xl, *hh, *hl;
    cudaGetSymbolAddress((void**)&qkv, g_qkv);
    cudaGetSymbolAddress((void**)&qih, g_qih);
    cudaGetSymbolAddress((void**)&qil, g_qil);
    cudaGetSymbolAddress((void**)&wqh, g_wqh);
    cudaGetSymbolAddress((void**)&wql, g_wql);
    cudaGetSymbolAddress((void**)&w1h, g_w1h);
    cudaGetSymbolAddress((void**)&w1l, g_w1l);
    cudaGetSymbolAddress((void**)&w2h, g_w2h);
    cudaGetSymbolAddress((void**)&w2l, g_w2l);
    cudaGetSymbolAddress((void**)&qh,  g_qh);
    cudaGetSymbolAddress((void**)&ql,  g_ql);
    cudaGetSymbolAddress((void**)&kh,  g_kh);
    cudaGetSymbolAddress((void**)&kl,  g_kl);
    cudaGetSymbolAddress((void**)&vh,  g_vh);
    cudaGetSymbolAddress((void**)&vl,  g_vl);
    cudaGetSymbolAddress((void**)&att, g_att);
    cudaGetSymbolAddress((void**)&x,   g_x);
    cudaGetSymbolAddress((void**)&xh,  g_xh);
    cudaGetSymbolAddress((void**)&xl,  g_xl);
    cudaGetSymbolAddress((void**)&hh,  g_hh);
    cudaGetSymbolAddress((void**)&hl,  g_hl);

    cudaFuncSetAttribute(fattn_kernel,
                         cudaFuncAttributeMaxDynamicSharedMemorySize, ATTN_SMEM);
    cudaFuncSetAttribute(mma_gemm<0>,
                         cudaFuncAttributeMaxDynamicSharedMemorySize, GEMM_SMEM);
    cudaFuncSetAttribute(mma_gemm<1>,
                         cudaFuncAttributeMaxDynamicSharedMemorySize, GEMM_SMEM);
    cudaFuncSetAttribute(mma_gemm<2>,
                         cudaFuncAttributeMaxDynamicSharedMemorySize, GEMM_SMEM);

    // 0) pre-split inputs and weights
    split_kernel<<<2048, 256>>>(Q, qih, qil, BS_ * D_ / 4);
    split_kernel<<<2048, 256>>>(Wqkv, wqh, wql, D_ * 3 * D_ / 4);
    split_kernel<<<2048, 256>>>(W1, w1h, w1l, D_ * FF_ / 4);
    split_kernel<<<2048, 256>>>(W2, w2h, w2l, FF_ * D_ / 4);

    // 1) QKV projection
    mma_gemm<0><<<dim3(3 * D_ / 128, BS_ / 128), 256, GEMM_SMEM>>>(
        qih, qil, wqh, wql, bqkv, nullptr, qkv, nullptr, nullptr,
        BS_, 3 * D_, D_);

    // 2) l2norm + scale + rotary -> split-bf16 planes
    transform_kernel<<<BH_ * S_ / 8, 256>>>(qkv, q_sc, k_sc,
                                            qh, ql, kh, kl, vh, vl);

    // 3) flash attention (4 warps x 32 q-rows, m-blocked)
    fattn_kernel<<<dim3(S_ / 128, BH_), 128, ATTN_SMEM>>>(
        qh, ql, kh, kl, vh, vl, att);

    // 4) LayerNorm -> x fp32 + hi/lo planes
    ln_kernel<<<BS_, 256>>>(att, ln_g, ln_b, x, xh, xl);

    // 5) FF1 + SiLU -> h hi/lo planes
    mma_gemm<1><<<dim3(FF_ / 128, BS_ / 128), 256, GEMM_SMEM>>>(
        xh, xl, w1h, w1l, b1, nullptr, nullptr, hh, hl,
        BS_, FF_, D_);

    // 6) FF2 + residual -> out fp32
    mma_gemm<2><<<dim3(D_ / 128, BS_ / 128), 256, GEMM_SMEM>>>(
        hh, hl, w2h, w2l, b2, x, out, nullptr, nullptr,
        BS_, D_, FF_);
}

// round 13
// speedup vs baseline: 3.7585x; 1.0079x over previous
#include <cuda_runtime.h>
#include <cuda_bf16.h>
#include <math.h>
#include <stdint.h>

#define B_   4
#define S_   2048
#define H_   16
#define DH_  64
#define D_   1024
#define FF_  2048
#define BS_  (B_*S_)
#define BH_  (B_*H_)

// ---------------- scratch (device globals; no runtime allocation) -----------
__device__ float g_qkv[(size_t)BS_ * 3 * D_];
__device__ __nv_bfloat16 g_qih[(size_t)BS_ * D_];
__device__ __nv_bfloat16 g_qil[(size_t)BS_ * D_];
__device__ __nv_bfloat16 g_wqh[(size_t)D_ * 3 * D_];
__device__ __nv_bfloat16 g_wql[(size_t)D_ * 3 * D_];
__device__ __nv_bfloat16 g_w1h[(size_t)D_ * FF_];
__device__ __nv_bfloat16 g_w1l[(size_t)D_ * FF_];
__device__ __nv_bfloat16 g_w2h[(size_t)FF_ * D_];
__device__ __nv_bfloat16 g_w2l[(size_t)FF_ * D_];
__device__ __nv_bfloat16 g_qh[(size_t)BH_ * S_ * DH_];
__device__ __nv_bfloat16 g_ql[(size_t)BH_ * S_ * DH_];
__device__ __nv_bfloat16 g_kh[(size_t)BH_ * S_ * DH_];
__device__ __nv_bfloat16 g_kl[(size_t)BH_ * S_ * DH_];
__device__ __nv_bfloat16 g_vh[(size_t)BH_ * S_ * DH_];
__device__ __nv_bfloat16 g_vl[(size_t)BH_ * S_ * DH_];
__device__ float g_att[(size_t)BS_ * D_];
__device__ float g_x  [(size_t)BS_ * D_];
__device__ __nv_bfloat16 g_xh[(size_t)BS_ * D_];
__device__ __nv_bfloat16 g_xl[(size_t)BS_ * D_];
__device__ __nv_bfloat16 g_hh[(size_t)BS_ * FF_];
__device__ __nv_bfloat16 g_hl[(size_t)BS_ * FF_];

// ---------------- split-bf16 helpers ----------------------------------------
__device__ __forceinline__ float bfres(float a) {
    return a - __bfloat162float(__float2bfloat16_rn(a));
}
__device__ __forceinline__ unsigned packbf(float a, float b) {
    __nv_bfloat162 t;
    t.x = __float2bfloat16_rn(a);
    t.y = __float2bfloat16_rn(b);
    return *reinterpret_cast<unsigned*>(&t);
}

// ---------------- PTX primitives ---------------------------------------------
__device__ __forceinline__ void ldsm4(unsigned* d, unsigned a) {
    asm volatile("ldmatrix.sync.aligned.m8n8.x4.shared.b16 {%0,%1,%2,%3}, [%4];"
                 : "=r"(d[0]), "=r"(d[1]), "=r"(d[2]), "=r"(d[3]) : "r"(a));
}
__device__ __forceinline__ void ldsm4t(unsigned* d, unsigned a) {
    asm volatile("ldmatrix.sync.aligned.m8n8.x4.trans.shared.b16 {%0,%1,%2,%3}, [%4];"
                 : "=r"(d[0]), "=r"(d[1]), "=r"(d[2]), "=r"(d[3]) : "r"(a));
}
__device__ __forceinline__ void mma_bf16(float* c, const unsigned* a,
                                         unsigned b0, unsigned b1) {
    asm volatile(
        "mma.sync.aligned.m16n8k16.row.col.f32.bf16.bf16.f32 "
        "{%0,%1,%2,%3}, {%4,%5,%6,%7}, {%8,%9}, {%0,%1,%2,%3};"
        : "+f"(c[0]), "+f"(c[1]), "+f"(c[2]), "+f"(c[3])
        : "r"(a[0]), "r"(a[1]), "r"(a[2]), "r"(a[3]), "r"(b0), "r"(b1));
}
__device__ __forceinline__ void cpa16(unsigned dst, const void* src) {
    asm volatile("cp.async.ca.shared.global [%0], [%1], 16;" :: "r"(dst), "l"(src));
}
__device__ __forceinline__ void cpa_commit() {
    asm volatile("cp.async.commit_group;");
}
__device__ __forceinline__ void cpa_wait0() {
    asm volatile("cp.async.wait_group 0;" ::: "memory");
}

// ============================================================================
// split_kernel: fp32 -> bf16 hi/lo planes
// ============================================================================
__global__ __launch_bounds__(256) void split_kernel(
    const float* __restrict__ X,
    __nv_bfloat16* __restrict__ Xh, __nv_bfloat16* __restrict__ Xl, int n4)
{
    const int stride = gridDim.x * blockDim.x;
    for (int i = blockIdx.x * blockDim.x + threadIdx.x; i < n4; i += stride) {
        float4 v = ((const float4*)X)[i];
        ((uint2*)Xh)[i] = make_uint2(packbf(v.x, v.y), packbf(v.z, v.w));
        ((uint2*)Xl)[i] = make_uint2(packbf(bfres(v.x), bfres(v.y)),
                                     packbf(bfres(v.z), bfres(v.w)));
    }
}

// ============================================================================
// Raw-mma split-bf16 GEMM (pre-split operands, cp.async double-buffer).
// R13: CTA 128x128, 4 warps (2m x 2n), warp tile 64x64 -> LDS redundancy
// drops from (2x A, 4x B) to (2x, 2x): 96KB -> 64KB per k-chunk.
// k-chunk 32, 1 sync/chunk. MODE 0: C fp32. 1: SiLU->Ch/Cl. 2: +res->C fp32.
// ============================================================================
#define GA_ 80
#define GB_ 272
#define GBUF 37888
#define GEMM_SMEM (2 * GBUF)

template <int MODE>
__global__ __launch_bounds__(128, 2) void mma_gemm(
    const __nv_bfloat16* __restrict__ Ah, const __nv_bfloat16* __restrict__ Al,
    const __nv_bfloat16* __restrict__ Bh, const __nv_bfloat16* __restrict__ Bl,
    const float* __restrict__ bias, const float* __restrict__ res,
    float* __restrict__ C,
    __nv_bfloat16* __restrict__ Ch, __nv_bfloat16* __restrict__ Cl,
    int M, int N, int K)
{
    extern __shared__ unsigned char smg[];
    const unsigned sb = (unsigned)__cvta_generic_to_shared(smg);

    const int tid = threadIdx.x;
    const int w = tid >> 5;
    const int lane = tid & 31;
    const int wmr = w >> 1;      // 2 m-warps: rows wmr*64..+64
    const int wnc = w & 1;       // 2 n-warps: cols wnc*64..+64
    const int bx = blockIdx.x, by = blockIdx.y;

    const int lj = lane >> 3, lr = lane & 7;
    const int rowoff = (lj & 1) * 8 + lr;
    const int coloff = (lj >> 1) * 8;
    const int g = lane >> 2, c2 = (lane & 3) * 2;

    float acc[4][8][4];
    #pragma unroll
    for (int mt = 0; mt < 4; mt++)
        #pragma unroll
        for (int n = 0; n < 8; n++) {
            acc[mt][n][0] = 0.f; acc[mt][n][1] = 0.f;
            acc[mt][n][2] = 0.f; acc[mt][n][3] = 0.f;
        }

    const int NC = K >> 5;

    // cp.async staging: 2048 16B-chunks per buffer, 16 per thread (128 thr)
    auto stage = [&](int kc, unsigned bufo) {
        const int k0 = kc * 32;
        #pragma unroll
        for (int i = 0; i < 16; i++) {
            int chunk = i * 128 + tid;
            if (chunk < 1024) {
                int plane = chunk >> 9;
                int rem = chunk & 511;
                int row = rem >> 2;
                int q = rem & 3;
                const __nv_bfloat16* src = (plane ? Al : Ah)
                    + (size_t)(by * 128 + row) * K + k0 + q * 8;
                cpa16(sb + bufo + plane * 10240u + row * GA_ + q * 16, src);
            } else {
                int c = chunk - 1024;
                int plane = c >> 9;
                int rem = c & 511;
                int row = rem >> 4;
                int o = rem & 15;
                const __nv_bfloat16* src = (plane ? Bl : Bh)
                    + (size_t)(k0 + row) * N + bx * 128 + o * 8;
                cpa16(sb + bufo + 20480u + plane * 8704u + row * GB_ + o * 16, src);
            }
        }
    };

    stage(0, 0u);
    cpa_commit();

    for (int kc = 0; kc < NC; kc++) {
        cpa_wait0();
        __syncthreads();

        const unsigned buf = (unsigned)((kc & 1) * GBUF);
        if (kc + 1 < NC) {
            stage(kc + 1, (unsigned)(((kc + 1) & 1) * GBUF));
            cpa_commit();
        }

        const unsigned uAh = sb + buf, uBh = sb + buf + 20480u;

        #pragma unroll
        for (int ks = 0; ks < 2; ks++) {
            unsigned ah[4][4], al[4][4];
            #pragma unroll
            for (int mt = 0; mt < 4; mt++) {
                const unsigned addr = uAh
                    + (unsigned)((wmr * 64 + mt * 16 + rowoff) * GA_ + (ks * 16 + coloff) * 2);
                ldsm4(ah[mt], addr);
                ldsm4(al[mt], addr + 10240u);
            }
            #pragma unroll
            for (int gg = 0; gg < 4; gg++) {
                unsigned bhf[4], blf[4];
                const unsigned baddr = uBh
                    + (unsigned)((ks * 16 + rowoff) * GB_ + (wnc * 64 + gg * 16 + coloff) * 2);
                ldsm4t(bhf, baddr);
                ldsm4t(blf, baddr + 8704u);
                #pragma unroll
                for (int mt = 0; mt < 4; mt++) {
                    mma_bf16(acc[mt][2 * gg],     ah[mt], bhf[0], bhf[1]);
                    mma_bf16(acc[mt][2 * gg],     ah[mt], blf[0], blf[1]);
                    mma_bf16(acc[mt][2 * gg],     al[mt], bhf[0], bhf[1]);
                    mma_bf16(acc[mt][2 * gg + 1], ah[mt], bhf[2], bhf[3]);
                    mma_bf16(acc[mt][2 * gg + 1], ah[mt], blf[2], blf[3]);
                    mma_bf16(acc[mt][2 * gg + 1], al[mt], bhf[2], bhf[3]);
                }
            }
        }
    }

    #pragma unroll
    for (int mt = 0; mt < 4; mt++) {
        #pragma unroll
        for (int n = 0; n < 8; n++) {
            const int row = by * 128 + wmr * 64 + mt * 16 + g;
            const int col = bx * 128 + wnc * 64 + n * 8 + c2;
            float2 bb2 = *(const float2*)(bias + col);
            float v0 = acc[mt][n][0] + bb2.x;
            float v1 = acc[mt][n][1] + bb2.y;
            float v2 = acc[mt][n][2] + bb2.x;
            float v3 = acc[mt][n][3] + bb2.y;
            if (MODE == 1) {
                v0 = v0 / (1.f + __expf(-v0));
                v1 = v1 / (1.f + __expf(-v1));
                v2 = v2 / (1.f + __expf(-v2));
                v3 = v3 / (1.f + __expf(-v3));
                *(unsigned*)(Ch + (size_t)row * N + col) = packbf(v0, v1);
                *(unsigned*)(Cl + (size_t)row * N + col) = packbf(bfres(v0), bfres(v1));
                *(unsigned*)(Ch + (size_t)(row + 8) * N + col) = packbf(v2, v3);
                *(unsigned*)(Cl + (size_t)(row + 8) * N + col) = packbf(bfres(v2), bfres(v3));
            } else {
                if (MODE == 2) {
                    float2 r0 = *(const float2*)(res + (size_t)row * N + col);
                    float2 r1 = *(const float2*)(res + (size_t)(row + 8) * N + col);
                    v0 += r0.x; v1 += r0.y; v2 += r1.x; v3 += r1.y;
                }
                *(float2*)(C + (size_t)row * N + col)       = make_float2(v0, v1);
                *(float2*)(C + (size_t)(row + 8) * N + col) = make_float2(v2, v3);
            }
        }
    }
}

// ============================================================================
// Flash attention, register softmax, split-bf16 mma (R12 shape: 4 warps x 32
// q-rows, K/V fragments shared across 2 m-subtiles).
// ============================================================================
#define ALD 144
#define APLANE 4608
#define AKVBUF 18432
#define AQH 36864
#define AQL 55296
#define ATTN_SMEM 73728

__global__ __launch_bounds__(128, 2) void fattn_kernel(
    const __nv_bfloat16* __restrict__ Qh, const __nv_bfloat16* __restrict__ Ql,
    const __nv_bfloat16* __restrict__ Kh, const __nv_bfloat16* __restrict__ Kl,
    const __nv_bfloat16* __restrict__ Vh, const __nv_bfloat16* __restrict__ Vl,
    float* __restrict__ O)
{
    extern __shared__ unsigned char smc[];
    const unsigned sbase = (unsigned)__cvta_generic_to_shared(smc);

    const int tid = threadIdx.x;
    const int w   = tid >> 5;
    const int lane = tid & 31;
    const int bh = blockIdx.y;
    const int qt = blockIdx.x;

    const int lj = lane >> 3, lr = lane & 7;
    const int rowoff = (lj & 1) * 8 + lr;
    const int coloff = (lj >> 1) * 8;

    const size_t qbase  = ((size_t)bh * S_ + qt * 128) * DH_;
    const size_t kvbase = (size_t)bh * S_ * DH_;

    #pragma unroll
    for (int i = 0; i < 16; i++) {
        int chunk = i * 128 + tid;
        int plane = chunk >> 10;
        int rem = chunk & 1023;
        int row = rem >> 3;
        int c8 = (rem & 7) * 8;
        const __nv_bfloat16* src = (plane ? Ql : Qh) + qbase + (size_t)row * DH_ + c8;
        cpa16(sbase + (plane ? AQL : AQH) + row * ALD + c8 * 2, src);
    }
    #pragma unroll
    for (int i = 0; i < 8; i++) {
        int chunk = i * 128 + tid;
        int plane = chunk >> 8;
        int rem = chunk & 255;
        int row = rem >> 3;
        int c8 = (rem & 7) * 8;
        const __nv_bfloat16* srcb =
            (plane == 0 ? Kh : plane == 1 ? Kl : plane == 2 ? Vh : Vl)
            + kvbase + (size_t)row * DH_ + c8;
        cpa16(sbase + plane * APLANE + row * ALD + c8 * 2, srcb);
    }
    cpa_commit();

    unsigned qfh[2][4][4], qfl[2][4][4];
    float oacc[2][8][4];
    #pragma unroll
    for (int mt = 0; mt < 2; mt++)
        #pragma unroll
        for (int t = 0; t < 8; t++) {
            oacc[mt][t][0] = 0.f; oacc[mt][t][1] = 0.f;
            oacc[mt][t][2] = 0.f; oacc[mt][t][3] = 0.f;
        }
    float lsum[2][2];
    lsum[0][0] = 0.f; lsum[0][1] = 0.f; lsum[1][0] = 0.f; lsum[1][1] = 0.f;

    const int NT = S_ / 32;
    for (int kt = 0; kt < NT; kt++) {
        cpa_wait0();
        __syncthreads();

        if (kt == 0) {
            #pragma unroll
            for (int mt = 0; mt < 2; mt++)
                #pragma unroll
                for (int ks = 0; ks < 4; ks++) {
                    unsigned qoff = (unsigned)((w * 32 + mt * 16 + rowoff) * ALD
                                               + (ks * 16 + coloff) * 2);
                    ldsm4(qfh[mt][ks], sbase + AQH + qoff);
                    ldsm4(qfl[mt][ks], sbase + AQL + qoff);
                }
        }

        const unsigned buf = sbase + (kt & 1) * AKVBUF;

        if (kt + 1 < NT) {
            const size_t tb = kvbase + (size_t)(kt + 1) * 32 * DH_;
            const unsigned dbuf = sbase + ((kt + 1) & 1) * AKVBUF;
            #pragma unroll
            for (int i = 0; i < 8; i++) {
                int chunk = i * 128 + tid;
                int plane = chunk >> 8;
                int rem = chunk & 255;
                int row = rem >> 3;
                int c8 = (rem & 7) * 8;
                const __nv_bfloat16* srcb =
                    (plane == 0 ? Kh : plane == 1 ? Kl : plane == 2 ? Vh : Vl)
                    + tb + (size_t)row * DH_ + c8;
                cpa16(dbuf + plane * APLANE + row * ALD + c8 * 2, srcb);
            }
            cpa_commit();
        }

        float sacc[2][4][4];
        #pragma unroll
        for (int mt = 0; mt < 2; mt++)
            #pragma unroll
            for (int nt = 0; nt < 4; nt++) {
                sacc[mt][nt][0] = 0.f; sacc[mt][nt][1] = 0.f;
                sacc[mt][nt][2] = 0.f; sacc[mt][nt][3] = 0.f;
            }
        #pragma unroll
        for (int ks = 0; ks < 4; ks++) {
            #pragma unroll
            for (int g2 = 0; g2 < 2; g2++) {
                unsigned kbh[4], kbl[4];
                unsigned off = buf + (unsigned)((g2 * 16 + rowoff) * ALD + (ks * 16 + coloff) * 2);
                ldsm4(kbh, off);
                ldsm4(kbl, off + APLANE);
                #pragma unroll
                for (int mt = 0; mt < 2; mt++) {
                    mma_bf16(sacc[mt][2 * g2],     qfh[mt][ks], kbh[0], kbh[2]);
                    mma_bf16(sacc[mt][2 * g2],     qfh[mt][ks], kbl[0], kbl[2]);
                    mma_bf16(sacc[mt][2 * g2],     qfl[mt][ks], kbh[0], kbh[2]);
                    mma_bf16(sacc[mt][2 * g2 + 1], qfh[mt][ks], kbh[1], kbh[3]);
                    mma_bf16(sacc[mt][2 * g2 + 1], qfh[mt][ks], kbl[1], kbl[3]);
                    mma_bf16(sacc[mt][2 * g2 + 1], qfl[mt][ks], kbh[1], kbh[3]);
                }
            }
        }

        #pragma unroll
        for (int mt = 0; mt < 2; mt++)
            #pragma unroll
            for (int nt = 0; nt < 4; nt++) {
                sacc[mt][nt][0] = __expf(sacc[mt][nt][0]); lsum[mt][0] += sacc[mt][nt][0];
                sacc[mt][nt][1] = __expf(sacc[mt][nt][1]); lsum[mt][0] += sacc[mt][nt][1];
                sacc[mt][nt][2] = __expf(sacc[mt][nt][2]); lsum[mt][1] += sacc[mt][nt][2];
                sacc[mt][nt][3] = __expf(sacc[mt][nt][3]); lsum[mt][1] += sacc[mt][nt][3];
            }

        #pragma unroll
        for (int ks2 = 0; ks2 < 2; ks2++) {
            unsigned aph[2][4], apl[2][4];
            #pragma unroll
            for (int mt = 0; mt < 2; mt++) {
                const float* t0 = sacc[mt][2 * ks2];
                const float* t1 = sacc[mt][2 * ks2 + 1];
                aph[mt][0] = packbf(t0[0], t0[1]); apl[mt][0] = packbf(bfres(t0[0]), bfres(t0[1]));
                aph[mt][1] = packbf(t0[2], t0[3]); apl[mt][1] = packbf(bfres(t0[2]), bfres(t0[3]));
                aph[mt][2] = packbf(t1[0], t1[1]); apl[mt][2] = packbf(bfres(t1[0]), bfres(t1[1]));
                aph[mt][3] = packbf(t1[2], t1[3]); apl[mt][3] = packbf(bfres(t1[2]), bfres(t1[3]));
            }
            #pragma unroll
            for (int gv = 0; gv < 4; gv++) {
                unsigned vbh[4], vbl[4];
                unsigned off = buf + 2 * APLANE
                             + (unsigned)((ks2 * 16 + rowoff) * ALD + (gv * 16 + coloff) * 2);
                ldsm4t(vbh, off);
                ldsm4t(vbl, off + APLANE);
                #pragma unroll
                for (int mt = 0; mt < 2; mt++) {
                    mma_bf16(oacc[mt][2 * gv],     aph[mt], vbh[0], vbh[1]);
                    mma_bf16(oacc[mt][2 * gv],     apl[mt], vbh[0], vbh[1]);
                    mma_bf16(oacc[mt][2 * gv],     aph[mt], vbl[0], vbl[1]);
                    mma_bf16(oacc[mt][2 * gv + 1], aph[mt], vbh[2], vbh[3]);
                    mma_bf16(oacc[mt][2 * gv + 1], apl[mt], vbh[2], vbh[3]);
                    mma_bf16(oacc[mt][2 * gv + 1], aph[mt], vbl[2], vbl[3]);
                }
            }
        }
    }

    #pragma unroll
    for (int mt = 0; mt < 2; mt++) {
        lsum[mt][0] += __shfl_xor_sync(0xffffffffu, lsum[mt][0], 1);
        lsum[mt][0] += __shfl_xor_sync(0xffffffffu, lsum[mt][0], 2);
        lsum[mt][1] += __shfl_xor_sync(0xffffffffu, lsum[mt][1], 1);
        lsum[mt][1] += __shfl_xor_sync(0xffffffffu, lsum[mt][1], 2);
    }

    const int b = bh >> 4, h = bh & 15;
    const int g = lane >> 2, c2 = (lane & 3) * 2;
    #pragma unroll
    for (int mt = 0; mt < 2; mt++) {
        const float inv0 = 1.f / lsum[mt][0];
        const float inv1 = 1.f / lsum[mt][1];
        const int r0 = qt * 128 + w * 32 + mt * 16 + g;
        float* o0 = O + ((size_t)(b * S_) + r0) * D_ + h * DH_;
        float* o1 = o0 + (size_t)8 * D_;
        #pragma unroll
        for (int t = 0; t < 8; t++) {
            *(float2*)(o0 + t * 8 + c2) =
                make_float2(oacc[mt][t][0] * inv0, oacc[mt][t][1] * inv0);
            *(float2*)(o1 + t * 8 + c2) =
                make_float2(oacc[mt][t][2] * inv1, oacc[mt][t][3] * inv1);
        }
    }
}

// ---------------- QKV transform: l2norm + scale + xpos rotary ---------------
__global__ __launch_bounds__(256) void transform_kernel(
    const float* __restrict__ qkv,
    const float* __restrict__ q_scale, const float* __restrict__ k_scale,
    __nv_bfloat16* __restrict__ Qh, __nv_bfloat16* __restrict__ Ql,
    __nv_bfloat16* __restrict__ Kh, __nv_bfloat16* __restrict__ Kl,
    __nv_bfloat16* __restrict__ Vh, __nv_bfloat16* __restrict__ Vl)
{
    const int gw   = (blockIdx.x * blockDim.x + threadIdx.x) >> 5;
    const int lane = threadIdx.x & 31;
    const int s  = gw & (S_ - 1);
    const int bh = gw >> 11;
    if (bh >= BH_) return;
    const int b = bh >> 4, h = bh & 15;

    const float* base = qkv + ((size_t)(b * S_ + s)) * (3 * D_) + h * (3 * DH_);
    float q0 = base[lane],       q1 = base[lane + 32];
    float k0 = base[64 + lane],  k1 = base[96 + lane];
    float v0 = base[128 + lane], v1 = base[160 + lane];

    float nq = q0 * q0 + q1 * q1;
    float nk = k0 * k0 + k1 * k1;
    #pragma unroll
    for (int off = 16; off; off >>= 1) {
        nq += __shfl_xor_sync(0xffffffffu, nq, off);
        nk += __shfl_xor_sync(0xffffffffu, nk, off);
    }
    nq = fmaxf(sqrtf(nq), 1e-12f);
    nk = fmaxf(sqrtf(nk), 1e-12f);

    q0 = q0 / nq * q_scale[lane]; q1 = q1 / nq * q_scale[lane + 32];
    k0 = k0 / nk * k_scale[lane]; k1 = k1 / nk * k_scale[lane + 32];

    const float d2 = 2.0f * (float)lane;
    const float inv_freq = exp2f(-d2 * (13.287712379549449f / 64.0f));
    const float fr = (float)s * inv_freq;
    float sn, c;
    sincosf(fr, &sn, &c);

    const float basev = (d2 + 0.4f * 64.0f) / (1.4f * 64.0f);
    const float power = ((float)s - (float)(S_ / 2)) / 512.0f;
    const float scale = exp2f(power * log2f(basev));
    const float iscale = 1.0f / scale;

    const float qo0 = (q0 * c - q1 * sn) * scale * 0.125f;
    const float qo1 = (q1 * c + q0 * sn) * scale * 0.125f;
    const float ko0 = (k0 * c - k1 * sn) * iscale;
    const float ko1 = (k1 * c + k0 * sn) * iscale;

    const size_t ob = ((size_t)bh * S_ + s) * DH_;
    Qh[ob + lane]      = __float2bfloat16_rn(qo0);
    Ql[ob + lane]      = __float2bfloat16_rn(bfres(qo0));
    Qh[ob + lane + 32] = __float2bfloat16_rn(qo1);
    Ql[ob + lane + 32] = __float2bfloat16_rn(bfres(qo1));
    Kh[ob + lane]      = __float2bfloat16_rn(ko0);
    Kl[ob + lane]      = __float2bfloat16_rn(bfres(ko0));
    Kh[ob + lane + 32] = __float2bfloat16_rn(ko1);
    Kl[ob + lane + 32] = __float2bfloat16_rn(bfres(ko1));
    Vh[ob + lane]      = __float2bfloat16_rn(v0);
    Vl[ob + lane]      = __float2bfloat16_rn(bfres(v0));
    Vh[ob + lane + 32] = __float2bfloat16_rn(v1);
    Vl[ob + lane + 32] = __float2bfloat16_rn(bfres(v1));
}

// ---------------- LayerNorm (emits fp32 + hi/lo planes) ----------------------
__global__ __launch_bounds__(256) void ln_kernel(
    const float* __restrict__ X, const float* __restrict__ g,
    const float* __restrict__ bb, float* __restrict__ Y,
    __nv_bfloat16* __restrict__ Yh, __nv_bfloat16* __restrict__ Yl)
{
    __shared__ float red[16];
    const int row = blockIdx.x;
    const int tid = threadIdx.x;
    const float* xp = X + (size_t)row * D_;

    float4 x4 = ((const float4*)xp)[tid];
    float s  = x4.x + x4.y + x4.z + x4.w;
    float ss = x4.x * x4.x + x4.y * x4.y + x4.z * x4.z + x4.w * x4.w;

    #pragma unroll
    for (int off = 16; off; off >>= 1) {
        s  += __shfl_xor_sync(0xffffffffu, s,  off);
        ss += __shfl_xor_sync(0xffffffffu, ss, off);
    }
    const int wid = tid >> 5, lane = tid & 31;
    if (lane == 0) { red[wid] = s; red[wid + 8] = ss; }
    __syncthreads();
    if (wid == 0) {
        float a = (lane < 8) ? red[lane] : 0.f;
        float bsum = (lane < 8) ? red[lane + 8] : 0.f;
        #pragma unroll
        for (int off = 4; off; off >>= 1) {
            a    += __shfl_xor_sync(0xffffffffu, a,    off);
            bsum += __shfl_xor_sync(0xffffffffu, bsum, off);
        }
        if (lane == 0) { red[0] = a; red[1] = bsum; }
    }
    __syncthreads();
    const float mu  = red[0] * (1.0f / D_);
    const float var = red[1] * (1.0f / D_) - mu * mu;
    const float rstd = rsqrtf(var + 1e-5f);

    float4 g4 = ((const float4*)g)[tid];
    float4 b4 = ((const float4*)bb)[tid];
    float4 y;
    y.x = (x4.x - mu) * rstd * g4.x + b4.x;
    y.y = (x4.y - mu) * rstd * g4.y + b4.y;
    y.z = (x4.z - mu) * rstd * g4.z + b4.z;
    y.w = (x4.w - mu) * rstd * g4.w + b4.w;
    ((float4*)(Y + (size_t)row * D_))[tid] = y;
    ((uint2*)(Yh + (size_t)row * D_))[tid] =
        make_uint2(packbf(y.x, y.y), packbf(y.z, y.w));
    ((uint2*)(Yl + (size_t)row * D_))[tid] =
        make_uint2(packbf(bfres(y.x), bfres(y.y)), packbf(bfres(y.z), bfres(y.w)));
}

// ---------------- launch -----------------------------------------------------
extern "C" void kernel_launch(void* const* d_in, const int* in_sizes, int n_in,
                              void* d_out, int out_size)
{
    const float* Q     = (const float*)d_in[0];
    const float* Wqkv  = (const float*)d_in[3];
    const float* bqkv  = (const float*)d_in[4];
    const float* q_sc  = (const float*)d_in[5];
    const float* k_sc  = (const float*)d_in[6];
    const float* ln_g  = (const float*)d_in[7];
    const float* ln_b  = (const float*)d_in[8];
    const float* W1    = (const float*)d_in[9];
    const float* b1    = (const float*)d_in[10];
    const float* W2    = (const float*)d_in[11];
    const float* b2    = (const float*)d_in[12];
    float* out = (float*)d_out;

    float *qkv, *att, *x;
    __nv_bfloat16 *qih, *qil, *wqh, *wql, *w1h, *w1l, *w2h, *w2l;
    __nv_bfloat16 *qh, *ql, *kh, *kl, *vh, *vl, *xh, *xl, *hh, *hl;
    cudaGetSymbolAddress((void**)&qkv, g_qkv);
    cudaGetSymbolAddress((void**)&qih, g_qih);
    cudaGetSymbolAddress((void**)&qil, g_qil);
    cudaGetSymbolAddress((void**)&wqh, g_wqh);
    cudaGetSymbolAddress((void**)&wql, g_wql);
    cudaGetSymbolAddress((void**)&w1h, g_w1h);
    cudaGetSymbolAddress((void**)&w1l, g_w1l);
    cudaGetSymbolAddress((void**)&w2h, g_w2h);
    cudaGetSymbolAddress((void**)&w2l, g_w2l);
    cudaGetSymbolAddress((void**)&qh,  g_qh);
    cudaGetSymbolAddress((void**)&ql,  g_ql);
    cudaGetSymbolAddress((void**)&kh,  g_kh);
    cudaGetSymbolAddress((void**)&kl,  g_kl);
    cudaGetSymbolAddress((void**)&vh,  g_vh);
    cudaGetSymbolAddress((void**)&vl,  g_vl);
    cudaGetSymbolAddress((void**)&att, g_att);
    cudaGetSymbolAddress((void**)&x,   g_x);
    cudaGetSymbolAddress((void**)&xh,  g_xh);
    cudaGetSymbolAddress((void**)&xl,  g_xl);
    cudaGetSymbolAddress((void**)&hh,  g_hh);
    cudaGetSymbolAddress((void**)&hl,  g_hl);

    cudaFuncSetAttribute(fattn_kernel,
                         cudaFuncAttributeMaxDynamicSharedMemorySize, ATTN_SMEM);
    cudaFuncSetAttribute(mma_gemm<0>,
                         cudaFuncAttributeMaxDynamicSharedMemorySize, GEMM_SMEM);
    cudaFuncSetAttribute(mma_gemm<1>,
                         cudaFuncAttributeMaxDynamicSharedMemorySize, GEMM_SMEM);
    cudaFuncSetAttribute(mma_gemm<2>,
                         cudaFuncAttributeMaxDynamicSharedMemorySize, GEMM_SMEM);

    // 0) pre-split inputs and weights
    split_kernel<<<2048, 256>>>(Q, qih, qil, BS_ * D_ / 4);
    split_kernel<<<2048, 256>>>(Wqkv, wqh, wql, D_ * 3 * D_ / 4);
    split_kernel<<<2048, 256>>>(W1, w1h, w1l, D_ * FF_ / 4);
    split_kernel<<<2048, 256>>>(W2, w2h, w2l, FF_ * D_ / 4);

    // 1) QKV projection
    mma_gemm<0><<<dim3(3 * D_ / 128, BS_ / 128), 128, GEMM_SMEM>>>(
        qih, qil, wqh, wql, bqkv, nullptr, qkv, nullptr, nullptr,
        BS_, 3 * D_, D_);

    // 2) l2norm + scale + rotary -> split-bf16 planes
    transform_kernel<<<BH_ * S_ / 8, 256>>>(qkv, q_sc, k_sc,
                                            qh, ql, kh, kl, vh, vl);

    // 3) flash attention
    fattn_kernel<<<dim3(S_ / 128, BH_), 128, ATTN_SMEM>>>(
        qh, ql, kh, kl, vh, vl, att);

    // 4) LayerNorm -> x fp32 + hi/lo planes
    ln_kernel<<<BS_, 256>>>(att, ln_g, ln_b, x, xh, xl);

    // 5) FF1 + SiLU -> h hi/lo planes
    mma_gemm<1><<<dim3(FF_ / 128, BS_ / 128), 128, GEMM_SMEM>>>(
        xh, xl, w1h, w1l, b1, nullptr, nullptr, hh, hl,
        BS_, FF_, D_);

    // 6) FF2 + residual -> out fp32
    mma_gemm<2><<<dim3(D_ / 128, BS_ / 128), 128, GEMM_SMEM>>>(
        hh, hl, w2h, w2l, b2, x, out, nullptr, nullptr,
        BS_, D_, FF_);
}

// round 15
// speedup vs baseline: 8.7577x; 2.3301x over previous
#include <cuda_runtime.h>
#include <cuda_bf16.h>
#include <cuda_fp16.h>
#include <math.h>
#include <stdint.h>

#define B_   4
#define S_   2048
#define H_   16
#define DH_  64
#define D_   1024
#define FF_  2048
#define BS_  (B_*S_)
#define BH_  (B_*H_)

// ---------------- scratch (device globals; no runtime allocation) -----------
__device__ float  g_qkv[(size_t)BS_ * 3 * D_];
__device__ __half g_qi [(size_t)BS_ * D_];        // fp16 input Q
__device__ __half g_wq [(size_t)D_ * 3 * D_];     // fp16 Wqkv [K][N]
__device__ __half g_w1 [(size_t)D_ * FF_];
__device__ __half g_w2 [(size_t)FF_ * D_];
__device__ __half g_qf [(size_t)BH_ * S_ * DH_];  // transformed q/k/v fp16
__device__ __half g_kf [(size_t)BH_ * S_ * DH_];
__device__ __half g_vf [(size_t)BH_ * S_ * DH_];
__device__ float  g_att[(size_t)BS_ * D_];
__device__ float  g_x  [(size_t)BS_ * D_];
__device__ __half g_xh [(size_t)BS_ * D_];        // LN output fp16
__device__ __half g_hh [(size_t)BS_ * FF_];       // FF hidden fp16

// ---------------- helpers ------------------------------------------------------
__device__ __forceinline__ unsigned packhf(float a, float b) {
    __half2 t = __floats2half2_rn(a, b);
    return *reinterpret_cast<unsigned*>(&t);
}

// ---------------- PTX primitives ---------------------------------------------
__device__ __forceinline__ void ldsm4(unsigned* d, unsigned a) {
    asm volatile("ldmatrix.sync.aligned.m8n8.x4.shared.b16 {%0,%1,%2,%3}, [%4];"
                 : "=r"(d[0]), "=r"(d[1]), "=r"(d[2]), "=r"(d[3]) : "r"(a));
}
__device__ __forceinline__ void ldsm4t(unsigned* d, unsigned a) {
    asm volatile("ldmatrix.sync.aligned.m8n8.x4.trans.shared.b16 {%0,%1,%2,%3}, [%4];"
                 : "=r"(d[0]), "=r"(d[1]), "=r"(d[2]), "=r"(d[3]) : "r"(a));
}
__device__ __forceinline__ void mma_f16(float* c, const unsigned* a,
                                        unsigned b0, unsigned b1) {
    asm volatile(
        "mma.sync.aligned.m16n8k16.row.col.f32.f16.f16.f32 "
        "{%0,%1,%2,%3}, {%4,%5,%6,%7}, {%8,%9}, {%0,%1,%2,%3};"
        : "+f"(c[0]), "+f"(c[1]), "+f"(c[2]), "+f"(c[3])
        : "r"(a[0]), "r"(a[1]), "r"(a[2]), "r"(a[3]), "r"(b0), "r"(b1));
}
__device__ __forceinline__ void cpa16(unsigned dst, const void* src) {
    asm volatile("cp.async.ca.shared.global [%0], [%1], 16;" :: "r"(dst), "l"(src));
}
__device__ __forceinline__ void cpa_commit() {
    asm volatile("cp.async.commit_group;");
}
__device__ __forceinline__ void cpa_wait0() {
    asm volatile("cp.async.wait_group 0;" ::: "memory");
}

// ============================================================================
// hsplit_kernel: fp32 -> fp16 plane
// ============================================================================
__global__ __launch_bounds__(256) void hsplit_kernel(
    const float* __restrict__ X, __half* __restrict__ Xh, int n4)
{
    const int stride = gridDim.x * blockDim.x;
    for (int i = blockIdx.x * blockDim.x + threadIdx.x; i < n4; i += stride) {
        float4 v = ((const float4*)X)[i];
        ((uint2*)Xh)[i] = make_uint2(packhf(v.x, v.y), packhf(v.z, v.w));
    }
}

// ============================================================================
// Raw-mma fp16 GEMM (single pass), cp.async double-buffer, R13 tile shape:
// CTA 128x128, 4 warps (2m x 2n), warp tile 64x64, k-chunk 32, 1 sync/chunk.
// MODE 0: C fp32.  MODE 1: SiLU -> Ch fp16.  MODE 2: +res -> C fp32.
// Buffer: A[128][40] 10240 B | B[32][136] 8704 B  => 18944 per buffer.
// ============================================================================
#define GA_ 80
#define GB_ 272
#define GBUF 18944
#define GEMM_SMEM (2 * GBUF)

template <int MODE>
__global__ __launch_bounds__(128, 2) void mma_gemm(
    const __half* __restrict__ Ah, const __half* __restrict__ Bh,
    const float* __restrict__ bias, const float* __restrict__ res,
    float* __restrict__ C, __half* __restrict__ Ch,
    int M, int N, int K)
{
    extern __shared__ unsigned char smg[];
    const unsigned sb = (unsigned)__cvta_generic_to_shared(smg);

    const int tid = threadIdx.x;
    const int w = tid >> 5;
    const int lane = tid & 31;
    const int wmr = w >> 1;      // 2 m-warps: rows wmr*64..+64
    const int wnc = w & 1;       // 2 n-warps: cols wnc*64..+64
    const int bx = blockIdx.x, by = blockIdx.y;

    const int lj = lane >> 3, lr = lane & 7;
    const int rowoff = (lj & 1) * 8 + lr;
    const int coloff = (lj >> 1) * 8;
    const int g = lane >> 2, c2 = (lane & 3) * 2;

    float acc[4][8][4];
    #pragma unroll
    for (int mt = 0; mt < 4; mt++)
        #pragma unroll
        for (int n = 0; n < 8; n++) {
            acc[mt][n][0] = 0.f; acc[mt][n][1] = 0.f;
            acc[mt][n][2] = 0.f; acc[mt][n][3] = 0.f;
        }

    const int NC = K >> 5;

    // staging: 1024 16B-chunks per buffer, 8 per thread (128 thr)
    auto stage = [&](int kc, unsigned bufo) {
        const int k0 = kc * 32;
        #pragma unroll
        for (int i = 0; i < 8; i++) {
            int chunk = i * 128 + tid;
            if (chunk < 512) {
                int row = chunk >> 2;
                int q = chunk & 3;
                const __half* src = Ah + (size_t)(by * 128 + row) * K + k0 + q * 8;
                cpa16(sb + bufo + row * GA_ + q * 16, src);
            } else {
                int c = chunk - 512;
                int row = c >> 4;
                int o = c & 15;
                const __half* src = Bh + (size_t)(k0 + row) * N + bx * 128 + o * 8;
                cpa16(sb + bufo + 10240u + row * GB_ + o * 16, src);
            }
        }
    };

    stage(0, 0u);
    cpa_commit();

    for (int kc = 0; kc < NC; kc++) {
        cpa_wait0();
        __syncthreads();

        const unsigned buf = (unsigned)((kc & 1) * GBUF);
        if (kc + 1 < NC) {
            stage(kc + 1, (unsigned)(((kc + 1) & 1) * GBUF));
            cpa_commit();
        }

        const unsigned uA = sb + buf, uB = sb + buf + 10240u;

        #pragma unroll
        for (int ks = 0; ks < 2; ks++) {
            unsigned ah[4][4];
            #pragma unroll
            for (int mt = 0; mt < 4; mt++) {
                const unsigned addr = uA
                    + (unsigned)((wmr * 64 + mt * 16 + rowoff) * GA_ + (ks * 16 + coloff) * 2);
                ldsm4(ah[mt], addr);
            }
            #pragma unroll
            for (int gg = 0; gg < 4; gg++) {
                unsigned bf[4];
                const unsigned baddr = uB
                    + (unsigned)((ks * 16 + rowoff) * GB_ + (wnc * 64 + gg * 16 + coloff) * 2);
                ldsm4t(bf, baddr);
                #pragma unroll
                for (int mt = 0; mt < 4; mt++) {
                    mma_f16(acc[mt][2 * gg],     ah[mt], bf[0], bf[1]);
                    mma_f16(acc[mt][2 * gg + 1], ah[mt], bf[2], bf[3]);
                }
            }
        }
    }

    #pragma unroll
    for (int mt = 0; mt < 4; mt++) {
        #pragma unroll
        for (int n = 0; n < 8; n++) {
            const int row = by * 128 + wmr * 64 + mt * 16 + g;
            const int col = bx * 128 + wnc * 64 + n * 8 + c2;
            float2 bb2 = *(const float2*)(bias + col);
            float v0 = acc[mt][n][0] + bb2.x;
            float v1 = acc[mt][n][1] + bb2.y;
            float v2 = acc[mt][n][2] + bb2.x;
            float v3 = acc[mt][n][3] + bb2.y;
            if (MODE == 1) {
                v0 = v0 / (1.f + __expf(-v0));
                v1 = v1 / (1.f + __expf(-v1));
                v2 = v2 / (1.f + __expf(-v2));
                v3 = v3 / (1.f + __expf(-v3));
                *(unsigned*)(Ch + (size_t)row * N + col)       = packhf(v0, v1);
                *(unsigned*)(Ch + (size_t)(row + 8) * N + col) = packhf(v2, v3);
            } else {
                if (MODE == 2) {
                    float2 r0 = *(const float2*)(res + (size_t)row * N + col);
                    float2 r1 = *(const float2*)(res + (size_t)(row + 8) * N + col);
                    v0 += r0.x; v1 += r0.y; v2 += r1.x; v3 += r1.y;
                }
                *(float2*)(C + (size_t)row * N + col)       = make_float2(v0, v1);
                *(float2*)(C + (size_t)(row + 8) * N + col) = make_float2(v2, v3);
            }
        }
    }
}

// ============================================================================
// Flash attention, register softmax, fp16 single-pass mma.
// 4 warps x 32 q-rows (m-blocked), key tile 32, cp.async double-buffer.
// SMEM: KV buf0 @0 (K 4608 | V 4608), buf1 @9216, Q @18432..36864
// ============================================================================
#define ALD 144
#define APLANE 4608
#define AKVBUF 9216
#define AQ 18432
#define ATTN_SMEM 36864

__global__ __launch_bounds__(128, 2) void fattn_kernel(
    const __half* __restrict__ Qf, const __half* __restrict__ Kf,
    const __half* __restrict__ Vf, float* __restrict__ O)
{
    extern __shared__ unsigned char smc[];
    const unsigned sbase = (unsigned)__cvta_generic_to_shared(smc);

    const int tid = threadIdx.x;
    const int w   = tid >> 5;
    const int lane = tid & 31;
    const int bh = blockIdx.y;
    const int qt = blockIdx.x;

    const int lj = lane >> 3, lr = lane & 7;
    const int rowoff = (lj & 1) * 8 + lr;
    const int coloff = (lj >> 1) * 8;

    const size_t qbase  = ((size_t)bh * S_ + qt * 128) * DH_;
    const size_t kvbase = (size_t)bh * S_ * DH_;

    // issue Q: 1024 16B chunks -> 8 per thread
    #pragma unroll
    for (int i = 0; i < 8; i++) {
        int chunk = i * 128 + tid;
        int row = chunk >> 3;
        int c8 = (chunk & 7) * 8;
        const __half* src = Qf + qbase + (size_t)row * DH_ + c8;
        cpa16(sbase + AQ + row * ALD + c8 * 2, src);
    }
    // KV tile 0: 512 chunks -> 4 per thread
    #pragma unroll
    for (int i = 0; i < 4; i++) {
        int chunk = i * 128 + tid;
        int plane = chunk >> 8;       // 0:K 1:V
        int rem = chunk & 255;
        int row = rem >> 3;
        int c8 = (rem & 7) * 8;
        const __half* src = (plane ? Vf : Kf) + kvbase + (size_t)row * DH_ + c8;
        cpa16(sbase + plane * APLANE + row * ALD + c8 * 2, src);
    }
    cpa_commit();

    unsigned qf[2][4][4];
    float oacc[2][8][4];
    #pragma unroll
    for (int mt = 0; mt < 2; mt++)
        #pragma unroll
        for (int t = 0; t < 8; t++) {
            oacc[mt][t][0] = 0.f; oacc[mt][t][1] = 0.f;
            oacc[mt][t][2] = 0.f; oacc[mt][t][3] = 0.f;
        }
    float lsum[2][2];
    lsum[0][0] = 0.f; lsum[0][1] = 0.f; lsum[1][0] = 0.f; lsum[1][1] = 0.f;

    const int NT = S_ / 32;
    for (int kt = 0; kt < NT; kt++) {
        cpa_wait0();
        __syncthreads();

        if (kt == 0) {
            #pragma unroll
            for (int mt = 0; mt < 2; mt++)
                #pragma unroll
                for (int ks = 0; ks < 4; ks++) {
                    unsigned qoff = (unsigned)((w * 32 + mt * 16 + rowoff) * ALD
                                               + (ks * 16 + coloff) * 2);
                    ldsm4(qf[mt][ks], sbase + AQ + qoff);
                }
        }

        const unsigned buf = sbase + (kt & 1) * AKVBUF;

        if (kt + 1 < NT) {
            const size_t tb = kvbase + (size_t)(kt + 1) * 32 * DH_;
            const unsigned dbuf = sbase + ((kt + 1) & 1) * AKVBUF;
            #pragma unroll
            for (int i = 0; i < 4; i++) {
                int chunk = i * 128 + tid;
                int plane = chunk >> 8;
                int rem = chunk & 255;
                int row = rem >> 3;
                int c8 = (rem & 7) * 8;
                const __half* src = (plane ? Vf : Kf) + tb + (size_t)row * DH_ + c8;
                cpa16(dbuf + plane * APLANE + row * ALD + c8 * 2, src);
            }
            cpa_commit();
        }

        // ---- S = Q @ K^T (32x32 per warp) ----
        float sacc[2][4][4];
        #pragma unroll
        for (int mt = 0; mt < 2; mt++)
            #pragma unroll
            for (int nt = 0; nt < 4; nt++) {
                sacc[mt][nt][0] = 0.f; sacc[mt][nt][1] = 0.f;
                sacc[mt][nt][2] = 0.f; sacc[mt][nt][3] = 0.f;
            }
        #pragma unroll
        for (int ks = 0; ks < 4; ks++) {
            #pragma unroll
            for (int g2 = 0; g2 < 2; g2++) {
                unsigned kb[4];
                unsigned off = buf + (unsigned)((g2 * 16 + rowoff) * ALD + (ks * 16 + coloff) * 2);
                ldsm4(kb, off);
                #pragma unroll
                for (int mt = 0; mt < 2; mt++) {
                    mma_f16(sacc[mt][2 * g2],     qf[mt][ks], kb[0], kb[2]);
                    mma_f16(sacc[mt][2 * g2 + 1], qf[mt][ks], kb[1], kb[3]);
                }
            }
        }

        // ---- exp in registers (no max needed: |logit| bounded) ----
        #pragma unroll
        for (int mt = 0; mt < 2; mt++)
            #pragma unroll
            for (int nt = 0; nt < 4; nt++) {
                sacc[mt][nt][0] = __expf(sacc[mt][nt][0]); lsum[mt][0] += sacc[mt][nt][0];
                sacc[mt][nt][1] = __expf(sacc[mt][nt][1]); lsum[mt][0] += sacc[mt][nt][1];
                sacc[mt][nt][2] = __expf(sacc[mt][nt][2]); lsum[mt][1] += sacc[mt][nt][2];
                sacc[mt][nt][3] = __expf(sacc[mt][nt][3]); lsum[mt][1] += sacc[mt][nt][3];
            }

        // ---- O += P @ V ----
        #pragma unroll
        for (int ks2 = 0; ks2 < 2; ks2++) {
            unsigned ap[2][4];
            #pragma unroll
            for (int mt = 0; mt < 2; mt++) {
                const float* t0 = sacc[mt][2 * ks2];
                const float* t1 = sacc[mt][2 * ks2 + 1];
                ap[mt][0] = packhf(t0[0], t0[1]);
                ap[mt][1] = packhf(t0[2], t0[3]);
                ap[mt][2] = packhf(t1[0], t1[1]);
                ap[mt][3] = packhf(t1[2], t1[3]);
            }
            #pragma unroll
            for (int gv = 0; gv < 4; gv++) {
                unsigned vb[4];
                unsigned off = buf + APLANE
                             + (unsigned)((ks2 * 16 + rowoff) * ALD + (gv * 16 + coloff) * 2);
                ldsm4t(vb, off);
                #pragma unroll
                for (int mt = 0; mt < 2; mt++) {
                    mma_f16(oacc[mt][2 * gv],     ap[mt], vb[0], vb[1]);
                    mma_f16(oacc[mt][2 * gv + 1], ap[mt], vb[2], vb[3]);
                }
            }
        }
    }

    #pragma unroll
    for (int mt = 0; mt < 2; mt++) {
        lsum[mt][0] += __shfl_xor_sync(0xffffffffu, lsum[mt][0], 1);
        lsum[mt][0] += __shfl_xor_sync(0xffffffffu, lsum[mt][0], 2);
        lsum[mt][1] += __shfl_xor_sync(0xffffffffu, lsum[mt][1], 1);
        lsum[mt][1] += __shfl_xor_sync(0xffffffffu, lsum[mt][1], 2);
    }

    const int b = bh >> 4, h = bh & 15;
    const int g = lane >> 2, c2 = (lane & 3) * 2;
    #pragma unroll
    for (int mt = 0; mt < 2; mt++) {
        const float inv0 = 1.f / lsum[mt][0];
        const float inv1 = 1.f / lsum[mt][1];
        const int r0 = qt * 128 + w * 32 + mt * 16 + g;
        float* o0 = O + ((size_t)(b * S_) + r0) * D_ + h * DH_;
        float* o1 = o0 + (size_t)8 * D_;
        #pragma unroll
        for (int t = 0; t < 8; t++) {
            *(float2*)(o0 + t * 8 + c2) =
                make_float2(oacc[mt][t][0] * inv0, oacc[mt][t][1] * inv0);
            *(float2*)(o1 + t * 8 + c2) =
                make_float2(oacc[mt][t][2] * inv1, oacc[mt][t][3] * inv1);
        }
    }
}

// ---------------- QKV transform: l2norm + scale + xpos rotary ---------------
__global__ __launch_bounds__(256) void transform_kernel(
    const float* __restrict__ qkv,
    const float* __restrict__ q_scale, const float* __restrict__ k_scale,
    __half* __restrict__ Qf, __half* __restrict__ Kf, __half* __restrict__ Vf)
{
    const int gw   = (blockIdx.x * blockDim.x + threadIdx.x) >> 5;
    const int lane = threadIdx.x & 31;
    const int s  = gw & (S_ - 1);
    const int bh = gw >> 11;
    if (bh >= BH_) return;
    const int b = bh >> 4, h = bh & 15;

    const float* base = qkv + ((size_t)(b * S_ + s)) * (3 * D_) + h * (3 * DH_);
    float q0 = base[lane],       q1 = base[lane + 32];
    float k0 = base[64 + lane],  k1 = base[96 + lane];
    float v0 = base[128 + lane], v1 = base[160 + lane];

    float nq = q0 * q0 + q1 * q1;
    float nk = k0 * k0 + k1 * k1;
    #pragma unroll
    for (int off = 16; off; off >>= 1) {
        nq += __shfl_xor_sync(0xffffffffu, nq, off);
        nk += __shfl_xor_sync(0xffffffffu, nk, off);
    }
    nq = fmaxf(sqrtf(nq), 1e-12f);
    nk = fmaxf(sqrtf(nk), 1e-12f);

    q0 = q0 / nq * q_scale[lane]; q1 = q1 / nq * q_scale[lane + 32];
    k0 = k0 / nk * k_scale[lane]; k1 = k1 / nk * k_scale[lane + 32];

    const float d2 = 2.0f * (float)lane;
    const float inv_freq = exp2f(-d2 * (13.287712379549449f / 64.0f));
    const float fr = (float)s * inv_freq;
    float sn, c;
    sincosf(fr, &sn, &c);

    const float basev = (d2 + 0.4f * 64.0f) / (1.4f * 64.0f);
    const float power = ((float)s - (float)(S_ / 2)) / 512.0f;
    const float scale = exp2f(power * log2f(basev));
    const float iscale = 1.0f / scale;

    const float qo0 = (q0 * c - q1 * sn) * scale * 0.125f;
    const float qo1 = (q1 * c + q0 * sn) * scale * 0.125f;
    const float ko0 = (k0 * c - k1 * sn) * iscale;
    const float ko1 = (k1 * c + k0 * sn) * iscale;

    const size_t ob = ((size_t)bh * S_ + s) * DH_;
    Qf[ob + lane]      = __float2half_rn(qo0);
    Qf[ob + lane + 32] = __float2half_rn(qo1);
    Kf[ob + lane]      = __float2half_rn(ko0);
    Kf[ob + lane + 32] = __float2half_rn(ko1);
    Vf[ob + lane]      = __float2half_rn(v0);
    Vf[ob + lane + 32] = __float2half_rn(v1);
}

// ---------------- LayerNorm (emits fp32 + fp16 plane) ------------------------
__global__ __launch_bounds__(256) void ln_kernel(
    const float* __restrict__ X, const float* __restrict__ g,
    const float* __restrict__ bb, float* __restrict__ Y,
    __half* __restrict__ Yh)
{
    __shared__ float red[16];
    const int row = blockIdx.x;
    const int tid = threadIdx.x;
    const float* xp = X + (size_t)row * D_;

    float4 x4 = ((const float4*)xp)[tid];
    float s  = x4.x + x4.y + x4.z + x4.w;
    float ss = x4.x * x4.x + x4.y * x4.y + x4.z * x4.z + x4.w * x4.w;

    #pragma unroll
    for (int off = 16; off; off >>= 1) {
        s  += __shfl_xor_sync(0xffffffffu, s,  off);
        ss += __shfl_xor_sync(0xffffffffu, ss, off);
    }
    const int wid = tid >> 5, lane = tid & 31;
    if (lane == 0) { red[wid] = s; red[wid + 8] = ss; }
    __syncthreads();
    if (wid == 0) {
        float a = (lane < 8) ? red[lane] : 0.f;
        float bsum = (lane < 8) ? red[lane + 8] : 0.f;
        #pragma unroll
        for (int off = 4; off; off >>= 1) {
            a    += __shfl_xor_sync(0xffffffffu, a,    off);
            bsum += __shfl_xor_sync(0xffffffffu, bsum, off);
        }
        if (lane == 0) { red[0] = a; red[1] = bsum; }
    }
    __syncthreads();
    const float mu  = red[0] * (1.0f / D_);
    const float var = red[1] * (1.0f / D_) - mu * mu;
    const float rstd = rsqrtf(var + 1e-5f);

    float4 g4 = ((const float4*)g)[tid];
    float4 b4 = ((const float4*)bb)[tid];
    float4 y;
    y.x = (x4.x - mu) * rstd * g4.x + b4.x;
    y.y = (x4.y - mu) * rstd * g4.y + b4.y;
    y.z = (x4.z - mu) * rstd * g4.z + b4.z;
    y.w = (x4.w - mu) * rstd * g4.w + b4.w;
    ((float4*)(Y + (size_t)row * D_))[tid] = y;
    ((uint2*)(Yh + (size_t)row * D_))[tid] =
        make_uint2(packhf(y.x, y.y), packhf(y.z, y.w));
}

// ---------------- launch -----------------------------------------------------
extern "C" void kernel_launch(void* const* d_in, const int* in_sizes, int n_in,
                              void* d_out, int out_size)
{
    const float* Q     = (const float*)d_in[0];
    const float* Wqkv  = (const float*)d_in[3];
    const float* bqkv  = (const float*)d_in[4];
    const float* q_sc  = (const float*)d_in[5];
    const float* k_sc  = (const float*)d_in[6];
    const float* ln_g  = (const float*)d_in[7];
    const float* ln_b  = (const float*)d_in[8];
    const float* W1    = (const float*)d_in[9];
    const float* b1    = (const float*)d_in[10];
    const float* W2    = (const float*)d_in[11];
    const float* b2    = (const float*)d_in[12];
    float* out = (float*)d_out;

    float *qkv, *att, *x;
    __half *qi, *wq, *w1, *w2, *qf, *kf, *vf, *xh, *hh;
    cudaGetSymbolAddress((void**)&qkv, g_qkv);
    cudaGetSymbolAddress((void**)&qi,  g_qi);
    cudaGetSymbolAddress((void**)&wq,  g_wq);
    cudaGetSymbolAddress((void**)&w1,  g_w1);
    cudaGetSymbolAddress((void**)&w2,  g_w2);
    cudaGetSymbolAddress((void**)&qf,  g_qf);
    cudaGetSymbolAddress((void**)&kf,  g_kf);
    cudaGetSymbolAddress((void**)&vf,  g_vf);
    cudaGetSymbolAddress((void**)&att, g_att);
    cudaGetSymbolAddress((void**)&x,   g_x);
    cudaGetSymbolAddress((void**)&xh,  g_xh);
    cudaGetSymbolAddress((void**)&hh,  g_hh);

    cudaFuncSetAttribute(fattn_kernel,
                         cudaFuncAttributeMaxDynamicSharedMemorySize, ATTN_SMEM);
    cudaFuncSetAttribute(mma_gemm<0>,
                         cudaFuncAttributeMaxDynamicSharedMemorySize, GEMM_SMEM);
    cudaFuncSetAttribute(mma_gemm<1>,
                         cudaFuncAttributeMaxDynamicSharedMemorySize, GEMM_SMEM);
    cudaFuncSetAttribute(mma_gemm<2>,
                         cudaFuncAttributeMaxDynamicSharedMemorySize, GEMM_SMEM);

    // 0) convert input + weights to fp16 planes
    hsplit_kernel<<<2048, 256>>>(Q, qi, BS_ * D_ / 4);
    hsplit_kernel<<<2048, 256>>>(Wqkv, wq, D_ * 3 * D_ / 4);
    hsplit_kernel<<<2048, 256>>>(W1, w1, D_ * FF_ / 4);
    hsplit_kernel<<<2048, 256>>>(W2, w2, FF_ * D_ / 4);

    // 1) QKV projection
    mma_gemm<0><<<dim3(3 * D_ / 128, BS_ / 128), 128, GEMM_SMEM>>>(
        qi, wq, bqkv, nullptr, qkv, nullptr, BS_, 3 * D_, D_);

    // 2) l2norm + scale + rotary -> fp16 q/k/v
    transform_kernel<<<BH_ * S_ / 8, 256>>>(qkv, q_sc, k_sc, qf, kf, vf);

    // 3) flash attention
    fattn_kernel<<<dim3(S_ / 128, BH_), 128, ATTN_SMEM>>>(qf, kf, vf, att);

    // 4) LayerNorm -> x fp32 + fp16 plane
    ln_kernel<<<BS_, 256>>>(att, ln_g, ln_b, x, xh);

    // 5) FF1 + SiLU -> h fp16
    mma_gemm<1><<<dim3(FF_ / 128, BS_ / 128), 128, GEMM_SMEM>>>(
        xh, w1, b1, nullptr, nullptr, hh, BS_, FF_, D_);

    // 6) FF2 + residual -> out fp32
    mma_gemm<2><<<dim3(D_ / 128, BS_ / 128), 128, GEMM_SMEM>>>(
        hh, w2, b2, x, out, nullptr, BS_, D_, FF_);
}